// round 4
// baseline (speedup 1.0000x reference)
#include <cuda_runtime.h>
#include <math.h>

#define NMAX 100000
#define EMAX 1600000

// ---------------- scratch (device globals: allocation-free) ----------------
__device__ __align__(16) float g_ni[(size_t)NMAX * 64];
__device__ __align__(16) float g_q [(size_t)NMAX * 64];
__device__ __align__(16) float g_k [(size_t)NMAX * 64];
__device__ __align__(16) float g_v [(size_t)NMAX * 64];
__device__ __align__(16) float g_agg[(size_t)NMAX * 64];
__device__ __align__(16) float g_smax[(size_t)NMAX * 8];
__device__ __align__(16) float g_ssum[(size_t)NMAX * 8];

// ---------------- init ----------------
__global__ void k_init(int N) {
    long long i = (long long)blockIdx.x * blockDim.x + threadIdx.x;
    if (i < (long long)N * 64) g_agg[i] = 0.f;
    if (i < (long long)N * 8) {
        g_smax[i] = __int_as_float(0xff800000); // -inf
        g_ssum[i] = 0.f;
    }
}

// ---------------- K1: node LN + Q,K,V projections ----------------
// dyn smem: wq|wk|wv (12288) + biases(192) + g(64) + b(64) + xs(512) = 13120 floats
__global__ void k_node_qkv(const float* __restrict__ ns,
                           const float* __restrict__ wq, const float* __restrict__ bq,
                           const float* __restrict__ wk, const float* __restrict__ bk,
                           const float* __restrict__ wv, const float* __restrict__ bv,
                           const float* __restrict__ gg, const float* __restrict__ bb,
                           int N) {
    extern __shared__ float sm[];
    float* W  = sm;            // 3*4096
    float* B  = sm + 12288;    // 3*64
    float* G  = sm + 12480;    // 64
    float* Bt = sm + 12544;    // 64
    float* xs = sm + 12608;    // 8*64
    int tid = threadIdx.x;
    for (int i = tid; i < 4096; i += 256) { W[i] = wq[i]; W[4096 + i] = wk[i]; W[8192 + i] = wv[i]; }
    if (tid < 64) { B[tid] = bq[tid]; B[64 + tid] = bk[tid]; B[128 + tid] = bv[tid]; G[tid] = gg[tid]; Bt[tid] = bb[tid]; }
    __syncthreads();
    int warp = tid >> 5, lane = tid & 31;
    float* xw = xs + warp * 64;
    for (long long r = (long long)blockIdx.x * 8 + warp; r < N; r += (long long)gridDim.x * 8) {
        const float* xr = ns + r * 64;
        float x0 = xr[lane], x1 = xr[lane + 32];
        float s = x0 + x1;
        #pragma unroll
        for (int o = 16; o; o >>= 1) s += __shfl_xor_sync(0xffffffffu, s, o);
        float m = s * 0.015625f;
        float d0 = x0 - m, d1 = x1 - m;
        float vv = d0 * d0 + d1 * d1;
        #pragma unroll
        for (int o = 16; o; o >>= 1) vv += __shfl_xor_sync(0xffffffffu, vv, o);
        float rs = rsqrtf(vv * 0.015625f + 1e-5f);
        float y0 = d0 * rs * G[lane] + Bt[lane];
        float y1 = d1 * rs * G[lane + 32] + Bt[lane + 32];
        g_ni[r * 64 + lane] = y0; g_ni[r * 64 + lane + 32] = y1;
        xw[lane] = y0; xw[lane + 32] = y1;
        __syncwarp();
        #pragma unroll
        for (int w3 = 0; w3 < 3; w3++) {
            const float* Wp = W + w3 * 4096;
            float a0 = B[w3 * 64 + lane], a1 = B[w3 * 64 + lane + 32];
            #pragma unroll 8
            for (int i = 0; i < 64; i++) {
                float xi = xw[i];
                a0 = fmaf(xi, Wp[i * 64 + lane], a0);
                a1 = fmaf(xi, Wp[i * 64 + lane + 32], a1);
            }
            float* o = (w3 == 0) ? g_q : ((w3 == 1) ? g_k : g_v);
            o[r * 64 + lane] = a0; o[r * 64 + lane + 32] = a1;
        }
        __syncwarp();
    }
}

// ---------------- K2: edge LN + score projection + scores + segment max ----------------
__global__ void k_edge_scores(const float* __restrict__ es,
                              const float* __restrict__ we, const float* __restrict__ be,
                              const float* __restrict__ gg, const float* __restrict__ bb,
                              const int* __restrict__ eidx, float* __restrict__ att,
                              int E) {
    __shared__ float W[4096];
    __shared__ float B[64], G[64], Bt[64];
    __shared__ float eis[8][64], ess[8][64];
    int tid = threadIdx.x;
    for (int i = tid; i < 4096; i += 256) W[i] = we[i];
    if (tid < 64) { B[tid] = be[tid]; G[tid] = gg[tid]; Bt[tid] = bb[tid]; }
    __syncthreads();
    int warp = tid >> 5, lane = tid & 31;
    for (long long e = (long long)blockIdx.x * 8 + warp; e < E; e += (long long)gridDim.x * 8) {
        const float* xr = es + e * 64;
        float x0 = xr[lane], x1 = xr[lane + 32];
        float s = x0 + x1;
        #pragma unroll
        for (int o = 16; o; o >>= 1) s += __shfl_xor_sync(0xffffffffu, s, o);
        float m = s * 0.015625f;
        float d0 = x0 - m, d1 = x1 - m;
        float vv = d0 * d0 + d1 * d1;
        #pragma unroll
        for (int o = 16; o; o >>= 1) vv += __shfl_xor_sync(0xffffffffu, vv, o);
        float rs = rsqrtf(vv * 0.015625f + 1e-5f);
        float y0 = d0 * rs * G[lane] + Bt[lane];
        float y1 = d1 * rs * G[lane + 32] + Bt[lane + 32];
        eis[warp][lane] = y0; eis[warp][lane + 32] = y1;
        __syncwarp();
        float a0 = B[lane], a1 = B[lane + 32];
        #pragma unroll 8
        for (int i = 0; i < 64; i++) {
            float xi = eis[warp][i];
            a0 = fmaf(xi, W[i * 64 + lane], a0);
            a1 = fmaf(xi, W[i * 64 + lane + 32], a1);
        }
        ess[warp][lane] = a0; ess[warp][lane + 32] = a1;
        __syncwarp();
        if (lane < 8) {
            int src = eidx[e], dst = eidx[(long long)E + e];
            const float4* qp = (const float4*)&g_q[(size_t)src * 64 + lane * 8];
            const float4* kp = (const float4*)&g_k[(size_t)dst * 64 + lane * 8];
            float4 q0 = qp[0], q1 = qp[1], k0 = kp[0], k1 = kp[1];
            float sc = q0.x * k0.x + q0.y * k0.y + q0.z * k0.z + q0.w * k0.w
                     + q1.x * k1.x + q1.y * k1.y + q1.z * k1.z + q1.w * k1.w;
            #pragma unroll
            for (int d = 0; d < 8; d++) sc += ess[warp][lane * 8 + d] * eis[warp][lane * 8 + d];
            sc *= 0.35355339059327373f; // 1/sqrt(8)
            att[e * 8 + lane] = sc;
            float* amp = &g_smax[(size_t)src * 8 + lane];
            if (sc >= 0.f) atomicMax((int*)amp, __float_as_int(sc));
            else atomicMin((unsigned int*)amp, __float_as_uint(sc));
        }
        __syncwarp();
    }
}

// ---------------- K3: exp(score - max) + segment sum ----------------
__global__ void k_softmax_sum(const int* __restrict__ eidx, float* __restrict__ att, int E) {
    long long e = (long long)blockIdx.x * blockDim.x + threadIdx.x;
    if (e >= E) return;
    int src = eidx[e];
    float4 s0 = *(float4*)&att[e * 8];
    float4 s1 = *(float4*)&att[e * 8 + 4];
    float4 m0 = *(float4*)&g_smax[(size_t)src * 8];
    float4 m1 = *(float4*)&g_smax[(size_t)src * 8 + 4];
    s0.x = __expf(s0.x - m0.x); s0.y = __expf(s0.y - m0.y);
    s0.z = __expf(s0.z - m0.z); s0.w = __expf(s0.w - m0.w);
    s1.x = __expf(s1.x - m1.x); s1.y = __expf(s1.y - m1.y);
    s1.z = __expf(s1.z - m1.z); s1.w = __expf(s1.w - m1.w);
    *(float4*)&att[e * 8] = s0;
    *(float4*)&att[e * 8 + 4] = s1;
    float* ss = &g_ssum[(size_t)src * 8];
    atomicAdd(ss + 0, s0.x); atomicAdd(ss + 1, s0.y);
    atomicAdd(ss + 2, s0.z); atomicAdd(ss + 3, s0.w);
    atomicAdd(ss + 4, s1.x); atomicAdd(ss + 5, s1.y);
    atomicAdd(ss + 6, s1.z); atomicAdd(ss + 7, s1.w);
}

// ---------------- K4: finalize attention + scatter-aggregate + edge update ----------------
__global__ void k_aggregate(const float* __restrict__ es_raw,
                            const float* __restrict__ weo, const float* __restrict__ beo,
                            const int* __restrict__ eidx, float* __restrict__ att,
                            float* __restrict__ edge_out, int E) {
    __shared__ float W[512];
    __shared__ float B[64];
    __shared__ float as[8][8];
    int tid = threadIdx.x;
    for (int i = tid; i < 512; i += 256) W[i] = weo[i];
    if (tid < 64) B[tid] = beo[tid];
    __syncthreads();
    int warp = tid >> 5, lane = tid & 31;
    for (long long e = (long long)blockIdx.x * 8 + warp; e < E; e += (long long)gridDim.x * 8) {
        int src = eidx[e], dst = eidx[(long long)E + e];
        if (lane < 8) {
            float ex = att[e * 8 + lane];
            float den = g_ssum[(size_t)src * 8 + lane];
            float a = ex / (den + 1e-12f);
            att[e * 8 + lane] = a;   // final attention output
            as[warp][lane] = a;
        }
        __syncwarp();
        float v0 = g_v[(size_t)dst * 64 + lane],  v1 = g_v[(size_t)dst * 64 + lane + 32];
        float n0 = g_ni[(size_t)dst * 64 + lane], n1 = g_ni[(size_t)dst * 64 + lane + 32];
        float a0 = as[warp][lane >> 3], a1 = as[warp][(lane + 32) >> 3];
        atomicAdd(&g_agg[(size_t)src * 64 + lane],      a0 * v0 * n0);
        atomicAdd(&g_agg[(size_t)src * 64 + lane + 32], a1 * v1 * n1);
        float u0 = B[lane], u1 = B[lane + 32];
        #pragma unroll
        for (int h = 0; h < 8; h++) {
            float ah = as[warp][h];
            u0 = fmaf(ah, W[h * 64 + lane], u0);
            u1 = fmaf(ah, W[h * 64 + lane + 32], u1);
        }
        edge_out[e * 64 + lane]      = es_raw[e * 64 + lane] + u0;
        edge_out[e * 64 + lane + 32] = es_raw[e * 64 + lane + 32] + u1;
        __syncwarp();
    }
}

// ---------------- K5: node update (agg@wno) + node FFN, fused ----------------
// dyn smem floats: wno 4096 | W1 8192 | W2 8192 | bno 64 | B1 128 | B2 64 | G 64 | Bt 64 | xs 512 | hs 1024 = 22400
__global__ void k_node_ffn(const float* __restrict__ ns,
                           const float* __restrict__ wno, const float* __restrict__ bno,
                           const float* __restrict__ g2, const float* __restrict__ b2,
                           const float* __restrict__ f1w, const float* __restrict__ f1b,
                           const float* __restrict__ f2w, const float* __restrict__ f2b,
                           float* __restrict__ node_out, int N) {
    extern __shared__ float sm[];
    float* Wno = sm;             // 4096
    float* W1  = sm + 4096;      // 8192
    float* W2  = sm + 12288;     // 8192
    float* Bno = sm + 20480;     // 64
    float* B1  = sm + 20544;     // 128
    float* B2  = sm + 20672;     // 64
    float* G   = sm + 20736;     // 64
    float* Bt  = sm + 20800;     // 64
    float* xs  = sm + 20864;     // 512
    float* hs  = sm + 21376;     // 1024
    int tid = threadIdx.x;
    for (int i = tid; i < 4096; i += 256) Wno[i] = wno[i];
    for (int i = tid; i < 8192; i += 256) { W1[i] = f1w[i]; W2[i] = f2w[i]; }
    if (tid < 128) B1[tid] = f1b[tid];
    if (tid < 64) { Bno[tid] = bno[tid]; B2[tid] = f2b[tid]; G[tid] = g2[tid]; Bt[tid] = b2[tid]; }
    __syncthreads();
    int warp = tid >> 5, lane = tid & 31;
    float* xw = xs + warp * 64;
    float* hw = hs + warp * 128;
    for (long long r = (long long)blockIdx.x * 8 + warp; r < N; r += (long long)gridDim.x * 8) {
        float ag0 = g_agg[r * 64 + lane], ag1 = g_agg[r * 64 + lane + 32];
        xw[lane] = ag0; xw[lane + 32] = ag1;
        __syncwarp();
        float s0 = ns[r * 64 + lane] + Bno[lane];
        float s1 = ns[r * 64 + lane + 32] + Bno[lane + 32];
        #pragma unroll 8
        for (int i = 0; i < 64; i++) {
            float xi = xw[i];
            s0 = fmaf(xi, Wno[i * 64 + lane], s0);
            s1 = fmaf(xi, Wno[i * 64 + lane + 32], s1);
        }
        __syncwarp();
        float sum = s0 + s1;
        #pragma unroll
        for (int o = 16; o; o >>= 1) sum += __shfl_xor_sync(0xffffffffu, sum, o);
        float m = sum * 0.015625f;
        float d0 = s0 - m, d1 = s1 - m;
        float vv = d0 * d0 + d1 * d1;
        #pragma unroll
        for (int o = 16; o; o >>= 1) vv += __shfl_xor_sync(0xffffffffu, vv, o);
        float rs = rsqrtf(vv * 0.015625f + 1e-5f);
        xw[lane]      = d0 * rs * G[lane] + Bt[lane];
        xw[lane + 32] = d1 * rs * G[lane + 32] + Bt[lane + 32];
        __syncwarp();
        float h0 = B1[lane], h1 = B1[lane + 32], h2 = B1[lane + 64], h3 = B1[lane + 96];
        #pragma unroll 8
        for (int i = 0; i < 64; i++) {
            float xi = xw[i];
            h0 = fmaf(xi, W1[i * 128 + lane],      h0);
            h1 = fmaf(xi, W1[i * 128 + lane + 32], h1);
            h2 = fmaf(xi, W1[i * 128 + lane + 64], h2);
            h3 = fmaf(xi, W1[i * 128 + lane + 96], h3);
        }
        hw[lane] = fmaxf(h0, 0.f); hw[lane + 32] = fmaxf(h1, 0.f);
        hw[lane + 64] = fmaxf(h2, 0.f); hw[lane + 96] = fmaxf(h3, 0.f);
        __syncwarp();
        float y0 = B2[lane], y1 = B2[lane + 32];
        #pragma unroll 8
        for (int i = 0; i < 128; i++) {
            float hi = hw[i];
            y0 = fmaf(hi, W2[i * 64 + lane], y0);
            y1 = fmaf(hi, W2[i * 64 + lane + 32], y1);
        }
        node_out[r * 64 + lane]      = s0 + y0;
        node_out[r * 64 + lane + 32] = s1 + y1;
        __syncwarp();
    }
}

// ---------------- K6: edge FFN (the hot kernel) — tiled 64-row blocks ----------------
// dyn smem floats: W1 8192 | W2 8192 | B1 128 | B2 64 | G 64 | Bt 64 | xs 4096 | xn 4096 | hs 8192 = 33088
__global__ void k_edge_ffn(float* __restrict__ eio,
                           const float* __restrict__ g2, const float* __restrict__ b2,
                           const float* __restrict__ f1w, const float* __restrict__ f1b,
                           const float* __restrict__ f2w, const float* __restrict__ f2b,
                           int E) {
    extern __shared__ float sm[];
    float* W1 = sm;           // 8192
    float* W2 = sm + 8192;    // 8192
    float* B1 = sm + 16384;   // 128
    float* B2 = sm + 16512;   // 64
    float* G  = sm + 16576;   // 64
    float* Bt = sm + 16640;   // 64
    float* xs = sm + 16704;   // 4096
    float* xn = sm + 20800;   // 4096
    float* hs = sm + 24896;   // 8192
    int tid = threadIdx.x;
    for (int i = tid; i < 8192; i += 256) { W1[i] = f1w[i]; W2[i] = f2w[i]; }
    if (tid < 128) B1[tid] = f1b[tid];
    if (tid < 64) { B2[tid] = f2b[tid]; G[tid] = g2[tid]; Bt[tid] = b2[tid]; }
    __syncthreads();
    int warp = tid >> 5, lane = tid & 31;
    int ct = tid & 31, rt = tid >> 5;
    long long ntiles = ((long long)E + 63) >> 6;
    for (long long t = blockIdx.x; t < ntiles; t += gridDim.x) {
        long long base = t * 64;
        for (int i = tid; i < 4096; i += 256) {
            int r = i >> 6, c = i & 63;
            long long row = base + r;
            xs[i] = (row < E) ? eio[row * 64 + c] : 0.f;
        }
        __syncthreads();
        #pragma unroll
        for (int r8 = 0; r8 < 8; r8++) {
            int r = warp * 8 + r8;
            float x0 = xs[r * 64 + lane], x1 = xs[r * 64 + lane + 32];
            float s = x0 + x1;
            #pragma unroll
            for (int o = 16; o; o >>= 1) s += __shfl_xor_sync(0xffffffffu, s, o);
            float m = s * 0.015625f;
            float d0 = x0 - m, d1 = x1 - m;
            float vv = d0 * d0 + d1 * d1;
            #pragma unroll
            for (int o = 16; o; o >>= 1) vv += __shfl_xor_sync(0xffffffffu, vv, o);
            float rs = rsqrtf(vv * 0.015625f + 1e-5f);
            xn[r * 64 + lane]      = d0 * rs * G[lane] + Bt[lane];
            xn[r * 64 + lane + 32] = d1 * rs * G[lane + 32] + Bt[lane + 32];
        }
        __syncthreads();
        // GEMM1: 64x64 @ 64x128 -> relu -> hs. thread: rows rt*8..+7, cols ct*4..+3
        float acc[8][4];
        #pragma unroll
        for (int r = 0; r < 8; r++) {
            acc[r][0] = B1[ct * 4]; acc[r][1] = B1[ct * 4 + 1];
            acc[r][2] = B1[ct * 4 + 2]; acc[r][3] = B1[ct * 4 + 3];
        }
        #pragma unroll 8
        for (int i = 0; i < 64; i++) {
            float4 w = *(const float4*)&W1[i * 128 + ct * 4];
            #pragma unroll
            for (int r = 0; r < 8; r++) {
                float a = xn[(rt * 8 + r) * 64 + i];
                acc[r][0] = fmaf(a, w.x, acc[r][0]);
                acc[r][1] = fmaf(a, w.y, acc[r][1]);
                acc[r][2] = fmaf(a, w.z, acc[r][2]);
                acc[r][3] = fmaf(a, w.w, acc[r][3]);
            }
        }
        #pragma unroll
        for (int r = 0; r < 8; r++) {
            float4 hv;
            hv.x = fmaxf(acc[r][0], 0.f); hv.y = fmaxf(acc[r][1], 0.f);
            hv.z = fmaxf(acc[r][2], 0.f); hv.w = fmaxf(acc[r][3], 0.f);
            *(float4*)&hs[(rt * 8 + r) * 128 + ct * 4] = hv;
        }
        __syncthreads();
        // GEMM2: 64x128 @ 128x64 + residual. thread: rows rt*8..+7, cols ct*2..+1
        float a2[8][2];
        #pragma unroll
        for (int r = 0; r < 8; r++) { a2[r][0] = B2[ct * 2]; a2[r][1] = B2[ct * 2 + 1]; }
        #pragma unroll 8
        for (int i = 0; i < 128; i++) {
            float2 w = *(const float2*)&W2[i * 64 + ct * 2];
            #pragma unroll
            for (int r = 0; r < 8; r++) {
                float h = hs[(rt * 8 + r) * 128 + i];
                a2[r][0] = fmaf(h, w.x, a2[r][0]);
                a2[r][1] = fmaf(h, w.y, a2[r][1]);
            }
        }
        #pragma unroll
        for (int r = 0; r < 8; r++) {
            long long row = base + rt * 8 + r;
            if (row < E) {
                float2 o;
                o.x = xs[(rt * 8 + r) * 64 + ct * 2]     + a2[r][0];
                o.y = xs[(rt * 8 + r) * 64 + ct * 2 + 1] + a2[r][1];
                *(float2*)&eio[row * 64 + ct * 2] = o;
            }
        }
        __syncthreads();
    }
}

// ---------------- launcher ----------------
extern "C" void kernel_launch(void* const* d_in, const int* in_sizes, int n_in,
                              void* d_out, int out_size) {
    int N = in_sizes[0] / 64;
    int E = in_sizes[1] / 64;

    // Detect edge_index position: setup_inputs dict order has it at slot 2;
    // signature order would put it last.
    const int* eidx;
    int base;
    if (in_sizes[2] == 2 * E) { eidx = (const int*)d_in[2]; base = 3; }
    else                      { eidx = (const int*)d_in[n_in - 1]; base = 2; }

    const float* ns = (const float*)d_in[0];
    const float* es = (const float*)d_in[1];
    const float* wq   = (const float*)d_in[base + 0];
    const float* bq   = (const float*)d_in[base + 1];
    const float* wk   = (const float*)d_in[base + 2];
    const float* bk   = (const float*)d_in[base + 3];
    const float* wv   = (const float*)d_in[base + 4];
    const float* bv   = (const float*)d_in[base + 5];
    const float* we   = (const float*)d_in[base + 6];
    const float* be   = (const float*)d_in[base + 7];
    const float* wno  = (const float*)d_in[base + 8];
    const float* bno  = (const float*)d_in[base + 9];
    const float* weo  = (const float*)d_in[base + 10];
    const float* beo  = (const float*)d_in[base + 11];
    const float* n1g  = (const float*)d_in[base + 12];
    const float* n1b  = (const float*)d_in[base + 13];
    const float* e1g  = (const float*)d_in[base + 14];
    const float* e1b  = (const float*)d_in[base + 15];
    const float* n2g  = (const float*)d_in[base + 16];
    const float* n2b  = (const float*)d_in[base + 17];
    const float* e2g  = (const float*)d_in[base + 18];
    const float* e2b  = (const float*)d_in[base + 19];
    const float* nf1w = (const float*)d_in[base + 20];
    const float* nf1b = (const float*)d_in[base + 21];
    const float* nf2w = (const float*)d_in[base + 22];
    const float* nf2b = (const float*)d_in[base + 23];
    const float* ef1w = (const float*)d_in[base + 24];
    const float* ef1b = (const float*)d_in[base + 25];
    const float* ef2w = (const float*)d_in[base + 26];
    const float* ef2b = (const float*)d_in[base + 27];

    float* out      = (float*)d_out;
    float* node_out = out;
    float* edge_out = out + (size_t)N * 64;
    float* att      = edge_out + (size_t)E * 64;

    (void)out_size;

    cudaFuncSetAttribute(k_node_qkv, cudaFuncAttributeMaxDynamicSharedMemorySize, 13120 * 4);
    cudaFuncSetAttribute(k_node_ffn, cudaFuncAttributeMaxDynamicSharedMemorySize, 22400 * 4);
    cudaFuncSetAttribute(k_edge_ffn, cudaFuncAttributeMaxDynamicSharedMemorySize, 33088 * 4);

    k_init<<<(N * 64 + 255) / 256, 256>>>(N);
    k_node_qkv<<<(N + 7) / 8, 256, 13120 * 4>>>(ns, wq, bq, wk, bk, wv, bv, n1g, n1b, N);
    k_edge_scores<<<(E + 7) / 8, 256>>>(es, we, be, e1g, e1b, eidx, att, E);
    k_softmax_sum<<<(E + 255) / 256, 256>>>(eidx, att, E);
    k_aggregate<<<(E + 7) / 8, 256>>>(es, weo, beo, eidx, att, edge_out, E);
    k_node_ffn<<<(N + 7) / 8, 256, 22400 * 4>>>(ns, wno, bno, n2g, n2b,
                                                nf1w, nf1b, nf2w, nf2b, node_out, N);
    k_edge_ffn<<<1520, 256, 33088 * 4>>>(edge_out, e2g, e2b, ef1w, ef1b, ef2w, ef2b, E);
}

// round 6
// speedup vs baseline: 1.2760x; 1.2760x over previous
#include <cuda_runtime.h>
#include <math.h>

#define NMAX 100000
#define EMAX 1600000

typedef unsigned int u32;
typedef unsigned long long u64;

// ---------------- PTX helpers ----------------
__device__ __forceinline__ u64 pk2(float x, float y) {
    u64 r; asm("mov.b64 %0, {%1,%2};" : "=l"(r) : "f"(x), "f"(y)); return r;
}
__device__ __forceinline__ float2 upk2(u64 v) {
    float2 r; asm("mov.b64 {%0,%1}, %2;" : "=f"(r.x), "=f"(r.y) : "l"(v)); return r;
}
__device__ __forceinline__ void fma2(u64& d, u64 a, u64 b) {
    asm("fma.rn.f32x2 %0, %1, %2, %0;" : "+l"(d) : "l"(a), "l"(b));
}
__device__ __forceinline__ u32 tf32of(float x) {
    u32 r; asm("cvt.rna.tf32.f32 %0, %1;" : "=r"(r) : "f"(x)); return r;
}
__device__ __forceinline__ void mma_tf32(float* c, u32 a0, u32 a1, u32 a2, u32 a3,
                                         u32 b0, u32 b1) {
    asm volatile("mma.sync.aligned.m16n8k8.row.col.f32.tf32.tf32.f32 "
                 "{%0,%1,%2,%3},{%4,%5,%6,%7},{%8,%9},{%0,%1,%2,%3};"
                 : "+f"(c[0]), "+f"(c[1]), "+f"(c[2]), "+f"(c[3])
                 : "r"(a0), "r"(a1), "r"(a2), "r"(a3), "r"(b0), "r"(b1));
}
__device__ __forceinline__ void red2(float* p, float x, float y) {
    asm volatile("red.global.v2.f32.add [%0], {%1,%2};" :: "l"(p), "f"(x), "f"(y) : "memory");
}

// ---------------- scratch ----------------
__device__ __align__(16) float g_ni[(size_t)NMAX * 64];
__device__ __align__(16) float g_q [(size_t)NMAX * 64];
__device__ __align__(16) float g_k [(size_t)NMAX * 64];
__device__ __align__(16) float g_v [(size_t)NMAX * 64];
__device__ __align__(16) float g_agg[(size_t)NMAX * 64];
__device__ __align__(16) float g_smax[(size_t)NMAX * 8];
__device__ __align__(16) float g_ssum[(size_t)NMAX * 8];

// ---------------- init ----------------
__global__ void k_init(int N) {
    long long i = (long long)blockIdx.x * blockDim.x + threadIdx.x;
    if (i < (long long)N * 64) g_agg[i] = 0.f;
    if (i < (long long)N * 8) {
        g_smax[i] = __int_as_float(0xff800000);
        g_ssum[i] = 0.f;
    }
}

// ---------------- K1: node LN + Q,K,V projections (f32x2) ----------------
__global__ void k_node_qkv(const float* __restrict__ ns,
                           const float* __restrict__ wq, const float* __restrict__ bq,
                           const float* __restrict__ wk, const float* __restrict__ bk,
                           const float* __restrict__ wv, const float* __restrict__ bv,
                           const float* __restrict__ gg, const float* __restrict__ bb,
                           int N) {
    extern __shared__ float sm[];
    float* W  = sm;            // 3*4096
    float* B  = sm + 12288;    // 3*64
    float* G  = sm + 12480;
    float* Bt = sm + 12544;
    float* xs = sm + 12608;    // 8*64
    int tid = threadIdx.x;
    for (int i = tid; i < 4096; i += 256) { W[i] = wq[i]; W[4096 + i] = wk[i]; W[8192 + i] = wv[i]; }
    if (tid < 64) { B[tid] = bq[tid]; B[64 + tid] = bk[tid]; B[128 + tid] = bv[tid]; G[tid] = gg[tid]; Bt[tid] = bb[tid]; }
    __syncthreads();
    int warp = tid >> 5, lane = tid & 31;
    float* xw = xs + warp * 64;
    for (long long r = (long long)blockIdx.x * 8 + warp; r < N; r += (long long)gridDim.x * 8) {
        const float* xr = ns + r * 64;
        float x0 = xr[lane], x1 = xr[lane + 32];
        float s = x0 + x1;
        #pragma unroll
        for (int o = 16; o; o >>= 1) s += __shfl_xor_sync(0xffffffffu, s, o);
        float m = s * 0.015625f;
        float d0 = x0 - m, d1 = x1 - m;
        float vv = d0 * d0 + d1 * d1;
        #pragma unroll
        for (int o = 16; o; o >>= 1) vv += __shfl_xor_sync(0xffffffffu, vv, o);
        float rs = rsqrtf(vv * 0.015625f + 1e-5f);
        float y0 = d0 * rs * G[lane] + Bt[lane];
        float y1 = d1 * rs * G[lane + 32] + Bt[lane + 32];
        g_ni[r * 64 + lane] = y0; g_ni[r * 64 + lane + 32] = y1;
        xw[lane] = y0; xw[lane + 32] = y1;
        __syncwarp();
        int c2 = 2 * lane;
        u64 aq = *(const u64*)&B[c2];
        u64 ak = *(const u64*)&B[64 + c2];
        u64 av = *(const u64*)&B[128 + c2];
        #pragma unroll 8
        for (int i = 0; i < 64; i++) {
            float xi = xw[i];
            u64 xx = pk2(xi, xi);
            fma2(aq, xx, *(const u64*)&W[i * 64 + c2]);
            fma2(ak, xx, *(const u64*)&W[4096 + i * 64 + c2]);
            fma2(av, xx, *(const u64*)&W[8192 + i * 64 + c2]);
        }
        *(float2*)&g_q[r * 64 + c2] = upk2(aq);
        *(float2*)&g_k[r * 64 + c2] = upk2(ak);
        *(float2*)&g_v[r * 64 + c2] = upk2(av);
        __syncwarp();
    }
}

// ---------------- K2: edge LN + score proj + scores + segment max (f32x2) ----------------
__global__ void k_edge_scores(const float* __restrict__ es,
                              const float* __restrict__ we, const float* __restrict__ be,
                              const float* __restrict__ gg, const float* __restrict__ bb,
                              const int* __restrict__ eidx, float* __restrict__ att,
                              int E) {
    __shared__ __align__(16) float W[4096];
    __shared__ __align__(16) float B[64], G[64], Bt[64];
    __shared__ __align__(16) float eis[8][64], ess[8][64];
    int tid = threadIdx.x;
    for (int i = tid; i < 4096; i += 256) W[i] = we[i];
    if (tid < 64) { B[tid] = be[tid]; G[tid] = gg[tid]; Bt[tid] = bb[tid]; }
    __syncthreads();
    int warp = tid >> 5, lane = tid & 31;
    for (long long e = (long long)blockIdx.x * 8 + warp; e < E; e += (long long)gridDim.x * 8) {
        const float* xr = es + e * 64;
        float x0 = xr[lane], x1 = xr[lane + 32];
        float s = x0 + x1;
        #pragma unroll
        for (int o = 16; o; o >>= 1) s += __shfl_xor_sync(0xffffffffu, s, o);
        float m = s * 0.015625f;
        float d0 = x0 - m, d1 = x1 - m;
        float vv = d0 * d0 + d1 * d1;
        #pragma unroll
        for (int o = 16; o; o >>= 1) vv += __shfl_xor_sync(0xffffffffu, vv, o);
        float rs = rsqrtf(vv * 0.015625f + 1e-5f);
        float y0 = d0 * rs * G[lane] + Bt[lane];
        float y1 = d1 * rs * G[lane + 32] + Bt[lane + 32];
        eis[warp][lane] = y0; eis[warp][lane + 32] = y1;
        __syncwarp();
        int c2 = 2 * lane;
        u64 acc = *(const u64*)&B[c2];
        #pragma unroll 8
        for (int i = 0; i < 64; i++) {
            float xi = eis[warp][i];
            fma2(acc, pk2(xi, xi), *(const u64*)&W[i * 64 + c2]);
        }
        *(float2*)&ess[warp][c2] = upk2(acc);
        __syncwarp();
        if (lane < 8) {
            int src = eidx[e], dst = eidx[(long long)E + e];
            const float4* qp = (const float4*)&g_q[(size_t)src * 64 + lane * 8];
            const float4* kp = (const float4*)&g_k[(size_t)dst * 64 + lane * 8];
            float4 q0 = qp[0], q1 = qp[1], k0 = kp[0], k1 = kp[1];
            float sc = q0.x * k0.x + q0.y * k0.y + q0.z * k0.z + q0.w * k0.w
                     + q1.x * k1.x + q1.y * k1.y + q1.z * k1.z + q1.w * k1.w;
            #pragma unroll
            for (int d = 0; d < 8; d++) sc += ess[warp][lane * 8 + d] * eis[warp][lane * 8 + d];
            sc *= 0.35355339059327373f;
            att[e * 8 + lane] = sc;
            float* amp = &g_smax[(size_t)src * 8 + lane];
            if (sc >= 0.f) atomicMax((int*)amp, __float_as_int(sc));
            else atomicMin((unsigned int*)amp, __float_as_uint(sc));
        }
        __syncwarp();
    }
}

// ---------------- K3: exp(score - max) + segment sum ----------------
__global__ void k_softmax_sum(const int* __restrict__ eidx, float* __restrict__ att, int E) {
    long long e = (long long)blockIdx.x * blockDim.x + threadIdx.x;
    if (e >= E) return;
    int src = eidx[e];
    float4 s0 = *(float4*)&att[e * 8];
    float4 s1 = *(float4*)&att[e * 8 + 4];
    float4 m0 = *(float4*)&g_smax[(size_t)src * 8];
    float4 m1 = *(float4*)&g_smax[(size_t)src * 8 + 4];
    s0.x = __expf(s0.x - m0.x); s0.y = __expf(s0.y - m0.y);
    s0.z = __expf(s0.z - m0.z); s0.w = __expf(s0.w - m0.w);
    s1.x = __expf(s1.x - m1.x); s1.y = __expf(s1.y - m1.y);
    s1.z = __expf(s1.z - m1.z); s1.w = __expf(s1.w - m1.w);
    *(float4*)&att[e * 8] = s0;
    *(float4*)&att[e * 8 + 4] = s1;
    float* ss = &g_ssum[(size_t)src * 8];
    red2(ss,     s0.x, s0.y);
    red2(ss + 2, s0.z, s0.w);
    red2(ss + 4, s1.x, s1.y);
    red2(ss + 6, s1.z, s1.w);
}

// ---------------- K4: finalize attention + scatter-aggregate + edge update ----------------
__global__ void k_aggregate(const float* __restrict__ es_raw,
                            const float* __restrict__ weo, const float* __restrict__ beo,
                            const int* __restrict__ eidx, float* __restrict__ att,
                            float* __restrict__ edge_out, int E) {
    __shared__ __align__(16) float W[512];
    __shared__ __align__(16) float B[64];
    __shared__ __align__(16) float as[8][8];
    int tid = threadIdx.x;
    for (int i = tid; i < 512; i += 256) W[i] = weo[i];
    if (tid < 64) B[tid] = beo[tid];
    __syncthreads();
    int warp = tid >> 5, lane = tid & 31;
    for (long long e = (long long)blockIdx.x * 8 + warp; e < E; e += (long long)gridDim.x * 8) {
        int src = eidx[e], dst = eidx[(long long)E + e];
        if (lane < 8) {
            float ex = att[e * 8 + lane];
            float den = g_ssum[(size_t)src * 8 + lane];
            float a = ex / (den + 1e-12f);
            att[e * 8 + lane] = a;
            as[warp][lane] = a;
        }
        __syncwarp();
        int c2 = 2 * lane;
        float2 v = *(const float2*)&g_v[(size_t)dst * 64 + c2];
        float2 n = *(const float2*)&g_ni[(size_t)dst * 64 + c2];
        float a = as[warp][lane >> 2];  // head of cols (2l, 2l+1) = l>>2
        red2(&g_agg[(size_t)src * 64 + c2], a * v.x * n.x, a * v.y * n.y);
        u64 acc = *(const u64*)&B[c2];
        #pragma unroll
        for (int h = 0; h < 8; h++) {
            float ah = as[warp][h];
            fma2(acc, pk2(ah, ah), *(const u64*)&W[h * 64 + c2]);
        }
        float2 u = upk2(acc);
        float2 er = *(const float2*)&es_raw[e * 64 + c2];
        float2 o; o.x = er.x + u.x; o.y = er.y + u.y;
        *(float2*)&edge_out[e * 64 + c2] = o;
        __syncwarp();
    }
}

// ---------------- K5: node update + node FFN (f32x2) ----------------
__global__ void k_node_ffn(const float* __restrict__ ns,
                           const float* __restrict__ wno, const float* __restrict__ bno,
                           const float* __restrict__ g2, const float* __restrict__ b2,
                           const float* __restrict__ f1w, const float* __restrict__ f1b,
                           const float* __restrict__ f2w, const float* __restrict__ f2b,
                           float* __restrict__ node_out, int N) {
    extern __shared__ float sm[];
    float* Wno = sm;             // 4096
    float* W1  = sm + 4096;      // 8192
    float* W2  = sm + 12288;     // 8192
    float* Bno = sm + 20480;     // 64
    float* B1  = sm + 20544;     // 128
    float* B2  = sm + 20672;     // 64
    float* G   = sm + 20736;     // 64
    float* Bt  = sm + 20800;     // 64
    float* xs  = sm + 20864;     // 512
    float* hs  = sm + 21376;     // 1024
    int tid = threadIdx.x;
    for (int i = tid; i < 4096; i += 256) Wno[i] = wno[i];
    for (int i = tid; i < 8192; i += 256) { W1[i] = f1w[i]; W2[i] = f2w[i]; }
    if (tid < 128) B1[tid] = f1b[tid];
    if (tid < 64) { Bno[tid] = bno[tid]; B2[tid] = f2b[tid]; G[tid] = g2[tid]; Bt[tid] = b2[tid]; }
    __syncthreads();
    int warp = tid >> 5, lane = tid & 31;
    int c2 = 2 * lane;
    float* xw = xs + warp * 64;
    float* hw = hs + warp * 128;
    for (long long r = (long long)blockIdx.x * 8 + warp; r < N; r += (long long)gridDim.x * 8) {
        float2 ag = *(const float2*)&g_agg[r * 64 + c2];
        *(float2*)&xw[c2] = ag;
        __syncwarp();
        u64 sacc = pk2(ns[r * 64 + c2] + Bno[c2], ns[r * 64 + c2 + 1] + Bno[c2 + 1]);
        #pragma unroll 8
        for (int i = 0; i < 64; i++) {
            float xi = xw[i];
            fma2(sacc, pk2(xi, xi), *(const u64*)&Wno[i * 64 + c2]);
        }
        float2 sv = upk2(sacc);
        __syncwarp();
        float sum = sv.x + sv.y;
        #pragma unroll
        for (int o = 16; o; o >>= 1) sum += __shfl_xor_sync(0xffffffffu, sum, o);
        float m = sum * 0.015625f;
        float d0 = sv.x - m, d1 = sv.y - m;
        float vv = d0 * d0 + d1 * d1;
        #pragma unroll
        for (int o = 16; o; o >>= 1) vv += __shfl_xor_sync(0xffffffffu, vv, o);
        float rs = rsqrtf(vv * 0.015625f + 1e-5f);
        xw[c2]     = d0 * rs * G[c2] + Bt[c2];
        xw[c2 + 1] = d1 * rs * G[c2 + 1] + Bt[c2 + 1];
        __syncwarp();
        u64 h01 = *(const u64*)&B1[c2];
        u64 h23 = *(const u64*)&B1[64 + c2];
        #pragma unroll 8
        for (int i = 0; i < 64; i++) {
            float xi = xw[i];
            u64 xx = pk2(xi, xi);
            fma2(h01, xx, *(const u64*)&W1[i * 128 + c2]);
            fma2(h23, xx, *(const u64*)&W1[i * 128 + 64 + c2]);
        }
        float2 ha = upk2(h01), hb = upk2(h23);
        hw[c2] = fmaxf(ha.x, 0.f); hw[c2 + 1] = fmaxf(ha.y, 0.f);
        hw[64 + c2] = fmaxf(hb.x, 0.f); hw[64 + c2 + 1] = fmaxf(hb.y, 0.f);
        __syncwarp();
        u64 yacc = *(const u64*)&B2[c2];
        #pragma unroll 8
        for (int i = 0; i < 128; i++) {
            float hi = hw[i];
            fma2(yacc, pk2(hi, hi), *(const u64*)&W2[i * 64 + c2]);
        }
        float2 yv = upk2(yacc);
        float2 o; o.x = sv.x + yv.x; o.y = sv.y + yv.y;
        *(float2*)&node_out[r * 64 + c2] = o;
        __syncwarp();
    }
}

// ---------------- K6: edge FFN via tf32 mma.sync (tensor cores) ----------------
// Tile = 128 edge rows, 512 threads (16 warps), persistent grid.
// smem floats: W1F 8192 | W2F 8192 | B1 128 | B2 64 | G 64 | Bt 64 |
//              XS 8192 | XnS 128*68=8704 | HS 128*132=16896  => 50496 floats (201984 B)
__global__ __launch_bounds__(512, 1)
void k_edge_ffn_tc(float* __restrict__ eio,
                   const float* __restrict__ g2, const float* __restrict__ b2,
                   const float* __restrict__ f1w, const float* __restrict__ f1b,
                   const float* __restrict__ f2w, const float* __restrict__ f2b,
                   int E) {
    extern __shared__ float sm[];
    u32*   W1F = (u32*)sm;              // 8192 (fragment-ordered tf32)
    u32*   W2F = (u32*)(sm + 8192);     // 8192
    float* B1  = sm + 16384;            // 128
    float* B2  = sm + 16512;            // 64
    float* G   = sm + 16576;            // 64
    float* Bt  = sm + 16640;            // 64
    float* XS  = sm + 16704;            // 8192 (residual, stride 64)
    u32*   XnS = (u32*)(sm + 24896);    // 8704 (tf32, stride 68)
    u32*   HS  = (u32*)(sm + 33600);    // 16896 (tf32, stride 132)
    int tid = threadIdx.x;

    // Pre-swizzle weights into m16n8k8 B-fragment order (b0,b1 pairs per lane).
    for (int idx = tid; idx < 4096; idx += 512) {
        int L = idx & 31, K = (idx >> 5) & 7, T = idx >> 8;
        int kk = K * 8 + (L & 3), nn = T * 8 + (L >> 2);
        W1F[idx * 2]     = tf32of(f1w[kk * 128 + nn]);
        W1F[idx * 2 + 1] = tf32of(f1w[(kk + 4) * 128 + nn]);
    }
    for (int idx = tid; idx < 4096; idx += 512) {
        int L = idx & 31, K = (idx >> 5) & 15, T = idx >> 9;
        int kk = K * 8 + (L & 3), nn = T * 8 + (L >> 2);
        W2F[idx * 2]     = tf32of(f2w[kk * 64 + nn]);
        W2F[idx * 2 + 1] = tf32of(f2w[(kk + 4) * 64 + nn]);
    }
    if (tid < 128) B1[tid] = f1b[tid];
    if (tid < 64) { B2[tid] = f2b[tid]; G[tid] = g2[tid]; Bt[tid] = b2[tid]; }
    __syncthreads();

    int warp = tid >> 5, lane = tid & 31;
    int wm = warp & 7, wn = warp >> 3;      // rows 16*wm, GEMM1 cols 64*wn
    int qr = lane >> 2, qc = lane & 3;
    int r0 = 16 * wm + qr;
    long long ntiles = ((long long)E + 127) >> 7;

    for (long long t = blockIdx.x; t < ntiles; t += gridDim.x) {
        long long base = t << 7;
        // load X tile (residual + LN input)
        for (int idx = tid; idx < 2048; idx += 512) {
            int r = idx >> 4, c4 = (idx & 15) << 2;
            long long row = base + r;
            float4 v = (row < E) ? *(const float4*)&eio[row * 64 + c4]
                                 : make_float4(0.f, 0.f, 0.f, 0.f);
            *(float4*)&XS[r * 64 + c4] = v;
        }
        __syncthreads();
        // LN -> XnS (tf32, stride 68)
        for (int r8 = 0; r8 < 8; r8++) {
            int r = warp * 8 + r8;
            float x0 = XS[r * 64 + lane], x1 = XS[r * 64 + lane + 32];
            float s = x0 + x1;
            #pragma unroll
            for (int o = 16; o; o >>= 1) s += __shfl_xor_sync(0xffffffffu, s, o);
            float m = s * 0.015625f;
            float d0 = x0 - m, d1 = x1 - m;
            float vv = d0 * d0 + d1 * d1;
            #pragma unroll
            for (int o = 16; o; o >>= 1) vv += __shfl_xor_sync(0xffffffffu, vv, o);
            float rs = rsqrtf(vv * 0.015625f + 1e-5f);
            XnS[r * 68 + lane]      = tf32of(d0 * rs * G[lane] + Bt[lane]);
            XnS[r * 68 + lane + 32] = tf32of(d1 * rs * G[lane + 32] + Bt[lane + 32]);
        }
        __syncthreads();
        // GEMM1: [128,64] @ [64,128] -> relu -> HS
        float c1[8][4];
        #pragma unroll
        for (int t8 = 0; t8 < 8; t8++) {
            int cc = 64 * wn + 8 * t8 + 2 * qc;
            c1[t8][0] = B1[cc]; c1[t8][1] = B1[cc + 1];
            c1[t8][2] = B1[cc]; c1[t8][3] = B1[cc + 1];
        }
        #pragma unroll
        for (int k = 0; k < 8; k++) {
            u32 a0 = XnS[r0 * 68 + 8 * k + qc];
            u32 a1 = XnS[(r0 + 8) * 68 + 8 * k + qc];
            u32 a2 = XnS[r0 * 68 + 8 * k + qc + 4];
            u32 a3 = XnS[(r0 + 8) * 68 + 8 * k + qc + 4];
            #pragma unroll
            for (int t8 = 0; t8 < 8; t8++) {
                uint2 b = *(const uint2*)&W1F[(((8 * wn + t8) * 8 + k) * 32 + lane) * 2];
                mma_tf32(c1[t8], a0, a1, a2, a3, b.x, b.y);
            }
        }
        #pragma unroll
        for (int t8 = 0; t8 < 8; t8++) {
            int cc = 64 * wn + 8 * t8 + 2 * qc;
            uint2 lo, hi;
            lo.x = tf32of(fmaxf(c1[t8][0], 0.f)); lo.y = tf32of(fmaxf(c1[t8][1], 0.f));
            hi.x = tf32of(fmaxf(c1[t8][2], 0.f)); hi.y = tf32of(fmaxf(c1[t8][3], 0.f));
            *(uint2*)&HS[r0 * 132 + cc] = lo;
            *(uint2*)&HS[(r0 + 8) * 132 + cc] = hi;
        }
        __syncthreads();
        // GEMM2: [128,128] @ [128,64] + residual -> eio
        float c2[4][4];
        #pragma unroll
        for (int t4 = 0; t4 < 4; t4++) {
            int cc = 32 * wn + 8 * t4 + 2 * qc;
            c2[t4][0] = B2[cc]; c2[t4][1] = B2[cc + 1];
            c2[t4][2] = B2[cc]; c2[t4][3] = B2[cc + 1];
        }
        #pragma unroll
        for (int k = 0; k < 16; k++) {
            u32 a0 = HS[r0 * 132 + 8 * k + qc];
            u32 a1 = HS[(r0 + 8) * 132 + 8 * k + qc];
            u32 a2 = HS[r0 * 132 + 8 * k + qc + 4];
            u32 a3 = HS[(r0 + 8) * 132 + 8 * k + qc + 4];
            #pragma unroll
            for (int t4 = 0; t4 < 4; t4++) {
                uint2 b = *(const uint2*)&W2F[(((4 * wn + t4) * 16 + k) * 32 + lane) * 2];
                mma_tf32(c2[t4], a0, a1, a2, a3, b.x, b.y);
            }
        }
        #pragma unroll
        for (int t4 = 0; t4 < 4; t4++) {
            int cc = 32 * wn + 8 * t4 + 2 * qc;
            long long ro = base + r0;
            if (ro < E) {
                float2 o;
                o.x = XS[r0 * 64 + cc]     + c2[t4][0];
                o.y = XS[r0 * 64 + cc + 1] + c2[t4][1];
                *(float2*)&eio[ro * 64 + cc] = o;
            }
            if (ro + 8 < E) {
                float2 o;
                o.x = XS[(r0 + 8) * 64 + cc]     + c2[t4][2];
                o.y = XS[(r0 + 8) * 64 + cc + 1] + c2[t4][3];
                *(float2*)&eio[(ro + 8) * 64 + cc] = o;
            }
        }
        __syncthreads();
    }
}

// ---------------- launcher ----------------
extern "C" void kernel_launch(void* const* d_in, const int* in_sizes, int n_in,
                              void* d_out, int out_size) {
    int N = in_sizes[0] / 64;
    int E = in_sizes[1] / 64;

    const int* eidx;
    int base;
    if (in_sizes[2] == 2 * E) { eidx = (const int*)d_in[2]; base = 3; }
    else                      { eidx = (const int*)d_in[n_in - 1]; base = 2; }

    const float* ns = (const float*)d_in[0];
    const float* es = (const float*)d_in[1];
    const float* wq   = (const float*)d_in[base + 0];
    const float* bq   = (const float*)d_in[base + 1];
    const float* wk   = (const float*)d_in[base + 2];
    const float* bk   = (const float*)d_in[base + 3];
    const float* wv   = (const float*)d_in[base + 4];
    const float* bv   = (const float*)d_in[base + 5];
    const float* we   = (const float*)d_in[base + 6];
    const float* be   = (const float*)d_in[base + 7];
    const float* wno  = (const float*)d_in[base + 8];
    const float* bno  = (const float*)d_in[base + 9];
    const float* weo  = (const float*)d_in[base + 10];
    const float* beo  = (const float*)d_in[base + 11];
    const float* n1g  = (const float*)d_in[base + 12];
    const float* n1b  = (const float*)d_in[base + 13];
    const float* e1g  = (const float*)d_in[base + 14];
    const float* e1b  = (const float*)d_in[base + 15];
    const float* n2g  = (const float*)d_in[base + 16];
    const float* n2b  = (const float*)d_in[base + 17];
    const float* e2g  = (const float*)d_in[base + 18];
    const float* e2b  = (const float*)d_in[base + 19];
    const float* nf1w = (const float*)d_in[base + 20];
    const float* nf1b = (const float*)d_in[base + 21];
    const float* nf2w = (const float*)d_in[base + 22];
    const float* nf2b = (const float*)d_in[base + 23];
    const float* ef1w = (const float*)d_in[base + 24];
    const float* ef1b = (const float*)d_in[base + 25];
    const float* ef2w = (const float*)d_in[base + 26];
    const float* ef2b = (const float*)d_in[base + 27];

    float* out      = (float*)d_out;
    float* node_out = out;
    float* edge_out = out + (size_t)N * 64;
    float* att      = edge_out + (size_t)E * 64;

    (void)out_size;

    cudaFuncSetAttribute(k_node_qkv, cudaFuncAttributeMaxDynamicSharedMemorySize, 13120 * 4);
    cudaFuncSetAttribute(k_node_ffn, cudaFuncAttributeMaxDynamicSharedMemorySize, 22400 * 4);
    cudaFuncSetAttribute(k_edge_ffn_tc, cudaFuncAttributeMaxDynamicSharedMemorySize, 50496 * 4);

    k_init<<<(N * 64 + 255) / 256, 256>>>(N);
    k_node_qkv<<<(N + 7) / 8, 256, 13120 * 4>>>(ns, wq, bq, wk, bk, wv, bv, n1g, n1b, N);
    k_edge_scores<<<(E + 7) / 8, 256>>>(es, we, be, e1g, e1b, eidx, att, E);
    k_softmax_sum<<<(E + 255) / 256, 256>>>(eidx, att, E);
    k_aggregate<<<(E + 7) / 8, 256>>>(es, weo, beo, eidx, att, edge_out, E);
    k_node_ffn<<<(N + 7) / 8, 256, 22400 * 4>>>(ns, wno, bno, n2g, n2b,
                                                nf1w, nf1b, nf2w, nf2b, node_out, N);
    k_edge_ffn_tc<<<148, 512, 50496 * 4>>>(edge_out, e2g, e2b, ef1w, ef1b, ef2w, ef2b, E);
}

// round 8
// speedup vs baseline: 1.7613x; 1.3804x over previous
#include <cuda_runtime.h>
#include <math.h>

#define NMAX 100000
#define EMAX 1600000

typedef unsigned int u32;
typedef unsigned long long u64;

// ---------------- PTX helpers ----------------
__device__ __forceinline__ u64 pk2(float x, float y) {
    u64 r; asm("mov.b64 %0, {%1,%2};" : "=l"(r) : "f"(x), "f"(y)); return r;
}
__device__ __forceinline__ float2 upk2(u64 v) {
    float2 r; asm("mov.b64 {%0,%1}, %2;" : "=f"(r.x), "=f"(r.y) : "l"(v)); return r;
}
__device__ __forceinline__ void fma2(u64& d, u64 a, u64 b) {
    asm("fma.rn.f32x2 %0, %1, %2, %0;" : "+l"(d) : "l"(a), "l"(b));
}
__device__ __forceinline__ u32 tf32of(float x) {
    u32 r; asm("cvt.rna.tf32.f32 %0, %1;" : "=r"(r) : "f"(x)); return r;
}
__device__ __forceinline__ float tf32f(float x) {
    u32 r; asm("cvt.rna.tf32.f32 %0, %1;" : "=r"(r) : "f"(x)); return __uint_as_float(r);
}
__device__ __forceinline__ void mma_tf32(float* c, u32 a0, u32 a1, u32 a2, u32 a3,
                                         u32 b0, u32 b1) {
    asm volatile("mma.sync.aligned.m16n8k8.row.col.f32.tf32.tf32.f32 "
                 "{%0,%1,%2,%3},{%4,%5,%6,%7},{%8,%9},{%0,%1,%2,%3};"
                 : "+f"(c[0]), "+f"(c[1]), "+f"(c[2]), "+f"(c[3])
                 : "r"(a0), "r"(a1), "r"(a2), "r"(a3), "r"(b0), "r"(b1));
}
__device__ __forceinline__ void red2(float* p, float x, float y) {
    asm volatile("red.global.v2.f32.add [%0], {%1,%2};" :: "l"(p), "f"(x), "f"(y) : "memory");
}

// ---------------- scratch ----------------
__device__ __align__(16) float g_ni[(size_t)NMAX * 64];
__device__ __align__(16) float g_q [(size_t)NMAX * 64];
__device__ __align__(16) float g_k [(size_t)NMAX * 64];
__device__ __align__(16) float g_v [(size_t)NMAX * 64];
__device__ __align__(16) float g_agg[(size_t)NMAX * 64];
__device__ __align__(16) float g_smax[(size_t)NMAX * 8];
__device__ __align__(16) float g_ssum[(size_t)NMAX * 8];
__device__ __align__(16) float g_eterm[(size_t)EMAX * 8];

// ---------------- init ----------------
__global__ void k_init(int N) {
    long long i = (long long)blockIdx.x * blockDim.x + threadIdx.x;
    if (i < (long long)N * 64) g_agg[i] = 0.f;
    if (i < (long long)N * 8) {
        g_smax[i] = __int_as_float(0xff800000);
        g_ssum[i] = 0.f;
    }
}

// ---------------- K1: node LN + Q,K,V projections (f32x2) ----------------
__global__ void k_node_qkv(const float* __restrict__ ns,
                           const float* __restrict__ wq, const float* __restrict__ bq,
                           const float* __restrict__ wk, const float* __restrict__ bk,
                           const float* __restrict__ wv, const float* __restrict__ bv,
                           const float* __restrict__ gg, const float* __restrict__ bb,
                           int N) {
    extern __shared__ float sm[];
    float* W  = sm;            // 3*4096
    float* B  = sm + 12288;    // 3*64
    float* G  = sm + 12480;
    float* Bt = sm + 12544;
    float* xs = sm + 12608;    // 8*64
    int tid = threadIdx.x;
    for (int i = tid; i < 4096; i += 256) { W[i] = wq[i]; W[4096 + i] = wk[i]; W[8192 + i] = wv[i]; }
    if (tid < 64) { B[tid] = bq[tid]; B[64 + tid] = bk[tid]; B[128 + tid] = bv[tid]; G[tid] = gg[tid]; Bt[tid] = bb[tid]; }
    __syncthreads();
    int warp = tid >> 5, lane = tid & 31;
    float* xw = xs + warp * 64;
    for (long long r = (long long)blockIdx.x * 8 + warp; r < N; r += (long long)gridDim.x * 8) {
        const float* xr = ns + r * 64;
        float x0 = xr[lane], x1 = xr[lane + 32];
        float s = x0 + x1;
        #pragma unroll
        for (int o = 16; o; o >>= 1) s += __shfl_xor_sync(0xffffffffu, s, o);
        float m = s * 0.015625f;
        float d0 = x0 - m, d1 = x1 - m;
        float vv = d0 * d0 + d1 * d1;
        #pragma unroll
        for (int o = 16; o; o >>= 1) vv += __shfl_xor_sync(0xffffffffu, vv, o);
        float rs = rsqrtf(vv * 0.015625f + 1e-5f);
        float y0 = d0 * rs * G[lane] + Bt[lane];
        float y1 = d1 * rs * G[lane + 32] + Bt[lane + 32];
        g_ni[r * 64 + lane] = y0; g_ni[r * 64 + lane + 32] = y1;
        xw[lane] = y0; xw[lane + 32] = y1;
        __syncwarp();
        int c2 = 2 * lane;
        u64 aq = *(const u64*)&B[c2];
        u64 ak = *(const u64*)&B[64 + c2];
        u64 av = *(const u64*)&B[128 + c2];
        #pragma unroll 8
        for (int i = 0; i < 64; i++) {
            float xi = xw[i];
            u64 xx = pk2(xi, xi);
            fma2(aq, xx, *(const u64*)&W[i * 64 + c2]);
            fma2(ak, xx, *(const u64*)&W[4096 + i * 64 + c2]);
            fma2(av, xx, *(const u64*)&W[8192 + i * 64 + c2]);
        }
        *(float2*)&g_q[r * 64 + c2] = upk2(aq);
        *(float2*)&g_k[r * 64 + c2] = upk2(ak);
        *(float2*)&g_v[r * 64 + c2] = upk2(av);
        __syncwarp();
    }
}

// ---------------- K2: edge LN + (ei@we+be)·ei per head, via split-tf32 mma ----------------
// smem floats: WH 4096 | WL 4096 | B 64 | G 64 | Bt 64 | XH 8704 | XL 8704 = 25792
__global__ __launch_bounds__(512, 1)
void k_edge_proj_tc(const float* __restrict__ es,
                    const float* __restrict__ we, const float* __restrict__ be,
                    const float* __restrict__ gg, const float* __restrict__ bb,
                    int E) {
    extern __shared__ float sm[];
    u32*   WH = (u32*)sm;            // 4096
    u32*   WL = (u32*)(sm + 4096);   // 4096
    float* B  = sm + 8192;           // 64
    float* G  = sm + 8256;
    float* Bt = sm + 8320;
    float* XH = sm + 8384;           // 128*68
    float* XL = sm + 17088;          // 128*68
    int tid = threadIdx.x;

    for (int idx = tid; idx < 2048; idx += 512) {
        int L = idx & 31, K = (idx >> 5) & 7, T = idx >> 8;
        int kk = K * 8 + (L & 3), nn = T * 8 + (L >> 2);
        float w0 = we[kk * 64 + nn], w1 = we[(kk + 4) * 64 + nn];
        u32 h0 = tf32of(w0), h1 = tf32of(w1);
        WH[idx * 2] = h0; WH[idx * 2 + 1] = h1;
        WL[idx * 2]     = tf32of(w0 - __uint_as_float(h0));
        WL[idx * 2 + 1] = tf32of(w1 - __uint_as_float(h1));
    }
    if (tid < 64) { B[tid] = be[tid]; G[tid] = gg[tid]; Bt[tid] = bb[tid]; }
    __syncthreads();

    int warp = tid >> 5, lane = tid & 31;
    int wm = warp & 7, wn = warp >> 3;
    int qr = lane >> 2, qc = lane & 3;
    int r0 = 16 * wm + qr;
    long long ntiles = ((long long)E + 127) >> 7;

    for (long long t = blockIdx.x; t < ntiles; t += gridDim.x) {
        long long base = t << 7;
        for (int r8 = 0; r8 < 8; r8++) {
            int r = warp * 8 + r8;
            long long row = base + r;
            float x0 = 0.f, x1 = 0.f;
            if (row < E) { x0 = es[row * 64 + lane]; x1 = es[row * 64 + lane + 32]; }
            float s = x0 + x1;
            #pragma unroll
            for (int o = 16; o; o >>= 1) s += __shfl_xor_sync(0xffffffffu, s, o);
            float m = s * 0.015625f;
            float d0 = x0 - m, d1 = x1 - m;
            float vv = d0 * d0 + d1 * d1;
            #pragma unroll
            for (int o = 16; o; o >>= 1) vv += __shfl_xor_sync(0xffffffffu, vv, o);
            float rs = rsqrtf(vv * 0.015625f + 1e-5f);
            float y0 = d0 * rs * G[lane] + Bt[lane];
            float y1 = d1 * rs * G[lane + 32] + Bt[lane + 32];
            float h0 = tf32f(y0), h1 = tf32f(y1);
            XH[r * 68 + lane] = h0;      XH[r * 68 + lane + 32] = h1;
            XL[r * 68 + lane] = tf32f(y0 - h0); XL[r * 68 + lane + 32] = tf32f(y1 - h1);
        }
        __syncthreads();
        float c[4][4];
        #pragma unroll
        for (int t4 = 0; t4 < 4; t4++) {
            int cc = 32 * wn + 8 * t4 + 2 * qc;
            c[t4][0] = B[cc]; c[t4][1] = B[cc + 1];
            c[t4][2] = B[cc]; c[t4][3] = B[cc + 1];
        }
        #pragma unroll
        for (int k = 0; k < 8; k++) {
            u32 ah0 = __float_as_uint(XH[r0 * 68 + 8 * k + qc]);
            u32 ah1 = __float_as_uint(XH[(r0 + 8) * 68 + 8 * k + qc]);
            u32 ah2 = __float_as_uint(XH[r0 * 68 + 8 * k + qc + 4]);
            u32 ah3 = __float_as_uint(XH[(r0 + 8) * 68 + 8 * k + qc + 4]);
            u32 al0 = __float_as_uint(XL[r0 * 68 + 8 * k + qc]);
            u32 al1 = __float_as_uint(XL[(r0 + 8) * 68 + 8 * k + qc]);
            u32 al2 = __float_as_uint(XL[r0 * 68 + 8 * k + qc + 4]);
            u32 al3 = __float_as_uint(XL[(r0 + 8) * 68 + 8 * k + qc + 4]);
            #pragma unroll
            for (int t4 = 0; t4 < 4; t4++) {
                int gidx = (((4 * wn + t4) * 8 + k) * 32 + lane) * 2;
                uint2 bh = *(const uint2*)&WH[gidx];
                uint2 bl = *(const uint2*)&WL[gidx];
                mma_tf32(c[t4], ah0, ah1, ah2, ah3, bh.x, bh.y);
                mma_tf32(c[t4], al0, al1, al2, al3, bh.x, bh.y);
                mma_tf32(c[t4], ah0, ah1, ah2, ah3, bl.x, bl.y);
            }
        }
        #pragma unroll
        for (int t4 = 0; t4 < 4; t4++) {
            int cc = 32 * wn + 8 * t4 + 2 * qc;
            float e00 = XH[r0 * 68 + cc]       + XL[r0 * 68 + cc];
            float e01 = XH[r0 * 68 + cc + 1]   + XL[r0 * 68 + cc + 1];
            float e10 = XH[(r0 + 8) * 68 + cc]     + XL[(r0 + 8) * 68 + cc];
            float e11 = XH[(r0 + 8) * 68 + cc + 1] + XL[(r0 + 8) * 68 + cc + 1];
            float p0 = c[t4][0] * e00 + c[t4][1] * e01;
            float p1 = c[t4][2] * e10 + c[t4][3] * e11;
            p0 += __shfl_xor_sync(0xffffffffu, p0, 1);
            p0 += __shfl_xor_sync(0xffffffffu, p0, 2);
            p1 += __shfl_xor_sync(0xffffffffu, p1, 1);
            p1 += __shfl_xor_sync(0xffffffffu, p1, 2);
            if (qc == 0) {
                long long row = base + 16 * wm + qr;
                if (row < E)     g_eterm[row * 8 + 4 * wn + t4] = p0;
                if (row + 8 < E) g_eterm[(row + 8) * 8 + 4 * wn + t4] = p1;
            }
        }
        __syncthreads();
    }
}

// ---------------- K3: scores = (q[src]·k[dst] + eterm)/sqrt(D) + segment max ----------------
__global__ void k_scores(const int* __restrict__ eidx, float* __restrict__ att, int E) {
    long long gid = (long long)blockIdx.x * blockDim.x + threadIdx.x;
    if (gid >= (long long)E * 8) return;
    long long e = gid >> 3; int h = (int)(gid & 7);
    int src = eidx[e], dst = eidx[(long long)E + e];
    const float4* qp = (const float4*)&g_q[(size_t)src * 64 + h * 8];
    const float4* kp = (const float4*)&g_k[(size_t)dst * 64 + h * 8];
    float4 q0 = qp[0], q1 = qp[1], k0 = kp[0], k1 = kp[1];
    float sc = q0.x * k0.x + q0.y * k0.y + q0.z * k0.z + q0.w * k0.w
             + q1.x * k1.x + q1.y * k1.y + q1.z * k1.z + q1.w * k1.w;
    sc = (sc + g_eterm[gid]) * 0.35355339059327373f;
    att[gid] = sc;
    float* amp = &g_smax[(size_t)src * 8 + h];
    if (sc >= 0.f) atomicMax((int*)amp, __float_as_int(sc));
    else atomicMin((unsigned int*)amp, __float_as_uint(sc));
}

// ---------------- K4: exp(score - max) + segment sum ----------------
__global__ void k_softmax_sum(const int* __restrict__ eidx, float* __restrict__ att, int E) {
    long long e = (long long)blockIdx.x * blockDim.x + threadIdx.x;
    if (e >= E) return;
    int src = eidx[e];
    float4 s0 = *(float4*)&att[e * 8];
    float4 s1 = *(float4*)&att[e * 8 + 4];
    float4 m0 = *(float4*)&g_smax[(size_t)src * 8];
    float4 m1 = *(float4*)&g_smax[(size_t)src * 8 + 4];
    s0.x = __expf(s0.x - m0.x); s0.y = __expf(s0.y - m0.y);
    s0.z = __expf(s0.z - m0.z); s0.w = __expf(s0.w - m0.w);
    s1.x = __expf(s1.x - m1.x); s1.y = __expf(s1.y - m1.y);
    s1.z = __expf(s1.z - m1.z); s1.w = __expf(s1.w - m1.w);
    *(float4*)&att[e * 8] = s0;
    *(float4*)&att[e * 8 + 4] = s1;
    float* ss = &g_ssum[(size_t)src * 8];
    red2(ss,     s0.x, s0.y);
    red2(ss + 2, s0.z, s0.w);
    red2(ss + 4, s1.x, s1.y);
    red2(ss + 6, s1.z, s1.w);
}

// ---------------- K5: finalize attention + scatter-aggregate (2 edges/warp) ----------------
__global__ void k_aggregate(const int* __restrict__ eidx, float* __restrict__ att, int E) {
    __shared__ float as[8][2][8];
    int tid = threadIdx.x, warp = tid >> 5, lane = tid & 31;
    int side = lane >> 4, hl = lane & 15;
    for (long long e0 = (long long)blockIdx.x * 16 + warp * 2; e0 < E;
         e0 += (long long)gridDim.x * 16) {
        long long e = e0 + side;
        bool ok = e < E;
        int src = 0, dst = 0;
        if (ok) { src = eidx[e]; dst = eidx[(long long)E + e]; }
        if (ok && hl < 8) {
            float ex = att[e * 8 + hl];
            float den = g_ssum[(size_t)src * 8 + hl];
            float a = ex / (den + 1e-12f);
            att[e * 8 + hl] = a;
            as[warp][side][hl] = a;
        }
        __syncwarp();
        if (ok) {
            int c4 = hl * 4;
            float4 v = *(const float4*)&g_v[(size_t)dst * 64 + c4];
            float4 n = *(const float4*)&g_ni[(size_t)dst * 64 + c4];
            float a = as[warp][side][hl >> 1];
            float* p = &g_agg[(size_t)src * 64 + c4];
            red2(p,     a * v.x * n.x, a * v.y * n.y);
            red2(p + 2, a * v.z * n.z, a * v.w * n.w);
        }
        __syncwarp();
    }
}

// ---------------- K6: node update + node FFN (f32x2) ----------------
__global__ void k_node_ffn(const float* __restrict__ ns,
                           const float* __restrict__ wno, const float* __restrict__ bno,
                           const float* __restrict__ g2, const float* __restrict__ b2,
                           const float* __restrict__ f1w, const float* __restrict__ f1b,
                           const float* __restrict__ f2w, const float* __restrict__ f2b,
                           float* __restrict__ node_out, int N) {
    extern __shared__ float sm[];
    float* Wno = sm;
    float* W1  = sm + 4096;
    float* W2  = sm + 12288;
    float* Bno = sm + 20480;
    float* B1  = sm + 20544;
    float* B2  = sm + 20672;
    float* G   = sm + 20736;
    float* Bt  = sm + 20800;
    float* xs  = sm + 20864;
    float* hs  = sm + 21376;
    int tid = threadIdx.x;
    for (int i = tid; i < 4096; i += 256) Wno[i] = wno[i];
    for (int i = tid; i < 8192; i += 256) { W1[i] = f1w[i]; W2[i] = f2w[i]; }
    if (tid < 128) B1[tid] = f1b[tid];
    if (tid < 64) { Bno[tid] = bno[tid]; B2[tid] = f2b[tid]; G[tid] = g2[tid]; Bt[tid] = b2[tid]; }
    __syncthreads();
    int warp = tid >> 5, lane = tid & 31;
    int c2 = 2 * lane;
    float* xw = xs + warp * 64;
    float* hw = hs + warp * 128;
    for (long long r = (long long)blockIdx.x * 8 + warp; r < N; r += (long long)gridDim.x * 8) {
        float2 ag = *(const float2*)&g_agg[r * 64 + c2];
        *(float2*)&xw[c2] = ag;
        __syncwarp();
        u64 sacc = pk2(ns[r * 64 + c2] + Bno[c2], ns[r * 64 + c2 + 1] + Bno[c2 + 1]);
        #pragma unroll 8
        for (int i = 0; i < 64; i++) {
            float xi = xw[i];
            fma2(sacc, pk2(xi, xi), *(const u64*)&Wno[i * 64 + c2]);
        }
        float2 sv = upk2(sacc);
        __syncwarp();
        float sum = sv.x + sv.y;
        #pragma unroll
        for (int o = 16; o; o >>= 1) sum += __shfl_xor_sync(0xffffffffu, sum, o);
        float m = sum * 0.015625f;
        float d0 = sv.x - m, d1 = sv.y - m;
        float vv = d0 * d0 + d1 * d1;
        #pragma unroll
        for (int o = 16; o; o >>= 1) vv += __shfl_xor_sync(0xffffffffu, vv, o);
        float rs = rsqrtf(vv * 0.015625f + 1e-5f);
        xw[c2]     = d0 * rs * G[c2] + Bt[c2];
        xw[c2 + 1] = d1 * rs * G[c2 + 1] + Bt[c2 + 1];
        __syncwarp();
        u64 h01 = *(const u64*)&B1[c2];
        u64 h23 = *(const u64*)&B1[64 + c2];
        #pragma unroll 8
        for (int i = 0; i < 64; i++) {
            float xi = xw[i];
            u64 xx = pk2(xi, xi);
            fma2(h01, xx, *(const u64*)&W1[i * 128 + c2]);
            fma2(h23, xx, *(const u64*)&W1[i * 128 + 64 + c2]);
        }
        float2 ha = upk2(h01), hb = upk2(h23);
        hw[c2] = fmaxf(ha.x, 0.f); hw[c2 + 1] = fmaxf(ha.y, 0.f);
        hw[64 + c2] = fmaxf(hb.x, 0.f); hw[64 + c2 + 1] = fmaxf(hb.y, 0.f);
        __syncwarp();
        u64 yacc = *(const u64*)&B2[c2];
        #pragma unroll 8
        for (int i = 0; i < 128; i++) {
            float hi = hw[i];
            fma2(yacc, pk2(hi, hi), *(const u64*)&W2[i * 64 + c2]);
        }
        float2 yv = upk2(yacc);
        float2 o; o.x = sv.x + yv.x; o.y = sv.y + yv.y;
        *(float2*)&node_out[r * 64 + c2] = o;
        __syncwarp();
    }
}

// ---------------- K7: edge update + edge FFN (tf32 mma) ----------------
// smem floats: W1F 8192 | W2F 8192 | B1 128 | B2 64 | G 64 | Bt 64 | WO 512 | BO 64 |
//              ATS 1024 | XS 8192 | XnS 8704 | HS 16896 = 52096 floats (208384 B)
__global__ __launch_bounds__(512, 1)
void k_edge_ffn_tc(const float* __restrict__ es, const float* __restrict__ att,
                   float* __restrict__ eout,
                   const float* __restrict__ weo, const float* __restrict__ beo,
                   const float* __restrict__ g2, const float* __restrict__ b2,
                   const float* __restrict__ f1w, const float* __restrict__ f1b,
                   const float* __restrict__ f2w, const float* __restrict__ f2b,
                   int E) {
    extern __shared__ float sm[];
    u32*   W1F = (u32*)sm;              // 8192
    u32*   W2F = (u32*)(sm + 8192);     // 8192
    float* B1  = sm + 16384;
    float* B2  = sm + 16512;
    float* G   = sm + 16576;
    float* Bt  = sm + 16640;
    float* WO  = sm + 16704;            // 512
    float* BO  = sm + 17216;            // 64
    float* ATS = sm + 17280;            // 1024
    float* XS  = sm + 18304;            // 8192
    u32*   XnS = (u32*)(sm + 26496);    // 8704
    u32*   HS  = (u32*)(sm + 35200);    // 16896
    int tid = threadIdx.x;

    for (int idx = tid; idx < 4096; idx += 512) {
        int L = idx & 31, K = (idx >> 5) & 7, T = idx >> 8;
        int kk = K * 8 + (L & 3), nn = T * 8 + (L >> 2);
        W1F[idx * 2]     = tf32of(f1w[kk * 128 + nn]);
        W1F[idx * 2 + 1] = tf32of(f1w[(kk + 4) * 128 + nn]);
    }
    for (int idx = tid; idx < 4096; idx += 512) {
        int L = idx & 31, K = (idx >> 5) & 15, T = idx >> 9;
        int kk = K * 8 + (L & 3), nn = T * 8 + (L >> 2);
        W2F[idx * 2]     = tf32of(f2w[kk * 64 + nn]);
        W2F[idx * 2 + 1] = tf32of(f2w[(kk + 4) * 64 + nn]);
    }
    for (int i = tid; i < 512; i += 512) WO[i] = weo[i];
    if (tid < 512) WO[tid] = weo[tid];
    if (tid < 128) B1[tid] = f1b[tid];
    if (tid < 64) { B2[tid] = f2b[tid]; G[tid] = g2[tid]; Bt[tid] = b2[tid]; BO[tid] = beo[tid]; }
    __syncthreads();

    int warp = tid >> 5, lane = tid & 31;
    int wm = warp & 7, wn = warp >> 3;
    int qr = lane >> 2, qc = lane & 3;
    int r0 = 16 * wm + qr;
    long long ntiles = ((long long)E + 127) >> 7;

    for (long long t = blockIdx.x; t < ntiles; t += gridDim.x) {
        long long base = t << 7;
        for (int idx = tid; idx < 1024; idx += 512) {
            long long ai = base * 8 + idx;
            ATS[idx] = (ai < (long long)E * 8) ? att[ai] : 0.f;
        }
        __syncthreads();
        // x = es + att @ weo + beo  (edge_s, residual)
        for (int idx = tid; idx < 2048; idx += 512) {
            int r = idx >> 4, c4 = (idx & 15) << 2;
            long long row = base + r;
            float4 x = make_float4(0.f, 0.f, 0.f, 0.f);
            if (row < E) x = *(const float4*)&es[row * 64 + c4];
            const float* a = &ATS[r * 8];
            float4 u = *(const float4*)&BO[c4];
            #pragma unroll
            for (int h = 0; h < 8; h++) {
                float ah = a[h];
                float4 w = *(const float4*)&WO[h * 64 + c4];
                u.x = fmaf(ah, w.x, u.x); u.y = fmaf(ah, w.y, u.y);
                u.z = fmaf(ah, w.z, u.z); u.w = fmaf(ah, w.w, u.w);
            }
            x.x += u.x; x.y += u.y; x.z += u.z; x.w += u.w;
            *(float4*)&XS[r * 64 + c4] = x;
        }
        __syncthreads();
        // LN -> XnS
        for (int r8 = 0; r8 < 8; r8++) {
            int r = warp * 8 + r8;
            float x0 = XS[r * 64 + lane], x1 = XS[r * 64 + lane + 32];
            float s = x0 + x1;
            #pragma unroll
            for (int o = 16; o; o >>= 1) s += __shfl_xor_sync(0xffffffffu, s, o);
            float m = s * 0.015625f;
            float d0 = x0 - m, d1 = x1 - m;
            float vv = d0 * d0 + d1 * d1;
            #pragma unroll
            for (int o = 16; o; o >>= 1) vv += __shfl_xor_sync(0xffffffffu, vv, o);
            float rs = rsqrtf(vv * 0.015625f + 1e-5f);
            XnS[r * 68 + lane]      = tf32of(d0 * rs * G[lane] + Bt[lane]);
            XnS[r * 68 + lane + 32] = tf32of(d1 * rs * G[lane + 32] + Bt[lane + 32]);
        }
        __syncthreads();
        // GEMM1 -> relu -> HS
        float c1[8][4];
        #pragma unroll
        for (int t8 = 0; t8 < 8; t8++) {
            int cc = 64 * wn + 8 * t8 + 2 * qc;
            c1[t8][0] = B1[cc]; c1[t8][1] = B1[cc + 1];
            c1[t8][2] = B1[cc]; c1[t8][3] = B1[cc + 1];
        }
        #pragma unroll
        for (int k = 0; k < 8; k++) {
            u32 a0 = XnS[r0 * 68 + 8 * k + qc];
            u32 a1 = XnS[(r0 + 8) * 68 + 8 * k + qc];
            u32 a2 = XnS[r0 * 68 + 8 * k + qc + 4];
            u32 a3 = XnS[(r0 + 8) * 68 + 8 * k + qc + 4];
            #pragma unroll
            for (int t8 = 0; t8 < 8; t8++) {
                uint2 b = *(const uint2*)&W1F[(((8 * wn + t8) * 8 + k) * 32 + lane) * 2];
                mma_tf32(c1[t8], a0, a1, a2, a3, b.x, b.y);
            }
        }
        #pragma unroll
        for (int t8 = 0; t8 < 8; t8++) {
            int cc = 64 * wn + 8 * t8 + 2 * qc;
            uint2 lo, hi;
            lo.x = tf32of(fmaxf(c1[t8][0], 0.f)); lo.y = tf32of(fmaxf(c1[t8][1], 0.f));
            hi.x = tf32of(fmaxf(c1[t8][2], 0.f)); hi.y = tf32of(fmaxf(c1[t8][3], 0.f));
            *(uint2*)&HS[r0 * 132 + cc] = lo;
            *(uint2*)&HS[(r0 + 8) * 132 + cc] = hi;
        }
        __syncthreads();
        // GEMM2 + residual
        float c2[4][4];
        #pragma unroll
        for (int t4 = 0; t4 < 4; t4++) {
            int cc = 32 * wn + 8 * t4 + 2 * qc;
            c2[t4][0] = B2[cc]; c2[t4][1] = B2[cc + 1];
            c2[t4][2] = B2[cc]; c2[t4][3] = B2[cc + 1];
        }
        #pragma unroll
        for (int k = 0; k < 16; k++) {
            u32 a0 = HS[r0 * 132 + 8 * k + qc];
            u32 a1 = HS[(r0 + 8) * 132 + 8 * k + qc];
            u32 a2 = HS[r0 * 132 + 8 * k + qc + 4];
            u32 a3 = HS[(r0 + 8) * 132 + 8 * k + qc + 4];
            #pragma unroll
            for (int t4 = 0; t4 < 4; t4++) {
                uint2 b = *(const uint2*)&W2F[(((4 * wn + t4) * 16 + k) * 32 + lane) * 2];
                mma_tf32(c2[t4], a0, a1, a2, a3, b.x, b.y);
            }
        }
        #pragma unroll
        for (int t4 = 0; t4 < 4; t4++) {
            int cc = 32 * wn + 8 * t4 + 2 * qc;
            long long ro = base + r0;
            if (ro < E) {
                float2 o;
                o.x = XS[r0 * 64 + cc]     + c2[t4][0];
                o.y = XS[r0 * 64 + cc + 1] + c2[t4][1];
                *(float2*)&eout[ro * 64 + cc] = o;
            }
            if (ro + 8 < E) {
                float2 o;
                o.x = XS[(r0 + 8) * 64 + cc]     + c2[t4][2];
                o.y = XS[(r0 + 8) * 64 + cc + 1] + c2[t4][3];
                *(float2*)&eout[(ro + 8) * 64 + cc] = o;
            }
        }
        __syncthreads();
    }
}

// ---------------- launcher ----------------
extern "C" void kernel_launch(void* const* d_in, const int* in_sizes, int n_in,
                              void* d_out, int out_size) {
    int N = in_sizes[0] / 64;
    int E = in_sizes[1] / 64;

    const int* eidx;
    int base;
    if (in_sizes[2] == 2 * E) { eidx = (const int*)d_in[2]; base = 3; }
    else                      { eidx = (const int*)d_in[n_in - 1]; base = 2; }

    const float* ns = (const float*)d_in[0];
    const float* es = (const float*)d_in[1];
    const float* wq   = (const float*)d_in[base + 0];
    const float* bq   = (const float*)d_in[base + 1];
    const float* wk   = (const float*)d_in[base + 2];
    const float* bk   = (const float*)d_in[base + 3];
    const float* wv   = (const float*)d_in[base + 4];
    const float* bv   = (const float*)d_in[base + 5];
    const float* we   = (const float*)d_in[base + 6];
    const float* be   = (const float*)d_in[base + 7];
    const float* wno  = (const float*)d_in[base + 8];
    const float* bno  = (const float*)d_in[base + 9];
    const float* weo  = (const float*)d_in[base + 10];
    const float* beo  = (const float*)d_in[base + 11];
    const float* n1g  = (const float*)d_in[base + 12];
    const float* n1b  = (const float*)d_in[base + 13];
    const float* e1g  = (const float*)d_in[base + 14];
    const float* e1b  = (const float*)d_in[base + 15];
    const float* n2g  = (const float*)d_in[base + 16];
    const float* n2b  = (const float*)d_in[base + 17];
    const float* e2g  = (const float*)d_in[base + 18];
    const float* e2b  = (const float*)d_in[base + 19];
    const float* nf1w = (const float*)d_in[base + 20];
    const float* nf1b = (const float*)d_in[base + 21];
    const float* nf2w = (const float*)d_in[base + 22];
    const float* nf2b = (const float*)d_in[base + 23];
    const float* ef1w = (const float*)d_in[base + 24];
    const float* ef1b = (const float*)d_in[base + 25];
    const float* ef2w = (const float*)d_in[base + 26];
    const float* ef2b = (const float*)d_in[base + 27];

    float* out      = (float*)d_out;
    float* node_out = out;
    float* edge_out = out + (size_t)N * 64;
    float* att      = edge_out + (size_t)E * 64;

    (void)out_size;

    cudaFuncSetAttribute(k_node_qkv, cudaFuncAttributeMaxDynamicSharedMemorySize, 13120 * 4);
    cudaFuncSetAttribute(k_edge_proj_tc, cudaFuncAttributeMaxDynamicSharedMemorySize, 25792 * 4);
    cudaFuncSetAttribute(k_node_ffn, cudaFuncAttributeMaxDynamicSharedMemorySize, 22400 * 4);
    cudaFuncSetAttribute(k_edge_ffn_tc, cudaFuncAttributeMaxDynamicSharedMemorySize, 52096 * 4);

    k_init<<<(N * 64 + 255) / 256, 256>>>(N);
    k_node_qkv<<<(N + 7) / 8, 256, 13120 * 4>>>(ns, wq, bq, wk, bk, wv, bv, n1g, n1b, N);
    k_edge_proj_tc<<<148, 512, 25792 * 4>>>(es, we, be, e1g, e1b, E);
    {
        long long tot = (long long)E * 8;
        k_scores<<<(unsigned)((tot + 255) / 256), 256>>>(eidx, att, E);
    }
    k_softmax_sum<<<(E + 255) / 256, 256>>>(eidx, att, E);
    k_aggregate<<<(E + 15) / 16, 256>>>(eidx, att, E);
    k_node_ffn<<<(N + 7) / 8, 256, 22400 * 4>>>(ns, wno, bno, n2g, n2b,
                                                nf1w, nf1b, nf2w, nf2b, node_out, N);
    k_edge_ffn_tc<<<148, 512, 52096 * 4>>>(es, att, edge_out, weo, beo, e2g, e2b,
                                           ef1w, ef1b, ef2w, ef2b, E);
}

// round 11
// speedup vs baseline: 1.9713x; 1.1192x over previous
#include <cuda_runtime.h>
#include <math.h>

#define NMAX 100000
#define EMAX 1600000

typedef unsigned int u32;
typedef unsigned long long u64;

// ---------------- PTX helpers ----------------
__device__ __forceinline__ u64 pk2(float x, float y) {
    u64 r; asm("mov.b64 %0, {%1,%2};" : "=l"(r) : "f"(x), "f"(y)); return r;
}
__device__ __forceinline__ float2 upk2(u64 v) {
    float2 r; asm("mov.b64 {%0,%1}, %2;" : "=f"(r.x), "=f"(r.y) : "l"(v)); return r;
}
__device__ __forceinline__ void fma2(u64& d, u64 a, u64 b) {
    asm("fma.rn.f32x2 %0, %1, %2, %0;" : "+l"(d) : "l"(a), "l"(b));
}
__device__ __forceinline__ u32 tf32of(float x) {
    u32 r; asm("cvt.rna.tf32.f32 %0, %1;" : "=r"(r) : "f"(x)); return r;
}
__device__ __forceinline__ float tf32f(float x) {
    u32 r; asm("cvt.rna.tf32.f32 %0, %1;" : "=r"(r) : "f"(x)); return __uint_as_float(r);
}
__device__ __forceinline__ void mma_tf32(float* c, u32 a0, u32 a1, u32 a2, u32 a3,
                                         u32 b0, u32 b1) {
    asm volatile("mma.sync.aligned.m16n8k8.row.col.f32.tf32.tf32.f32 "
                 "{%0,%1,%2,%3},{%4,%5,%6,%7},{%8,%9},{%0,%1,%2,%3};"
                 : "+f"(c[0]), "+f"(c[1]), "+f"(c[2]), "+f"(c[3])
                 : "r"(a0), "r"(a1), "r"(a2), "r"(a3), "r"(b0), "r"(b1));
}
__device__ __forceinline__ void red4(float* p, float a, float b, float c, float d) {
    asm volatile("red.global.v4.f32.add [%0], {%1,%2,%3,%4};"
                 :: "l"(p), "f"(a), "f"(b), "f"(c), "f"(d) : "memory");
}
__device__ __forceinline__ void cp16(u32 smem, const void* gmem, int bytes) {
    asm volatile("cp.async.cg.shared.global [%0], [%1], 16, %2;"
                 :: "r"(smem), "l"(gmem), "r"(bytes));
}
#define CP_COMMIT() asm volatile("cp.async.commit_group;" ::: "memory")
#define CP_WAIT1()  asm volatile("cp.async.wait_group 1;" ::: "memory")
#define CP_WAIT0()  asm volatile("cp.async.wait_group 0;" ::: "memory")

// ---------------- scratch ----------------
__device__ __align__(16) float g_ni[(size_t)NMAX * 64];
__device__ __align__(16) float g_q [(size_t)NMAX * 64];
__device__ __align__(16) float g_k [(size_t)NMAX * 64];
__device__ __align__(16) float g_v [(size_t)NMAX * 64];
__device__ __align__(16) float g_agg[(size_t)NMAX * 64];
__device__ __align__(16) float g_smax[(size_t)NMAX * 8];
__device__ __align__(16) float g_ssum[(size_t)NMAX * 8];
__device__ __align__(16) float g_eterm[(size_t)EMAX * 8];

// ---------------- init ----------------
__global__ void k_init(int N) {
    long long i = (long long)blockIdx.x * blockDim.x + threadIdx.x;
    if (i < (long long)N * 64) g_agg[i] = 0.f;
    if (i < (long long)N * 8) {
        g_smax[i] = __int_as_float(0xff800000);
        g_ssum[i] = 0.f;
    }
}

// ---------------- K1: node LN + Q,K,V projections (f32x2) ----------------
__global__ void k_node_qkv(const float* __restrict__ ns,
                           const float* __restrict__ wq, const float* __restrict__ bq,
                           const float* __restrict__ wk, const float* __restrict__ bk,
                           const float* __restrict__ wv, const float* __restrict__ bv,
                           const float* __restrict__ gg, const float* __restrict__ bb,
                           int N) {
    extern __shared__ float sm[];
    float* W  = sm;            // 3*4096
    float* B  = sm + 12288;
    float* G  = sm + 12480;
    float* Bt = sm + 12544;
    float* xs = sm + 12608;    // 8*64
    int tid = threadIdx.x;
    for (int i = tid; i < 4096; i += 256) { W[i] = wq[i]; W[4096 + i] = wk[i]; W[8192 + i] = wv[i]; }
    if (tid < 64) { B[tid] = bq[tid]; B[64 + tid] = bk[tid]; B[128 + tid] = bv[tid]; G[tid] = gg[tid]; Bt[tid] = bb[tid]; }
    __syncthreads();
    int warp = tid >> 5, lane = tid & 31;
    float* xw = xs + warp * 64;
    for (long long r = (long long)blockIdx.x * 8 + warp; r < N; r += (long long)gridDim.x * 8) {
        const float* xr = ns + r * 64;
        float x0 = xr[lane], x1 = xr[lane + 32];
        float s = x0 + x1;
        #pragma unroll
        for (int o = 16; o; o >>= 1) s += __shfl_xor_sync(0xffffffffu, s, o);
        float m = s * 0.015625f;
        float d0 = x0 - m, d1 = x1 - m;
        float vv = d0 * d0 + d1 * d1;
        #pragma unroll
        for (int o = 16; o; o >>= 1) vv += __shfl_xor_sync(0xffffffffu, vv, o);
        float rs = rsqrtf(vv * 0.015625f + 1e-5f);
        float y0 = d0 * rs * G[lane] + Bt[lane];
        float y1 = d1 * rs * G[lane + 32] + Bt[lane + 32];
        g_ni[r * 64 + lane] = y0; g_ni[r * 64 + lane + 32] = y1;
        xw[lane] = y0; xw[lane + 32] = y1;
        __syncwarp();
        int c2 = 2 * lane;
        u64 aq = *(const u64*)&B[c2];
        u64 ak = *(const u64*)&B[64 + c2];
        u64 av = *(const u64*)&B[128 + c2];
        #pragma unroll 8
        for (int i = 0; i < 64; i++) {
            float xi = xw[i];
            u64 xx = pk2(xi, xi);
            fma2(aq, xx, *(const u64*)&W[i * 64 + c2]);
            fma2(ak, xx, *(const u64*)&W[4096 + i * 64 + c2]);
            fma2(av, xx, *(const u64*)&W[8192 + i * 64 + c2]);
        }
        *(float2*)&g_q[r * 64 + c2] = upk2(aq);
        *(float2*)&g_k[r * 64 + c2] = upk2(ak);
        *(float2*)&g_v[r * 64 + c2] = upk2(av);
        __syncwarp();
    }
}

// ---------------- K2: edge LN + (ei@we+be)·ei per head, split-tf32 mma, cp.async pipeline ---
__global__ __launch_bounds__(512, 1)
void k_edge_proj_tc(const float* __restrict__ es,
                    const float* __restrict__ we, const float* __restrict__ be,
                    const float* __restrict__ gg, const float* __restrict__ bb,
                    int E) {
    extern __shared__ float sm[];
    u32*   WH = (u32*)sm;            // 4096
    u32*   WL = (u32*)(sm + 4096);   // 4096
    float* B  = sm + 8192;
    float* G  = sm + 8256;
    float* Bt = sm + 8320;
    float* ES = sm + 8384;           // 2*8192
    float* XH = sm + 24768;          // 128*68
    float* XL = sm + 33472;          // 128*68
    int tid = threadIdx.x;

    for (int idx = tid; idx < 2048; idx += 512) {
        int L = idx & 31, K = (idx >> 5) & 7, T = idx >> 8;
        int kk = K * 8 + (L & 3), nn = T * 8 + (L >> 2);
        float w0 = we[kk * 64 + nn], w1 = we[(kk + 4) * 64 + nn];
        u32 h0 = tf32of(w0), h1 = tf32of(w1);
        WH[idx * 2] = h0; WH[idx * 2 + 1] = h1;
        WL[idx * 2]     = tf32of(w0 - __uint_as_float(h0));
        WL[idx * 2 + 1] = tf32of(w1 - __uint_as_float(h1));
    }
    if (tid < 64) { B[tid] = be[tid]; G[tid] = gg[tid]; Bt[tid] = bb[tid]; }
    __syncthreads();

    int warp = tid >> 5, lane = tid & 31;
    int wm = warp & 7, wn = warp >> 3;
    int qr = lane >> 2, qc = lane & 3;
    int r0 = 16 * wm + qr;
    long long ntiles = ((long long)E + 127) >> 7;
    long long stride = gridDim.x;
    u32 es_smem0 = (u32)__cvta_generic_to_shared(ES);

    long long t = blockIdx.x;
    if (t < ntiles) {
        long long base = t << 7;
        #pragma unroll
        for (int j = 0; j < 4; j++) {
            int idx = j * 512 + tid;               // float4 index 0..2047
            int r = idx >> 4, c4 = (idx & 15) << 2;
            int ok = (base + r) < E ? 16 : 0;
            cp16(es_smem0 + (u32)((r * 64 + c4) * 4), &es[(base + r) * 64 + c4], ok);
        }
    }
    CP_COMMIT();

    int pb = 0;
    for (; t < ntiles; t += stride) {
        long long tn = t + stride;
        if (tn < ntiles) {
            long long basen = tn << 7;
            u32 dst = es_smem0 + (u32)((pb ^ 1) * 8192 * 4);
            #pragma unroll
            for (int j = 0; j < 4; j++) {
                int idx = j * 512 + tid;
                int r = idx >> 4, c4 = (idx & 15) << 2;
                int ok = (basen + r) < E ? 16 : 0;
                cp16(dst + (u32)((r * 64 + c4) * 4), &es[(basen + r) * 64 + c4], ok);
            }
            CP_COMMIT();
            CP_WAIT1();
        } else {
            CP_COMMIT();
            CP_WAIT0();
        }
        __syncthreads();

        long long base = t << 7;
        const float* EScur = ES + pb * 8192;
        for (int r8 = 0; r8 < 8; r8++) {
            int r = warp * 8 + r8;
            float x0 = EScur[r * 64 + lane], x1 = EScur[r * 64 + lane + 32];
            float s = x0 + x1;
            #pragma unroll
            for (int o = 16; o; o >>= 1) s += __shfl_xor_sync(0xffffffffu, s, o);
            float m = s * 0.015625f;
            float d0 = x0 - m, d1 = x1 - m;
            float vv = d0 * d0 + d1 * d1;
            #pragma unroll
            for (int o = 16; o; o >>= 1) vv += __shfl_xor_sync(0xffffffffu, vv, o);
            float rs = rsqrtf(vv * 0.015625f + 1e-5f);
            float y0 = d0 * rs * G[lane] + Bt[lane];
            float y1 = d1 * rs * G[lane + 32] + Bt[lane + 32];
            float h0 = tf32f(y0), h1 = tf32f(y1);
            XH[r * 68 + lane] = h0;      XH[r * 68 + lane + 32] = h1;
            XL[r * 68 + lane] = tf32f(y0 - h0); XL[r * 68 + lane + 32] = tf32f(y1 - h1);
        }
        __syncthreads();
        float c[4][4];
        #pragma unroll
        for (int t4 = 0; t4 < 4; t4++) {
            int cc = 32 * wn + 8 * t4 + 2 * qc;
            c[t4][0] = B[cc]; c[t4][1] = B[cc + 1];
            c[t4][2] = B[cc]; c[t4][3] = B[cc + 1];
        }
        #pragma unroll
        for (int k = 0; k < 8; k++) {
            u32 ah0 = __float_as_uint(XH[r0 * 68 + 8 * k + qc]);
            u32 ah1 = __float_as_uint(XH[(r0 + 8) * 68 + 8 * k + qc]);
            u32 ah2 = __float_as_uint(XH[r0 * 68 + 8 * k + qc + 4]);
            u32 ah3 = __float_as_uint(XH[(r0 + 8) * 68 + 8 * k + qc + 4]);
            u32 al0 = __float_as_uint(XL[r0 * 68 + 8 * k + qc]);
            u32 al1 = __float_as_uint(XL[(r0 + 8) * 68 + 8 * k + qc]);
            u32 al2 = __float_as_uint(XL[r0 * 68 + 8 * k + qc + 4]);
            u32 al3 = __float_as_uint(XL[(r0 + 8) * 68 + 8 * k + qc + 4]);
            #pragma unroll
            for (int t4 = 0; t4 < 4; t4++) {
                int gidx = (((4 * wn + t4) * 8 + k) * 32 + lane) * 2;
                uint2 bh = *(const uint2*)&WH[gidx];
                uint2 bl = *(const uint2*)&WL[gidx];
                mma_tf32(c[t4], ah0, ah1, ah2, ah3, bh.x, bh.y);
                mma_tf32(c[t4], al0, al1, al2, al3, bh.x, bh.y);
                mma_tf32(c[t4], ah0, ah1, ah2, ah3, bl.x, bl.y);
            }
        }
        #pragma unroll
        for (int t4 = 0; t4 < 4; t4++) {
            int cc = 32 * wn + 8 * t4 + 2 * qc;
            float e00 = XH[r0 * 68 + cc]       + XL[r0 * 68 + cc];
            float e01 = XH[r0 * 68 + cc + 1]   + XL[r0 * 68 + cc + 1];
            float e10 = XH[(r0 + 8) * 68 + cc]     + XL[(r0 + 8) * 68 + cc];
            float e11 = XH[(r0 + 8) * 68 + cc + 1] + XL[(r0 + 8) * 68 + cc + 1];
            float p0 = c[t4][0] * e00 + c[t4][1] * e01;
            float p1 = c[t4][2] * e10 + c[t4][3] * e11;
            p0 += __shfl_xor_sync(0xffffffffu, p0, 1);
            p0 += __shfl_xor_sync(0xffffffffu, p0, 2);
            p1 += __shfl_xor_sync(0xffffffffu, p1, 1);
            p1 += __shfl_xor_sync(0xffffffffu, p1, 2);
            if (qc == 0) {
                long long row = base + 16 * wm + qr;
                if (row < E)     g_eterm[row * 8 + 4 * wn + t4] = p0;
                if (row + 8 < E) g_eterm[(row + 8) * 8 + 4 * wn + t4] = p1;
            }
        }
        __syncthreads();
        pb ^= 1;
    }
}

// ---------------- K3: scores = (q[src]·k[dst] + eterm)/sqrt(D) + segment max ----------------
__global__ void k_scores(const int* __restrict__ eidx, float* __restrict__ att, int E) {
    long long gid = (long long)blockIdx.x * blockDim.x + threadIdx.x;
    if (gid >= (long long)E * 8) return;
    long long e = gid >> 3; int h = (int)(gid & 7);
    int src = eidx[e], dst = eidx[(long long)E + e];
    const float4* qp = (const float4*)&g_q[(size_t)src * 64 + h * 8];
    const float4* kp = (const float4*)&g_k[(size_t)dst * 64 + h * 8];
    float4 q0 = qp[0], q1 = qp[1], k0 = kp[0], k1 = kp[1];
    float sc = q0.x * k0.x + q0.y * k0.y + q0.z * k0.z + q0.w * k0.w
             + q1.x * k1.x + q1.y * k1.y + q1.z * k1.z + q1.w * k1.w;
    sc = (sc + g_eterm[gid]) * 0.35355339059327373f;
    att[gid] = sc;
    float* amp = &g_smax[(size_t)src * 8 + h];
    if (sc >= 0.f) atomicMax((int*)amp, __float_as_int(sc));
    else atomicMin((unsigned int*)amp, __float_as_uint(sc));
}

// ---------------- K4: exp(score - max) + segment sum ----------------
__global__ void k_softmax_sum(const int* __restrict__ eidx, float* __restrict__ att, int E) {
    long long e = (long long)blockIdx.x * blockDim.x + threadIdx.x;
    if (e >= E) return;
    int src = eidx[e];
    float4 s0 = *(float4*)&att[e * 8];
    float4 s1 = *(float4*)&att[e * 8 + 4];
    float4 m0 = *(float4*)&g_smax[(size_t)src * 8];
    float4 m1 = *(float4*)&g_smax[(size_t)src * 8 + 4];
    s0.x = __expf(s0.x - m0.x); s0.y = __expf(s0.y - m0.y);
    s0.z = __expf(s0.z - m0.z); s0.w = __expf(s0.w - m0.w);
    s1.x = __expf(s1.x - m1.x); s1.y = __expf(s1.y - m1.y);
    s1.z = __expf(s1.z - m1.z); s1.w = __expf(s1.w - m1.w);
    *(float4*)&att[e * 8] = s0;
    *(float4*)&att[e * 8 + 4] = s1;
    float* ss = &g_ssum[(size_t)src * 8];
    red4(ss,     s0.x, s0.y, s0.z, s0.w);
    red4(ss + 4, s1.x, s1.y, s1.z, s1.w);
}

// ---------------- K5: finalize attention + scatter-aggregate (2 edges/warp) ----------------
__global__ void k_aggregate(const int* __restrict__ eidx, float* __restrict__ att, int E) {
    __shared__ float as[8][2][8];
    int tid = threadIdx.x, warp = tid >> 5, lane = tid & 31;
    int side = lane >> 4, hl = lane & 15;
    for (long long e0 = (long long)blockIdx.x * 16 + warp * 2; e0 < E;
         e0 += (long long)gridDim.x * 16) {
        long long e = e0 + side;
        bool ok = e < E;
        int src = 0, dst = 0;
        if (ok) { src = eidx[e]; dst = eidx[(long long)E + e]; }
        if (ok && hl < 8) {
            float ex = att[e * 8 + hl];
            float den = g_ssum[(size_t)src * 8 + hl];
            float a = ex / (den + 1e-12f);
            att[e * 8 + hl] = a;
            as[warp][side][hl] = a;
        }
        __syncwarp();
        if (ok) {
            int c4 = hl * 4;
            float4 v = *(const float4*)&g_v[(size_t)dst * 64 + c4];
            float4 n = *(const float4*)&g_ni[(size_t)dst * 64 + c4];
            float a = as[warp][side][hl >> 1];
            red4(&g_agg[(size_t)src * 64 + c4],
                 a * v.x * n.x, a * v.y * n.y, a * v.z * n.z, a * v.w * n.w);
        }
        __syncwarp();
    }
}

// ---------------- K6: node update + node FFN (f32x2) ----------------
__global__ void k_node_ffn(const float* __restrict__ ns,
                           const float* __restrict__ wno, const float* __restrict__ bno,
                           const float* __restrict__ g2, const float* __restrict__ b2,
                           const float* __restrict__ f1w, const float* __restrict__ f1b,
                           const float* __restrict__ f2w, const float* __restrict__ f2b,
                           float* __restrict__ node_out, int N) {
    extern __shared__ float sm[];
    float* Wno = sm;
    float* W1  = sm + 4096;
    float* W2  = sm + 12288;
    float* Bno = sm + 20480;
    float* B1  = sm + 20544;
    float* B2  = sm + 20672;
    float* G   = sm + 20736;
    float* Bt  = sm + 20800;
    float* xs  = sm + 20864;
    float* hs  = sm + 21376;
    int tid = threadIdx.x;
    for (int i = tid; i < 4096; i += 256) Wno[i] = wno[i];
    for (int i = tid; i < 8192; i += 256) { W1[i] = f1w[i]; W2[i] = f2w[i]; }
    if (tid < 128) B1[tid] = f1b[tid];
    if (tid < 64) { Bno[tid] = bno[tid]; B2[tid] = f2b[tid]; G[tid] = g2[tid]; Bt[tid] = b2[tid]; }
    __syncthreads();
    int warp = tid >> 5, lane = tid & 31;
    int c2 = 2 * lane;
    float* xw = xs + warp * 64;
    float* hw = hs + warp * 128;
    for (long long r = (long long)blockIdx.x * 8 + warp; r < N; r += (long long)gridDim.x * 8) {
        float2 ag = *(const float2*)&g_agg[r * 64 + c2];
        *(float2*)&xw[c2] = ag;
        __syncwarp();
        u64 sacc = pk2(ns[r * 64 + c2] + Bno[c2], ns[r * 64 + c2 + 1] + Bno[c2 + 1]);
        #pragma unroll 8
        for (int i = 0; i < 64; i++) {
            float xi = xw[i];
            fma2(sacc, pk2(xi, xi), *(const u64*)&Wno[i * 64 + c2]);
        }
        float2 sv = upk2(sacc);
        __syncwarp();
        float sum = sv.x + sv.y;
        #pragma unroll
        for (int o = 16; o; o >>= 1) sum += __shfl_xor_sync(0xffffffffu, sum, o);
        float m = sum * 0.015625f;
        float d0 = sv.x - m, d1 = sv.y - m;
        float vv = d0 * d0 + d1 * d1;
        #pragma unroll
        for (int o = 16; o; o >>= 1) vv += __shfl_xor_sync(0xffffffffu, vv, o);
        float rs = rsqrtf(vv * 0.015625f + 1e-5f);
        xw[c2]     = d0 * rs * G[c2] + Bt[c2];
        xw[c2 + 1] = d1 * rs * G[c2 + 1] + Bt[c2 + 1];
        __syncwarp();
        u64 h01 = *(const u64*)&B1[c2];
        u64 h23 = *(const u64*)&B1[64 + c2];
        #pragma unroll 8
        for (int i = 0; i < 64; i++) {
            float xi = xw[i];
            u64 xx = pk2(xi, xi);
            fma2(h01, xx, *(const u64*)&W1[i * 128 + c2]);
            fma2(h23, xx, *(const u64*)&W1[i * 128 + 64 + c2]);
        }
        float2 ha = upk2(h01), hb = upk2(h23);
        hw[c2] = fmaxf(ha.x, 0.f); hw[c2 + 1] = fmaxf(ha.y, 0.f);
        hw[64 + c2] = fmaxf(hb.x, 0.f); hw[64 + c2 + 1] = fmaxf(hb.y, 0.f);
        __syncwarp();
        u64 yacc = *(const u64*)&B2[c2];
        #pragma unroll 8
        for (int i = 0; i < 128; i++) {
            float hi = hw[i];
            fma2(yacc, pk2(hi, hi), *(const u64*)&W2[i * 64 + c2]);
        }
        float2 yv = upk2(yacc);
        float2 o; o.x = sv.x + yv.x; o.y = sv.y + yv.y;
        *(float2*)&node_out[r * 64 + c2] = o;
        __syncwarp();
    }
}

// ---------------- K7: edge update + edge FFN (tf32 mma, cp.async pipeline) ----------------
__global__ __launch_bounds__(512, 1)
void k_edge_ffn_tc(const float* __restrict__ es, const float* __restrict__ att,
                   float* __restrict__ eout,
                   const float* __restrict__ weo, const float* __restrict__ beo,
                   const float* __restrict__ g2, const float* __restrict__ b2,
                   const float* __restrict__ f1w, const float* __restrict__ f1b,
                   const float* __restrict__ f2w, const float* __restrict__ f2b,
                   int E) {
    extern __shared__ float sm[];
    u32*   W1F = (u32*)sm;              // 8192
    u32*   W2F = (u32*)(sm + 8192);     // 8192
    float* B1  = sm + 16384;
    float* B2  = sm + 16512;
    float* G   = sm + 16576;
    float* Bt  = sm + 16640;
    float* WO  = sm + 16704;            // 512
    float* BO  = sm + 17216;            // 64
    float* ES  = sm + 17280;            // 2*8192 (raw es -> in-place x)
    float* AT  = sm + 33664;            // 2*1024
    u32*   XnS = (u32*)(sm + 35712);    // stride 68 (union lo)
    u32*   HS  = (u32*)(sm + 35712);    // stride 132 (union, after sync)
    int tid = threadIdx.x;

    for (int idx = tid; idx < 4096; idx += 512) {
        int L = idx & 31, K = (idx >> 5) & 7, T = idx >> 8;
        int kk = K * 8 + (L & 3), nn = T * 8 + (L >> 2);
        W1F[idx * 2]     = tf32of(f1w[kk * 128 + nn]);
        W1F[idx * 2 + 1] = tf32of(f1w[(kk + 4) * 128 + nn]);
    }
    for (int idx = tid; idx < 4096; idx += 512) {
        int L = idx & 31, K = (idx >> 5) & 15, T = idx >> 9;
        int kk = K * 8 + (L & 3), nn = T * 8 + (L >> 2);
        W2F[idx * 2]     = tf32of(f2w[kk * 64 + nn]);
        W2F[idx * 2 + 1] = tf32of(f2w[(kk + 4) * 64 + nn]);
    }
    if (tid < 512) WO[tid] = weo[tid];
    if (tid < 128) B1[tid] = f1b[tid];
    if (tid < 64) { B2[tid] = f2b[tid]; G[tid] = g2[tid]; Bt[tid] = b2[tid]; BO[tid] = beo[tid]; }
    __syncthreads();

    int warp = tid >> 5, lane = tid & 31;
    int wm = warp & 7, wn = warp >> 3;
    int qr = lane >> 2, qc = lane & 3;
    int r0 = 16 * wm + qr;
    long long ntiles = ((long long)E + 127) >> 7;
    long long stride = gridDim.x;
    u32 es_s0 = (u32)__cvta_generic_to_shared(ES);
    u32 at_s0 = (u32)__cvta_generic_to_shared(AT);

    long long t = blockIdx.x;
    if (t < ntiles) {
        long long base = t << 7;
        #pragma unroll
        for (int j = 0; j < 4; j++) {
            int idx = j * 512 + tid;
            int r = idx >> 4, c4 = (idx & 15) << 2;
            int ok = (base + r) < E ? 16 : 0;
            cp16(es_s0 + (u32)((r * 64 + c4) * 4), &es[(base + r) * 64 + c4], ok);
        }
        if (tid < 256) {
            int ok = (base + (tid >> 1) * 1 + 0) < E ? 16 : 0;
            cp16(at_s0 + (u32)(tid * 16), &att[base * 8 + tid * 4], ok);
        }
    }
    CP_COMMIT();

    int pb = 0;
    for (; t < ntiles; t += stride) {
        long long tn = t + stride;
        if (tn < ntiles) {
            long long basen = tn << 7;
            u32 esd = es_s0 + (u32)((pb ^ 1) * 8192 * 4);
            u32 atd = at_s0 + (u32)((pb ^ 1) * 1024 * 4);
            #pragma unroll
            for (int j = 0; j < 4; j++) {
                int idx = j * 512 + tid;
                int r = idx >> 4, c4 = (idx & 15) << 2;
                int ok = (basen + r) < E ? 16 : 0;
                cp16(esd + (u32)((r * 64 + c4) * 4), &es[(basen + r) * 64 + c4], ok);
            }
            if (tid < 256) {
                int ok = (basen + (tid >> 1)) < E ? 16 : 0;
                cp16(atd + (u32)(tid * 16), &att[basen * 8 + tid * 4], ok);
            }
            CP_COMMIT();
            CP_WAIT1();
        } else {
            CP_COMMIT();
            CP_WAIT0();
        }
        __syncthreads();

        long long base = t << 7;
        float* XS = ES + pb * 8192;
        const float* ATc = AT + pb * 1024;

        // phase A (warp-local rows 8*warp..+7): x = es + att@weo + beo (in place), then LN
        #pragma unroll
        for (int j = 0; j < 4; j++) {
            int idx = j * 32 + lane;                 // 0..127
            int r = warp * 8 + (idx >> 4);
            int c4 = (idx & 15) << 2;
            float4 x = *(float4*)&XS[r * 64 + c4];
            const float* a = &ATc[r * 8];
            float4 u = *(const float4*)&BO[c4];
            #pragma unroll
            for (int h = 0; h < 8; h++) {
                float ah = a[h];
                float4 w = *(const float4*)&WO[h * 64 + c4];
                u.x = fmaf(ah, w.x, u.x); u.y = fmaf(ah, w.y, u.y);
                u.z = fmaf(ah, w.z, u.z); u.w = fmaf(ah, w.w, u.w);
            }
            x.x += u.x; x.y += u.y; x.z += u.z; x.w += u.w;
            *(float4*)&XS[r * 64 + c4] = x;
        }
        __syncwarp();
        for (int r8 = 0; r8 < 8; r8++) {
            int r = warp * 8 + r8;
            float x0 = XS[r * 64 + lane], x1 = XS[r * 64 + lane + 32];
            float s = x0 + x1;
            #pragma unroll
            for (int o = 16; o; o >>= 1) s += __shfl_xor_sync(0xffffffffu, s, o);
            float m = s * 0.015625f;
            float d0 = x0 - m, d1 = x1 - m;
            float vv = d0 * d0 + d1 * d1;
            #pragma unroll
            for (int o = 16; o; o >>= 1) vv += __shfl_xor_sync(0xffffffffu, vv, o);
            float rs = rsqrtf(vv * 0.015625f + 1e-5f);
            XnS[r * 68 + lane]      = tf32of(d0 * rs * G[lane] + Bt[lane]);
            XnS[r * 68 + lane + 32] = tf32of(d1 * rs * G[lane + 32] + Bt[lane + 32]);
        }
        __syncthreads();
        // GEMM1 (accumulate in regs from XnS)
        float c1[8][4];
        #pragma unroll
        for (int t8 = 0; t8 < 8; t8++) {
            int cc = 64 * wn + 8 * t8 + 2 * qc;
            c1[t8][0] = B1[cc]; c1[t8][1] = B1[cc + 1];
            c1[t8][2] = B1[cc]; c1[t8][3] = B1[cc + 1];
        }
        #pragma unroll
        for (int k = 0; k < 8; k++) {
            u32 a0 = XnS[r0 * 68 + 8 * k + qc];
            u32 a1 = XnS[(r0 + 8) * 68 + 8 * k + qc];
            u32 a2 = XnS[r0 * 68 + 8 * k + qc + 4];
            u32 a3 = XnS[(r0 + 8) * 68 + 8 * k + qc + 4];
            #pragma unroll
            for (int t8 = 0; t8 < 8; t8++) {
                uint2 b = *(const uint2*)&W1F[(((8 * wn + t8) * 8 + k) * 32 + lane) * 2];
                mma_tf32(c1[t8], a0, a1, a2, a3, b.x, b.y);
            }
        }
        __syncthreads();   // XnS fully consumed; HS may overwrite union region
        #pragma unroll
        for (int t8 = 0; t8 < 8; t8++) {
            int cc = 64 * wn + 8 * t8 + 2 * qc;
            uint2 lo, hi;
            lo.x = tf32of(fmaxf(c1[t8][0], 0.f)); lo.y = tf32of(fmaxf(c1[t8][1], 0.f));
            hi.x = tf32of(fmaxf(c1[t8][2], 0.f)); hi.y = tf32of(fmaxf(c1[t8][3], 0.f));
            *(uint2*)&HS[r0 * 132 + cc] = lo;
            *(uint2*)&HS[(r0 + 8) * 132 + cc] = hi;
        }
        __syncthreads();
        // GEMM2 + residual
        float c2[4][4];
        #pragma unroll
        for (int t4 = 0; t4 < 4; t4++) {
            int cc = 32 * wn + 8 * t4 + 2 * qc;
            c2[t4][0] = B2[cc]; c2[t4][1] = B2[cc + 1];
            c2[t4][2] = B2[cc]; c2[t4][3] = B2[cc + 1];
        }
        #pragma unroll
        for (int k = 0; k < 16; k++) {
            u32 a0 = HS[r0 * 132 + 8 * k + qc];
            u32 a1 = HS[(r0 + 8) * 132 + 8 * k + qc];
            u32 a2 = HS[r0 * 132 + 8 * k + qc + 4];
            u32 a3 = HS[(r0 + 8) * 132 + 8 * k + qc + 4];
            #pragma unroll
            for (int t4 = 0; t4 < 4; t4++) {
                uint2 b = *(const uint2*)&W2F[(((4 * wn + t4) * 16 + k) * 32 + lane) * 2];
                mma_tf32(c2[t4], a0, a1, a2, a3, b.x, b.y);
            }
        }
        #pragma unroll
        for (int t4 = 0; t4 < 4; t4++) {
            int cc = 32 * wn + 8 * t4 + 2 * qc;
            long long ro = base + r0;
            if (ro < E) {
                float2 o;
                o.x = XS[r0 * 64 + cc]     + c2[t4][0];
                o.y = XS[r0 * 64 + cc + 1] + c2[t4][1];
                *(float2*)&eout[ro * 64 + cc] = o;
            }
            if (ro + 8 < E) {
                float2 o;
                o.x = XS[(r0 + 8) * 64 + cc]     + c2[t4][2];
                o.y = XS[(r0 + 8) * 64 + cc + 1] + c2[t4][3];
                *(float2*)&eout[(ro + 8) * 64 + cc] = o;
            }
        }
        __syncthreads();
        pb ^= 1;
    }
}

// ---------------- launcher ----------------
extern "C" void kernel_launch(void* const* d_in, const int* in_sizes, int n_in,
                              void* d_out, int out_size) {
    int N = in_sizes[0] / 64;
    int E = in_sizes[1] / 64;

    const int* eidx;
    int base;
    if (in_sizes[2] == 2 * E) { eidx = (const int*)d_in[2]; base = 3; }
    else                      { eidx = (const int*)d_in[n_in - 1]; base = 2; }

    const float* ns = (const float*)d_in[0];
    const float* es = (const float*)d_in[1];
    const float* wq   = (const float*)d_in[base + 0];
    const float* bq   = (const float*)d_in[base + 1];
    const float* wk   = (const float*)d_in[base + 2];
    const float* bk   = (const float*)d_in[base + 3];
    const float* wv   = (const float*)d_in[base + 4];
    const float* bv   = (const float*)d_in[base + 5];
    const float* we   = (const float*)d_in[base + 6];
    const float* be   = (const float*)d_in[base + 7];
    const float* wno  = (const float*)d_in[base + 8];
    const float* bno  = (const float*)d_in[base + 9];
    const float* weo  = (const float*)d_in[base + 10];
    const float* beo  = (const float*)d_in[base + 11];
    const float* n1g  = (const float*)d_in[base + 12];
    const float* n1b  = (const float*)d_in[base + 13];
    const float* e1g  = (const float*)d_in[base + 14];
    const float* e1b  = (const float*)d_in[base + 15];
    const float* n2g  = (const float*)d_in[base + 16];
    const float* n2b  = (const float*)d_in[base + 17];
    const float* e2g  = (const float*)d_in[base + 18];
    const float* e2b  = (const float*)d_in[base + 19];
    const float* nf1w = (const float*)d_in[base + 20];
    const float* nf1b = (const float*)d_in[base + 21];
    const float* nf2w = (const float*)d_in[base + 22];
    const float* nf2b = (const float*)d_in[base + 23];
    const float* ef1w = (const float*)d_in[base + 24];
    const float* ef1b = (const float*)d_in[base + 25];
    const float* ef2w = (const float*)d_in[base + 26];
    const float* ef2b = (const float*)d_in[base + 27];

    float* out      = (float*)d_out;
    float* node_out = out;
    float* edge_out = out + (size_t)N * 64;
    float* att      = edge_out + (size_t)E * 64;

    (void)out_size;

    cudaFuncSetAttribute(k_node_qkv, cudaFuncAttributeMaxDynamicSharedMemorySize, 13120 * 4);
    cudaFuncSetAttribute(k_edge_proj_tc, cudaFuncAttributeMaxDynamicSharedMemorySize, 42176 * 4);
    cudaFuncSetAttribute(k_node_ffn, cudaFuncAttributeMaxDynamicSharedMemorySize, 22400 * 4);
    cudaFuncSetAttribute(k_edge_ffn_tc, cudaFuncAttributeMaxDynamicSharedMemorySize, 52608 * 4);

    k_init<<<(N * 64 + 255) / 256, 256>>>(N);
    k_node_qkv<<<(N + 7) / 8, 256, 13120 * 4>>>(ns, wq, bq, wk, bk, wv, bv, n1g, n1b, N);
    k_edge_proj_tc<<<148, 512, 42176 * 4>>>(es, we, be, e1g, e1b, E);
    {
        long long tot = (long long)E * 8;
        k_scores<<<(unsigned)((tot + 255) / 256), 256>>>(eidx, att, E);
    }
    k_softmax_sum<<<(E + 255) / 256, 256>>>(eidx, att, E);
    k_aggregate<<<(E + 15) / 16, 256>>>(eidx, att, E);
    k_node_ffn<<<(N + 7) / 8, 256, 22400 * 4>>>(ns, wno, bno, n2g, n2b,
                                                nf1w, nf1b, nf2w, nf2b, node_out, N);
    k_edge_ffn_tc<<<148, 512, 52608 * 4>>>(es, att, edge_out, weo, beo, e2g, e2b,
                                           ef1w, ef1b, ef2w, ef2b, E);
}

// round 12
// speedup vs baseline: 2.0736x; 1.0519x over previous
#include <cuda_runtime.h>
#include <math.h>

#define NMAX 100000
#define EMAX 1600000

typedef unsigned int u32;
typedef unsigned long long u64;

// ---------------- PTX helpers ----------------
__device__ __forceinline__ u64 pk2(float x, float y) {
    u64 r; asm("mov.b64 %0, {%1,%2};" : "=l"(r) : "f"(x), "f"(y)); return r;
}
__device__ __forceinline__ float2 upk2(u64 v) {
    float2 r; asm("mov.b64 {%0,%1}, %2;" : "=f"(r.x), "=f"(r.y) : "l"(v)); return r;
}
__device__ __forceinline__ void fma2(u64& d, u64 a, u64 b) {
    asm("fma.rn.f32x2 %0, %1, %2, %0;" : "+l"(d) : "l"(a), "l"(b));
}
__device__ __forceinline__ u32 tf32of(float x) {
    u32 r; asm("cvt.rna.tf32.f32 %0, %1;" : "=r"(r) : "f"(x)); return r;
}
__device__ __forceinline__ float tf32f(float x) {
    u32 r; asm("cvt.rna.tf32.f32 %0, %1;" : "=r"(r) : "f"(x)); return __uint_as_float(r);
}
__device__ __forceinline__ void mma_tf32(float* c, u32 a0, u32 a1, u32 a2, u32 a3,
                                         u32 b0, u32 b1) {
    asm volatile("mma.sync.aligned.m16n8k8.row.col.f32.tf32.tf32.f32 "
                 "{%0,%1,%2,%3},{%4,%5,%6,%7},{%8,%9},{%0,%1,%2,%3};"
                 : "+f"(c[0]), "+f"(c[1]), "+f"(c[2]), "+f"(c[3])
                 : "r"(a0), "r"(a1), "r"(a2), "r"(a3), "r"(b0), "r"(b1));
}
__device__ __forceinline__ void red4(float* p, float a, float b, float c, float d) {
    asm volatile("red.global.v4.f32.add [%0], {%1,%2,%3,%4};"
                 :: "l"(p), "f"(a), "f"(b), "f"(c), "f"(d) : "memory");
}
__device__ __forceinline__ void cp16(u32 smem, const void* gmem, int bytes) {
    asm volatile("cp.async.cg.shared.global [%0], [%1], 16, %2;"
                 :: "r"(smem), "l"(gmem), "r"(bytes));
}
#define CP_COMMIT() asm volatile("cp.async.commit_group;" ::: "memory")
#define CP_WAIT1()  asm volatile("cp.async.wait_group 1;" ::: "memory")
#define CP_WAIT0()  asm volatile("cp.async.wait_group 0;" ::: "memory")

// ---------------- scratch ----------------
__device__ __align__(16) float g_q [(size_t)NMAX * 64];
__device__ __align__(16) float g_k [(size_t)NMAX * 64];
__device__ __align__(16) float g_vn[(size_t)NMAX * 64];   // v ⊙ ni
__device__ __align__(16) float g_agg[(size_t)NMAX * 64];
__device__ __align__(16) float g_ssum[(size_t)NMAX * 8];
__device__ __align__(16) float g_eterm[(size_t)EMAX * 8];

// ---------------- init ----------------
__global__ void k_init(int N) {
    long long i = (long long)blockIdx.x * blockDim.x + threadIdx.x;
    if (i < (long long)N * 64) g_agg[i] = 0.f;
    if (i < (long long)N * 8) g_ssum[i] = 0.f;
}

// ---------------- K1: node LN + Q,K,V projections (f32x2), vn = v*ni ----------------
__global__ void k_node_qkv(const float* __restrict__ ns,
                           const float* __restrict__ wq, const float* __restrict__ bq,
                           const float* __restrict__ wk, const float* __restrict__ bk,
                           const float* __restrict__ wv, const float* __restrict__ bv,
                           const float* __restrict__ gg, const float* __restrict__ bb,
                           int N) {
    extern __shared__ float sm[];
    float* W  = sm;            // 3*4096
    float* B  = sm + 12288;
    float* G  = sm + 12480;
    float* Bt = sm + 12544;
    float* xs = sm + 12608;    // 8*64
    int tid = threadIdx.x;
    for (int i = tid; i < 4096; i += 256) { W[i] = wq[i]; W[4096 + i] = wk[i]; W[8192 + i] = wv[i]; }
    if (tid < 64) { B[tid] = bq[tid]; B[64 + tid] = bk[tid]; B[128 + tid] = bv[tid]; G[tid] = gg[tid]; Bt[tid] = bb[tid]; }
    __syncthreads();
    int warp = tid >> 5, lane = tid & 31;
    float* xw = xs + warp * 64;
    for (long long r = (long long)blockIdx.x * 8 + warp; r < N; r += (long long)gridDim.x * 8) {
        const float* xr = ns + r * 64;
        float x0 = xr[lane], x1 = xr[lane + 32];
        float s = x0 + x1;
        #pragma unroll
        for (int o = 16; o; o >>= 1) s += __shfl_xor_sync(0xffffffffu, s, o);
        float m = s * 0.015625f;
        float d0 = x0 - m, d1 = x1 - m;
        float vv = d0 * d0 + d1 * d1;
        #pragma unroll
        for (int o = 16; o; o >>= 1) vv += __shfl_xor_sync(0xffffffffu, vv, o);
        float rs = rsqrtf(vv * 0.015625f + 1e-5f);
        float y0 = d0 * rs * G[lane] + Bt[lane];
        float y1 = d1 * rs * G[lane + 32] + Bt[lane + 32];
        xw[lane] = y0; xw[lane + 32] = y1;
        __syncwarp();
        int c2 = 2 * lane;
        u64 aq = *(const u64*)&B[c2];
        u64 ak = *(const u64*)&B[64 + c2];
        u64 av = *(const u64*)&B[128 + c2];
        #pragma unroll 8
        for (int i = 0; i < 64; i++) {
            float xi = xw[i];
            u64 xx = pk2(xi, xi);
            fma2(aq, xx, *(const u64*)&W[i * 64 + c2]);
            fma2(ak, xx, *(const u64*)&W[4096 + i * 64 + c2]);
            fma2(av, xx, *(const u64*)&W[8192 + i * 64 + c2]);
        }
        *(float2*)&g_q[r * 64 + c2] = upk2(aq);
        *(float2*)&g_k[r * 64 + c2] = upk2(ak);
        float2 vproj = upk2(av);
        float2 vn; vn.x = vproj.x * xw[c2]; vn.y = vproj.y * xw[c2 + 1];
        *(float2*)&g_vn[r * 64 + c2] = vn;
        __syncwarp();
    }
}

// ---------------- K2: edge LN + (ei@we+be)·ei per head, 2-pass split-tf32, cp.async -------
// smem floats: WH 4096 | B 64 | G 64 | Bt 64 | ES 16384 | XH 8704 | XL 8704 = 38080
__global__ __launch_bounds__(512, 1)
void k_edge_proj_tc(const float* __restrict__ es,
                    const float* __restrict__ we, const float* __restrict__ be,
                    const float* __restrict__ gg, const float* __restrict__ bb,
                    int E) {
    extern __shared__ float sm[];
    u32*   WH = (u32*)sm;            // 4096
    float* B  = sm + 4096;
    float* G  = sm + 4160;
    float* Bt = sm + 4224;
    float* ES = sm + 4288;           // 2*8192
    float* XH = sm + 20672;          // 128*68
    float* XL = sm + 29376;          // 128*68
    int tid = threadIdx.x;

    for (int idx = tid; idx < 2048; idx += 512) {
        int L = idx & 31, K = (idx >> 5) & 7, T = idx >> 8;
        int kk = K * 8 + (L & 3), nn = T * 8 + (L >> 2);
        WH[idx * 2]     = tf32of(we[kk * 64 + nn]);
        WH[idx * 2 + 1] = tf32of(we[(kk + 4) * 64 + nn]);
    }
    if (tid < 64) { B[tid] = be[tid]; G[tid] = gg[tid]; Bt[tid] = bb[tid]; }
    __syncthreads();

    int warp = tid >> 5, lane = tid & 31;
    int wm = warp & 7, wn = warp >> 3;
    int qr = lane >> 2, qc = lane & 3;
    int r0 = 16 * wm + qr;
    long long ntiles = ((long long)E + 127) >> 7;
    long long stride = gridDim.x;
    u32 es_smem0 = (u32)__cvta_generic_to_shared(ES);

    long long t = blockIdx.x;
    if (t < ntiles) {
        long long base = t << 7;
        #pragma unroll
        for (int j = 0; j < 4; j++) {
            int idx = j * 512 + tid;
            int r = idx >> 4, c4 = (idx & 15) << 2;
            int ok = (base + r) < E ? 16 : 0;
            cp16(es_smem0 + (u32)((r * 64 + c4) * 4), &es[(base + r) * 64 + c4], ok);
        }
    }
    CP_COMMIT();

    int pb = 0;
    for (; t < ntiles; t += stride) {
        long long tn = t + stride;
        if (tn < ntiles) {
            long long basen = tn << 7;
            u32 dst = es_smem0 + (u32)((pb ^ 1) * 8192 * 4);
            #pragma unroll
            for (int j = 0; j < 4; j++) {
                int idx = j * 512 + tid;
                int r = idx >> 4, c4 = (idx & 15) << 2;
                int ok = (basen + r) < E ? 16 : 0;
                cp16(dst + (u32)((r * 64 + c4) * 4), &es[(basen + r) * 64 + c4], ok);
            }
            CP_COMMIT();
            CP_WAIT1();
        } else {
            CP_COMMIT();
            CP_WAIT0();
        }
        __syncthreads();

        long long base = t << 7;
        const float* EScur = ES + pb * 8192;
        for (int r8 = 0; r8 < 8; r8++) {
            int r = warp * 8 + r8;
            float x0 = EScur[r * 64 + lane], x1 = EScur[r * 64 + lane + 32];
            float s = x0 + x1;
            #pragma unroll
            for (int o = 16; o; o >>= 1) s += __shfl_xor_sync(0xffffffffu, s, o);
            float m = s * 0.015625f;
            float d0 = x0 - m, d1 = x1 - m;
            float vv = d0 * d0 + d1 * d1;
            #pragma unroll
            for (int o = 16; o; o >>= 1) vv += __shfl_xor_sync(0xffffffffu, vv, o);
            float rs = rsqrtf(vv * 0.015625f + 1e-5f);
            float y0 = d0 * rs * G[lane] + Bt[lane];
            float y1 = d1 * rs * G[lane + 32] + Bt[lane + 32];
            float h0 = tf32f(y0), h1 = tf32f(y1);
            XH[r * 68 + lane] = h0;      XH[r * 68 + lane + 32] = h1;
            XL[r * 68 + lane] = tf32f(y0 - h0); XL[r * 68 + lane + 32] = tf32f(y1 - h1);
        }
        __syncthreads();
        float c[4][4];
        #pragma unroll
        for (int t4 = 0; t4 < 4; t4++) {
            int cc = 32 * wn + 8 * t4 + 2 * qc;
            c[t4][0] = B[cc]; c[t4][1] = B[cc + 1];
            c[t4][2] = B[cc]; c[t4][3] = B[cc + 1];
        }
        #pragma unroll
        for (int k = 0; k < 8; k++) {
            u32 ah0 = __float_as_uint(XH[r0 * 68 + 8 * k + qc]);
            u32 ah1 = __float_as_uint(XH[(r0 + 8) * 68 + 8 * k + qc]);
            u32 ah2 = __float_as_uint(XH[r0 * 68 + 8 * k + qc + 4]);
            u32 ah3 = __float_as_uint(XH[(r0 + 8) * 68 + 8 * k + qc + 4]);
            u32 al0 = __float_as_uint(XL[r0 * 68 + 8 * k + qc]);
            u32 al1 = __float_as_uint(XL[(r0 + 8) * 68 + 8 * k + qc]);
            u32 al2 = __float_as_uint(XL[r0 * 68 + 8 * k + qc + 4]);
            u32 al3 = __float_as_uint(XL[(r0 + 8) * 68 + 8 * k + qc + 4]);
            #pragma unroll
            for (int t4 = 0; t4 < 4; t4++) {
                int gidx = (((4 * wn + t4) * 8 + k) * 32 + lane) * 2;
                uint2 bh = *(const uint2*)&WH[gidx];
                mma_tf32(c[t4], ah0, ah1, ah2, ah3, bh.x, bh.y);
                mma_tf32(c[t4], al0, al1, al2, al3, bh.x, bh.y);
            }
        }
        #pragma unroll
        for (int t4 = 0; t4 < 4; t4++) {
            int cc = 32 * wn + 8 * t4 + 2 * qc;
            float e00 = XH[r0 * 68 + cc]       + XL[r0 * 68 + cc];
            float e01 = XH[r0 * 68 + cc + 1]   + XL[r0 * 68 + cc + 1];
            float e10 = XH[(r0 + 8) * 68 + cc]     + XL[(r0 + 8) * 68 + cc];
            float e11 = XH[(r0 + 8) * 68 + cc + 1] + XL[(r0 + 8) * 68 + cc + 1];
            float p0 = c[t4][0] * e00 + c[t4][1] * e01;
            float p1 = c[t4][2] * e10 + c[t4][3] * e11;
            p0 += __shfl_xor_sync(0xffffffffu, p0, 1);
            p0 += __shfl_xor_sync(0xffffffffu, p0, 2);
            p1 += __shfl_xor_sync(0xffffffffu, p1, 1);
            p1 += __shfl_xor_sync(0xffffffffu, p1, 2);
            if (qc == 0) {
                long long row = base + 16 * wm + qr;
                if (row < E)     g_eterm[row * 8 + 4 * wn + t4] = p0;
                if (row + 8 < E) g_eterm[(row + 8) * 8 + 4 * wn + t4] = p1;
            }
        }
        __syncthreads();
        pb ^= 1;
    }
}

// ---------------- K3: att = exp(score) + segment sum (no max; scores bounded) -------------
__global__ void k_scores(const int* __restrict__ eidx, float* __restrict__ att, int E) {
    long long gid = (long long)blockIdx.x * blockDim.x + threadIdx.x;
    long long E8 = (long long)E * 8;
    bool act = gid < E8;
    long long e = act ? (gid >> 3) : 0;
    int h = (int)(gid & 7);
    int src = 0, dst = 0;
    if (act) { src = eidx[e]; dst = eidx[(long long)E + e]; }
    float a = 0.f;
    if (act) {
        const float4* qp = (const float4*)&g_q[(size_t)src * 64 + h * 8];
        const float4* kp = (const float4*)&g_k[(size_t)dst * 64 + h * 8];
        float4 q0 = qp[0], q1 = qp[1], k0 = kp[0], k1 = kp[1];
        float sc = q0.x * k0.x + q0.y * k0.y + q0.z * k0.z + q0.w * k0.w
                 + q1.x * k1.x + q1.y * k1.y + q1.z * k1.z + q1.w * k1.w;
        sc = (sc + g_eterm[gid]) * 0.35355339059327373f;
        a = __expf(sc);
        att[gid] = a;
    }
    float b1 = __shfl_down_sync(0xffffffffu, a, 1);
    float b2 = __shfl_down_sync(0xffffffffu, a, 2);
    float b3 = __shfl_down_sync(0xffffffffu, a, 3);
    if (act && (h & 3) == 0)
        red4(&g_ssum[(size_t)src * 8 + h], a, b1, b2, b3);
}

// ---------------- K4: finalize attention + scatter-aggregate (vn gather) ----------------
__global__ void k_aggregate(const int* __restrict__ eidx, float* __restrict__ att, int E) {
    __shared__ float as[8][2][8];
    int tid = threadIdx.x, warp = tid >> 5, lane = tid & 31;
    int side = lane >> 4, hl = lane & 15;
    for (long long e0 = (long long)blockIdx.x * 16 + warp * 2; e0 < E;
         e0 += (long long)gridDim.x * 16) {
        long long e = e0 + side;
        bool ok = e < E;
        int src = 0, dst = 0;
        if (ok) { src = eidx[e]; dst = eidx[(long long)E + e]; }
        if (ok && hl < 8) {
            float ex = att[e * 8 + hl];
            float den = g_ssum[(size_t)src * 8 + hl];
            float a = ex / (den + 1e-12f);
            att[e * 8 + hl] = a;
            as[warp][side][hl] = a;
        }
        __syncwarp();
        if (ok) {
            int c4 = hl * 4;
            float4 vn = *(const float4*)&g_vn[(size_t)dst * 64 + c4];
            float a = as[warp][side][hl >> 1];
            red4(&g_agg[(size_t)src * 64 + c4],
                 a * vn.x, a * vn.y, a * vn.z, a * vn.w);
        }
        __syncwarp();
    }
}

// ---------------- K5: node update + node FFN (f32x2) ----------------
__global__ void k_node_ffn(const float* __restrict__ ns,
                           const float* __restrict__ wno, const float* __restrict__ bno,
                           const float* __restrict__ g2, const float* __restrict__ b2,
                           const float* __restrict__ f1w, const float* __restrict__ f1b,
                           const float* __restrict__ f2w, const float* __restrict__ f2b,
                           float* __restrict__ node_out, int N) {
    extern __shared__ float sm[];
    float* Wno = sm;
    float* W1  = sm + 4096;
    float* W2  = sm + 12288;
    float* Bno = sm + 20480;
    float* B1  = sm + 20544;
    float* B2  = sm + 20672;
    float* G   = sm + 20736;
    float* Bt  = sm + 20800;
    float* xs  = sm + 20864;
    float* hs  = sm + 21376;
    int tid = threadIdx.x;
    for (int i = tid; i < 4096; i += 256) Wno[i] = wno[i];
    for (int i = tid; i < 8192; i += 256) { W1[i] = f1w[i]; W2[i] = f2w[i]; }
    if (tid < 128) B1[tid] = f1b[tid];
    if (tid < 64) { Bno[tid] = bno[tid]; B2[tid] = f2b[tid]; G[tid] = g2[tid]; Bt[tid] = b2[tid]; }
    __syncthreads();
    int warp = tid >> 5, lane = tid & 31;
    int c2 = 2 * lane;
    float* xw = xs + warp * 64;
    float* hw = hs + warp * 128;
    for (long long r = (long long)blockIdx.x * 8 + warp; r < N; r += (long long)gridDim.x * 8) {
        float2 ag = *(const float2*)&g_agg[r * 64 + c2];
        *(float2*)&xw[c2] = ag;
        __syncwarp();
        u64 sacc = pk2(ns[r * 64 + c2] + Bno[c2], ns[r * 64 + c2 + 1] + Bno[c2 + 1]);
        #pragma unroll 8
        for (int i = 0; i < 64; i++) {
            float xi = xw[i];
            fma2(sacc, pk2(xi, xi), *(const u64*)&Wno[i * 64 + c2]);
        }
        float2 sv = upk2(sacc);
        __syncwarp();
        float sum = sv.x + sv.y;
        #pragma unroll
        for (int o = 16; o; o >>= 1) sum += __shfl_xor_sync(0xffffffffu, sum, o);
        float m = sum * 0.015625f;
        float d0 = sv.x - m, d1 = sv.y - m;
        float vv = d0 * d0 + d1 * d1;
        #pragma unroll
        for (int o = 16; o; o >>= 1) vv += __shfl_xor_sync(0xffffffffu, vv, o);
        float rs = rsqrtf(vv * 0.015625f + 1e-5f);
        xw[c2]     = d0 * rs * G[c2] + Bt[c2];
        xw[c2 + 1] = d1 * rs * G[c2 + 1] + Bt[c2 + 1];
        __syncwarp();
        u64 h01 = *(const u64*)&B1[c2];
        u64 h23 = *(const u64*)&B1[64 + c2];
        #pragma unroll 8
        for (int i = 0; i < 64; i++) {
            float xi = xw[i];
            u64 xx = pk2(xi, xi);
            fma2(h01, xx, *(const u64*)&W1[i * 128 + c2]);
            fma2(h23, xx, *(const u64*)&W1[i * 128 + 64 + c2]);
        }
        float2 ha = upk2(h01), hb = upk2(h23);
        hw[c2] = fmaxf(ha.x, 0.f); hw[c2 + 1] = fmaxf(ha.y, 0.f);
        hw[64 + c2] = fmaxf(hb.x, 0.f); hw[64 + c2 + 1] = fmaxf(hb.y, 0.f);
        __syncwarp();
        u64 yacc = *(const u64*)&B2[c2];
        #pragma unroll 8
        for (int i = 0; i < 128; i++) {
            float hi = hw[i];
            fma2(yacc, pk2(hi, hi), *(const u64*)&W2[i * 64 + c2]);
        }
        float2 yv = upk2(yacc);
        float2 o; o.x = sv.x + yv.x; o.y = sv.y + yv.y;
        *(float2*)&node_out[r * 64 + c2] = o;
        __syncwarp();
    }
}

// ---------------- K6: edge update + edge FFN (tf32 mma, cp.async pipeline) ----------------
__global__ __launch_bounds__(512, 1)
void k_edge_ffn_tc(const float* __restrict__ es, const float* __restrict__ att,
                   float* __restrict__ eout,
                   const float* __restrict__ weo, const float* __restrict__ beo,
                   const float* __restrict__ g2, const float* __restrict__ b2,
                   const float* __restrict__ f1w, const float* __restrict__ f1b,
                   const float* __restrict__ f2w, const float* __restrict__ f2b,
                   int E) {
    extern __shared__ float sm[];
    u32*   W1F = (u32*)sm;              // 8192
    u32*   W2F = (u32*)(sm + 8192);     // 8192
    float* B1  = sm + 16384;
    float* B2  = sm + 16512;
    float* G   = sm + 16576;
    float* Bt  = sm + 16640;
    float* WO  = sm + 16704;            // 512
    float* BO  = sm + 17216;            // 64
    float* ES  = sm + 17280;            // 2*8192 (raw es -> in-place x)
    float* AT  = sm + 33664;            // 2*1024
    u32*   XnS = (u32*)(sm + 35712);    // stride 68 (union lo)
    u32*   HS  = (u32*)(sm + 35712);    // stride 132 (union, after sync)
    int tid = threadIdx.x;

    for (int idx = tid; idx < 4096; idx += 512) {
        int L = idx & 31, K = (idx >> 5) & 7, T = idx >> 8;
        int kk = K * 8 + (L & 3), nn = T * 8 + (L >> 2);
        W1F[idx * 2]     = tf32of(f1w[kk * 128 + nn]);
        W1F[idx * 2 + 1] = tf32of(f1w[(kk + 4) * 128 + nn]);
    }
    for (int idx = tid; idx < 4096; idx += 512) {
        int L = idx & 31, K = (idx >> 5) & 15, T = idx >> 9;
        int kk = K * 8 + (L & 3), nn = T * 8 + (L >> 2);
        W2F[idx * 2]     = tf32of(f2w[kk * 64 + nn]);
        W2F[idx * 2 + 1] = tf32of(f2w[(kk + 4) * 64 + nn]);
    }
    if (tid < 512) WO[tid] = weo[tid];
    if (tid < 128) B1[tid] = f1b[tid];
    if (tid < 64) { B2[tid] = f2b[tid]; G[tid] = g2[tid]; Bt[tid] = b2[tid]; BO[tid] = beo[tid]; }
    __syncthreads();

    int warp = tid >> 5, lane = tid & 31;
    int wm = warp & 7, wn = warp >> 3;
    int qr = lane >> 2, qc = lane & 3;
    int r0 = 16 * wm + qr;
    long long ntiles = ((long long)E + 127) >> 7;
    long long stride = gridDim.x;
    u32 es_s0 = (u32)__cvta_generic_to_shared(ES);
    u32 at_s0 = (u32)__cvta_generic_to_shared(AT);

    long long t = blockIdx.x;
    if (t < ntiles) {
        long long base = t << 7;
        #pragma unroll
        for (int j = 0; j < 4; j++) {
            int idx = j * 512 + tid;
            int r = idx >> 4, c4 = (idx & 15) << 2;
            int ok = (base + r) < E ? 16 : 0;
            cp16(es_s0 + (u32)((r * 64 + c4) * 4), &es[(base + r) * 64 + c4], ok);
        }
        if (tid < 256) {
            int ok = (base + (tid >> 1)) < E ? 16 : 0;
            cp16(at_s0 + (u32)(tid * 16), &att[base * 8 + tid * 4], ok);
        }
    }
    CP_COMMIT();

    int pb = 0;
    for (; t < ntiles; t += stride) {
        long long tn = t + stride;
        if (tn < ntiles) {
            long long basen = tn << 7;
            u32 esd = es_s0 + (u32)((pb ^ 1) * 8192 * 4);
            u32 atd = at_s0 + (u32)((pb ^ 1) * 1024 * 4);
            #pragma unroll
            for (int j = 0; j < 4; j++) {
                int idx = j * 512 + tid;
                int r = idx >> 4, c4 = (idx & 15) << 2;
                int ok = (basen + r) < E ? 16 : 0;
                cp16(esd + (u32)((r * 64 + c4) * 4), &es[(basen + r) * 64 + c4], ok);
            }
            if (tid < 256) {
                int ok = (basen + (tid >> 1)) < E ? 16 : 0;
                cp16(atd + (u32)(tid * 16), &att[basen * 8 + tid * 4], ok);
            }
            CP_COMMIT();
            CP_WAIT1();
        } else {
            CP_COMMIT();
            CP_WAIT0();
        }
        __syncthreads();

        long long base = t << 7;
        float* XS = ES + pb * 8192;
        const float* ATc = AT + pb * 1024;

        // phase A (warp-local rows 8*warp..+7): x = es + att@weo + beo (in place), then LN
        #pragma unroll
        for (int j = 0; j < 4; j++) {
            int idx = j * 32 + lane;                 // 0..127
            int r = warp * 8 + (idx >> 4);
            int c4 = (idx & 15) << 2;
            float4 x = *(float4*)&XS[r * 64 + c4];
            const float* a = &ATc[r * 8];
            float4 u = *(const float4*)&BO[c4];
            #pragma unroll
            for (int h = 0; h < 8; h++) {
                float ah = a[h];
                float4 w = *(const float4*)&WO[h * 64 + c4];
                u.x = fmaf(ah, w.x, u.x); u.y = fmaf(ah, w.y, u.y);
                u.z = fmaf(ah, w.z, u.z); u.w = fmaf(ah, w.w, u.w);
            }
            x.x += u.x; x.y += u.y; x.z += u.z; x.w += u.w;
            *(float4*)&XS[r * 64 + c4] = x;
        }
        __syncwarp();
        for (int r8 = 0; r8 < 8; r8++) {
            int r = warp * 8 + r8;
            float x0 = XS[r * 64 + lane], x1 = XS[r * 64 + lane + 32];
            float s = x0 + x1;
            #pragma unroll
            for (int o = 16; o; o >>= 1) s += __shfl_xor_sync(0xffffffffu, s, o);
            float m = s * 0.015625f;
            float d0 = x0 - m, d1 = x1 - m;
            float vv = d0 * d0 + d1 * d1;
            #pragma unroll
            for (int o = 16; o; o >>= 1) vv += __shfl_xor_sync(0xffffffffu, vv, o);
            float rs = rsqrtf(vv * 0.015625f + 1e-5f);
            XnS[r * 68 + lane]      = tf32of(d0 * rs * G[lane] + Bt[lane]);
            XnS[r * 68 + lane + 32] = tf32of(d1 * rs * G[lane + 32] + Bt[lane + 32]);
        }
        __syncthreads();
        // GEMM1 (accumulate in regs from XnS)
        float c1[8][4];
        #pragma unroll
        for (int t8 = 0; t8 < 8; t8++) {
            int cc = 64 * wn + 8 * t8 + 2 * qc;
            c1[t8][0] = B1[cc]; c1[t8][1] = B1[cc + 1];
            c1[t8][2] = B1[cc]; c1[t8][3] = B1[cc + 1];
        }
        #pragma unroll
        for (int k = 0; k < 8; k++) {
            u32 a0 = XnS[r0 * 68 + 8 * k + qc];
            u32 a1 = XnS[(r0 + 8) * 68 + 8 * k + qc];
            u32 a2 = XnS[r0 * 68 + 8 * k + qc + 4];
            u32 a3 = XnS[(r0 + 8) * 68 + 8 * k + qc + 4];
            #pragma unroll
            for (int t8 = 0; t8 < 8; t8++) {
                uint2 b = *(const uint2*)&W1F[(((8 * wn + t8) * 8 + k) * 32 + lane) * 2];
                mma_tf32(c1[t8], a0, a1, a2, a3, b.x, b.y);
            }
        }
        __syncthreads();   // XnS fully consumed; HS may overwrite union region
        #pragma unroll
        for (int t8 = 0; t8 < 8; t8++) {
            int cc = 64 * wn + 8 * t8 + 2 * qc;
            uint2 lo, hi;
            lo.x = tf32of(fmaxf(c1[t8][0], 0.f)); lo.y = tf32of(fmaxf(c1[t8][1], 0.f));
            hi.x = tf32of(fmaxf(c1[t8][2], 0.f)); hi.y = tf32of(fmaxf(c1[t8][3], 0.f));
            *(uint2*)&HS[r0 * 132 + cc] = lo;
            *(uint2*)&HS[(r0 + 8) * 132 + cc] = hi;
        }
        __syncthreads();
        // GEMM2 + residual
        float c2[4][4];
        #pragma unroll
        for (int t4 = 0; t4 < 4; t4++) {
            int cc = 32 * wn + 8 * t4 + 2 * qc;
            c2[t4][0] = B2[cc]; c2[t4][1] = B2[cc + 1];
            c2[t4][2] = B2[cc]; c2[t4][3] = B2[cc + 1];
        }
        #pragma unroll
        for (int k = 0; k < 16; k++) {
            u32 a0 = HS[r0 * 132 + 8 * k + qc];
            u32 a1 = HS[(r0 + 8) * 132 + 8 * k + qc];
            u32 a2 = HS[r0 * 132 + 8 * k + qc + 4];
            u32 a3 = HS[(r0 + 8) * 132 + 8 * k + qc + 4];
            #pragma unroll
            for (int t4 = 0; t4 < 4; t4++) {
                uint2 b = *(const uint2*)&W2F[(((4 * wn + t4) * 16 + k) * 32 + lane) * 2];
                mma_tf32(c2[t4], a0, a1, a2, a3, b.x, b.y);
            }
        }
        #pragma unroll
        for (int t4 = 0; t4 < 4; t4++) {
            int cc = 32 * wn + 8 * t4 + 2 * qc;
            long long ro = base + r0;
            if (ro < E) {
                float2 o;
                o.x = XS[r0 * 64 + cc]     + c2[t4][0];
                o.y = XS[r0 * 64 + cc + 1] + c2[t4][1];
                *(float2*)&eout[ro * 64 + cc] = o;
            }
            if (ro + 8 < E) {
                float2 o;
                o.x = XS[(r0 + 8) * 64 + cc]     + c2[t4][2];
                o.y = XS[(r0 + 8) * 64 + cc + 1] + c2[t4][3];
                *(float2*)&eout[(ro + 8) * 64 + cc] = o;
            }
        }
        __syncthreads();
        pb ^= 1;
    }
}

// ---------------- launcher ----------------
extern "C" void kernel_launch(void* const* d_in, const int* in_sizes, int n_in,
                              void* d_out, int out_size) {
    int N = in_sizes[0] / 64;
    int E = in_sizes[1] / 64;

    const int* eidx;
    int base;
    if (in_sizes[2] == 2 * E) { eidx = (const int*)d_in[2]; base = 3; }
    else                      { eidx = (const int*)d_in[n_in - 1]; base = 2; }

    const float* ns = (const float*)d_in[0];
    const float* es = (const float*)d_in[1];
    const float* wq   = (const float*)d_in[base + 0];
    const float* bq   = (const float*)d_in[base + 1];
    const float* wk   = (const float*)d_in[base + 2];
    const float* bk   = (const float*)d_in[base + 3];
    const float* wv   = (const float*)d_in[base + 4];
    const float* bv   = (const float*)d_in[base + 5];
    const float* we   = (const float*)d_in[base + 6];
    const float* be   = (const float*)d_in[base + 7];
    const float* wno  = (const float*)d_in[base + 8];
    const float* bno  = (const float*)d_in[base + 9];
    const float* weo  = (const float*)d_in[base + 10];
    const float* beo  = (const float*)d_in[base + 11];
    const float* n1g  = (const float*)d_in[base + 12];
    const float* n1b  = (const float*)d_in[base + 13];
    const float* e1g  = (const float*)d_in[base + 14];
    const float* e1b  = (const float*)d_in[base + 15];
    const float* n2g  = (const float*)d_in[base + 16];
    const float* n2b  = (const float*)d_in[base + 17];
    const float* e2g  = (const float*)d_in[base + 18];
    const float* e2b  = (const float*)d_in[base + 19];
    const float* nf1w = (const float*)d_in[base + 20];
    const float* nf1b = (const float*)d_in[base + 21];
    const float* nf2w = (const float*)d_in[base + 22];
    const float* nf2b = (const float*)d_in[base + 23];
    const float* ef1w = (const float*)d_in[base + 24];
    const float* ef1b = (const float*)d_in[base + 25];
    const float* ef2w = (const float*)d_in[base + 26];
    const float* ef2b = (const float*)d_in[base + 27];

    float* out      = (float*)d_out;
    float* node_out = out;
    float* edge_out = out + (size_t)N * 64;
    float* att      = edge_out + (size_t)E * 64;

    (void)out_size;

    cudaFuncSetAttribute(k_node_qkv, cudaFuncAttributeMaxDynamicSharedMemorySize, 13120 * 4);
    cudaFuncSetAttribute(k_edge_proj_tc, cudaFuncAttributeMaxDynamicSharedMemorySize, 38080 * 4);
    cudaFuncSetAttribute(k_node_ffn, cudaFuncAttributeMaxDynamicSharedMemorySize, 22400 * 4);
    cudaFuncSetAttribute(k_edge_ffn_tc, cudaFuncAttributeMaxDynamicSharedMemorySize, 52608 * 4);

    k_init<<<(N * 64 + 255) / 256, 256>>>(N);
    k_node_qkv<<<(N + 7) / 8, 256, 13120 * 4>>>(ns, wq, bq, wk, bk, wv, bv, n1g, n1b, N);
    k_edge_proj_tc<<<148, 512, 38080 * 4>>>(es, we, be, e1g, e1b, E);
    {
        long long tot = (long long)E * 8;
        k_scores<<<(unsigned)((tot + 255) / 256), 256>>>(eidx, att, E);
    }
    k_aggregate<<<(E + 15) / 16, 256>>>(eidx, att, E);
    k_node_ffn<<<(N + 7) / 8, 256, 22400 * 4>>>(ns, wno, bno, n2g, n2b,
                                                nf1w, nf1b, nf2w, nf2b, node_out, N);
    k_edge_ffn_tc<<<148, 512, 52608 * 4>>>(es, att, edge_out, weo, beo, e2g, e2b,
                                           ef1w, ef1b, ef2w, ef2b, E);
}

// round 13
// speedup vs baseline: 2.1399x; 1.0319x over previous
#include <cuda_runtime.h>
#include <math.h>

#define NMAX 100000
#define EMAX 1600000

typedef unsigned int u32;
typedef unsigned long long u64;

// ---------------- PTX helpers ----------------
__device__ __forceinline__ u64 pk2(float x, float y) {
    u64 r; asm("mov.b64 %0, {%1,%2};" : "=l"(r) : "f"(x), "f"(y)); return r;
}
__device__ __forceinline__ float2 upk2(u64 v) {
    float2 r; asm("mov.b64 {%0,%1}, %2;" : "=f"(r.x), "=f"(r.y) : "l"(v)); return r;
}
__device__ __forceinline__ void fma2(u64& d, u64 a, u64 b) {
    asm("fma.rn.f32x2 %0, %1, %2, %0;" : "+l"(d) : "l"(a), "l"(b));
}
__device__ __forceinline__ u32 tf32of(float x) {
    u32 r; asm("cvt.rna.tf32.f32 %0, %1;" : "=r"(r) : "f"(x)); return r;
}
__device__ __forceinline__ float tf32f(float x) {
    u32 r; asm("cvt.rna.tf32.f32 %0, %1;" : "=r"(r) : "f"(x)); return __uint_as_float(r);
}
__device__ __forceinline__ void mma_tf32(float* c, u32 a0, u32 a1, u32 a2, u32 a3,
                                         u32 b0, u32 b1) {
    asm volatile("mma.sync.aligned.m16n8k8.row.col.f32.tf32.tf32.f32 "
                 "{%0,%1,%2,%3},{%4,%5,%6,%7},{%8,%9},{%0,%1,%2,%3};"
                 : "+f"(c[0]), "+f"(c[1]), "+f"(c[2]), "+f"(c[3])
                 : "r"(a0), "r"(a1), "r"(a2), "r"(a3), "r"(b0), "r"(b1));
}
__device__ __forceinline__ void red4(float* p, float a, float b, float c, float d) {
    asm volatile("red.global.v4.f32.add [%0], {%1,%2,%3,%4};"
                 :: "l"(p), "f"(a), "f"(b), "f"(c), "f"(d) : "memory");
}
__device__ __forceinline__ void cp16(u32 smem, const void* gmem, int bytes) {
    asm volatile("cp.async.cg.shared.global [%0], [%1], 16, %2;"
                 :: "r"(smem), "l"(gmem), "r"(bytes));
}
#define CP_COMMIT() asm volatile("cp.async.commit_group;" ::: "memory")
#define CP_WAIT1()  asm volatile("cp.async.wait_group 1;" ::: "memory")
#define CP_WAIT0()  asm volatile("cp.async.wait_group 0;" ::: "memory")

// ---------------- scratch ----------------
__device__ __align__(16) float g_q [(size_t)NMAX * 64];
__device__ __align__(16) float g_k [(size_t)NMAX * 64];
__device__ __align__(16) float g_vn[(size_t)NMAX * 64];   // v ⊙ ni
__device__ __align__(16) float g_agg[(size_t)NMAX * 64];  // unnormalized Σ exp·vn
__device__ __align__(16) float g_ssum[(size_t)NMAX * 8];
__device__ __align__(16) float g_eterm[(size_t)EMAX * 8];

// ---------------- init ----------------
__global__ void k_init(int N) {
    long long i = (long long)blockIdx.x * blockDim.x + threadIdx.x;
    if (i < (long long)N * 64) g_agg[i] = 0.f;
    if (i < (long long)N * 8) g_ssum[i] = 0.f;
}

// ---------------- K1: node LN + Q,K,V projections (f32x2), vn = v*ni ----------------
__global__ void k_node_qkv(const float* __restrict__ ns,
                           const float* __restrict__ wq, const float* __restrict__ bq,
                           const float* __restrict__ wk, const float* __restrict__ bk,
                           const float* __restrict__ wv, const float* __restrict__ bv,
                           const float* __restrict__ gg, const float* __restrict__ bb,
                           int N) {
    extern __shared__ float sm[];
    float* W  = sm;            // 3*4096
    float* B  = sm + 12288;
    float* G  = sm + 12480;
    float* Bt = sm + 12544;
    float* xs = sm + 12608;    // 8*64
    int tid = threadIdx.x;
    for (int i = tid; i < 4096; i += 256) { W[i] = wq[i]; W[4096 + i] = wk[i]; W[8192 + i] = wv[i]; }
    if (tid < 64) { B[tid] = bq[tid]; B[64 + tid] = bk[tid]; B[128 + tid] = bv[tid]; G[tid] = gg[tid]; Bt[tid] = bb[tid]; }
    __syncthreads();
    int warp = tid >> 5, lane = tid & 31;
    float* xw = xs + warp * 64;
    for (long long r = (long long)blockIdx.x * 8 + warp; r < N; r += (long long)gridDim.x * 8) {
        const float* xr = ns + r * 64;
        float x0 = xr[lane], x1 = xr[lane + 32];
        float s = x0 + x1;
        #pragma unroll
        for (int o = 16; o; o >>= 1) s += __shfl_xor_sync(0xffffffffu, s, o);
        float m = s * 0.015625f;
        float d0 = x0 - m, d1 = x1 - m;
        float vv = d0 * d0 + d1 * d1;
        #pragma unroll
        for (int o = 16; o; o >>= 1) vv += __shfl_xor_sync(0xffffffffu, vv, o);
        float rs = rsqrtf(vv * 0.015625f + 1e-5f);
        float y0 = d0 * rs * G[lane] + Bt[lane];
        float y1 = d1 * rs * G[lane + 32] + Bt[lane + 32];
        xw[lane] = y0; xw[lane + 32] = y1;
        __syncwarp();
        int c2 = 2 * lane;
        u64 aq = *(const u64*)&B[c2];
        u64 ak = *(const u64*)&B[64 + c2];
        u64 av = *(const u64*)&B[128 + c2];
        #pragma unroll 8
        for (int i = 0; i < 64; i++) {
            float xi = xw[i];
            u64 xx = pk2(xi, xi);
            fma2(aq, xx, *(const u64*)&W[i * 64 + c2]);
            fma2(ak, xx, *(const u64*)&W[4096 + i * 64 + c2]);
            fma2(av, xx, *(const u64*)&W[8192 + i * 64 + c2]);
        }
        *(float2*)&g_q[r * 64 + c2] = upk2(aq);
        *(float2*)&g_k[r * 64 + c2] = upk2(ak);
        float2 vproj = upk2(av);
        float2 vn; vn.x = vproj.x * xw[c2]; vn.y = vproj.y * xw[c2 + 1];
        *(float2*)&g_vn[r * 64 + c2] = vn;
        __syncwarp();
    }
}

// ---------------- K2: edge LN + (ei@we+be)·ei per head, 2-pass split-tf32, cp.async -------
__global__ __launch_bounds__(512, 1)
void k_edge_proj_tc(const float* __restrict__ es,
                    const float* __restrict__ we, const float* __restrict__ be,
                    const float* __restrict__ gg, const float* __restrict__ bb,
                    int E) {
    extern __shared__ float sm[];
    u32*   WH = (u32*)sm;            // 4096
    float* B  = sm + 4096;
    float* G  = sm + 4160;
    float* Bt = sm + 4224;
    float* ES = sm + 4288;           // 2*8192
    float* XH = sm + 20672;          // 128*68
    float* XL = sm + 29376;          // 128*68
    int tid = threadIdx.x;

    for (int idx = tid; idx < 2048; idx += 512) {
        int L = idx & 31, K = (idx >> 5) & 7, T = idx >> 8;
        int kk = K * 8 + (L & 3), nn = T * 8 + (L >> 2);
        WH[idx * 2]     = tf32of(we[kk * 64 + nn]);
        WH[idx * 2 + 1] = tf32of(we[(kk + 4) * 64 + nn]);
    }
    if (tid < 64) { B[tid] = be[tid]; G[tid] = gg[tid]; Bt[tid] = bb[tid]; }
    __syncthreads();

    int warp = tid >> 5, lane = tid & 31;
    int wm = warp & 7, wn = warp >> 3;
    int qr = lane >> 2, qc = lane & 3;
    int r0 = 16 * wm + qr;
    long long ntiles = ((long long)E + 127) >> 7;
    long long stride = gridDim.x;
    u32 es_smem0 = (u32)__cvta_generic_to_shared(ES);

    long long t = blockIdx.x;
    if (t < ntiles) {
        long long base = t << 7;
        #pragma unroll
        for (int j = 0; j < 4; j++) {
            int idx = j * 512 + tid;
            int r = idx >> 4, c4 = (idx & 15) << 2;
            int ok = (base + r) < E ? 16 : 0;
            cp16(es_smem0 + (u32)((r * 64 + c4) * 4), &es[(base + r) * 64 + c4], ok);
        }
    }
    CP_COMMIT();

    int pb = 0;
    for (; t < ntiles; t += stride) {
        long long tn = t + stride;
        if (tn < ntiles) {
            long long basen = tn << 7;
            u32 dst = es_smem0 + (u32)((pb ^ 1) * 8192 * 4);
            #pragma unroll
            for (int j = 0; j < 4; j++) {
                int idx = j * 512 + tid;
                int r = idx >> 4, c4 = (idx & 15) << 2;
                int ok = (basen + r) < E ? 16 : 0;
                cp16(dst + (u32)((r * 64 + c4) * 4), &es[(basen + r) * 64 + c4], ok);
            }
            CP_COMMIT();
            CP_WAIT1();
        } else {
            CP_COMMIT();
            CP_WAIT0();
        }
        __syncthreads();

        long long base = t << 7;
        const float* EScur = ES + pb * 8192;
        for (int r8 = 0; r8 < 8; r8++) {
            int r = warp * 8 + r8;
            float x0 = EScur[r * 64 + lane], x1 = EScur[r * 64 + lane + 32];
            float s = x0 + x1;
            #pragma unroll
            for (int o = 16; o; o >>= 1) s += __shfl_xor_sync(0xffffffffu, s, o);
            float m = s * 0.015625f;
            float d0 = x0 - m, d1 = x1 - m;
            float vv = d0 * d0 + d1 * d1;
            #pragma unroll
            for (int o = 16; o; o >>= 1) vv += __shfl_xor_sync(0xffffffffu, vv, o);
            float rs = rsqrtf(vv * 0.015625f + 1e-5f);
            float y0 = d0 * rs * G[lane] + Bt[lane];
            float y1 = d1 * rs * G[lane + 32] + Bt[lane + 32];
            float h0 = tf32f(y0), h1 = tf32f(y1);
            XH[r * 68 + lane] = h0;      XH[r * 68 + lane + 32] = h1;
            XL[r * 68 + lane] = tf32f(y0 - h0); XL[r * 68 + lane + 32] = tf32f(y1 - h1);
        }
        __syncthreads();
        float c[4][4];
        #pragma unroll
        for (int t4 = 0; t4 < 4; t4++) {
            int cc = 32 * wn + 8 * t4 + 2 * qc;
            c[t4][0] = B[cc]; c[t4][1] = B[cc + 1];
            c[t4][2] = B[cc]; c[t4][3] = B[cc + 1];
        }
        #pragma unroll
        for (int k = 0; k < 8; k++) {
            u32 ah0 = __float_as_uint(XH[r0 * 68 + 8 * k + qc]);
            u32 ah1 = __float_as_uint(XH[(r0 + 8) * 68 + 8 * k + qc]);
            u32 ah2 = __float_as_uint(XH[r0 * 68 + 8 * k + qc + 4]);
            u32 ah3 = __float_as_uint(XH[(r0 + 8) * 68 + 8 * k + qc + 4]);
            u32 al0 = __float_as_uint(XL[r0 * 68 + 8 * k + qc]);
            u32 al1 = __float_as_uint(XL[(r0 + 8) * 68 + 8 * k + qc]);
            u32 al2 = __float_as_uint(XL[r0 * 68 + 8 * k + qc + 4]);
            u32 al3 = __float_as_uint(XL[(r0 + 8) * 68 + 8 * k + qc + 4]);
            #pragma unroll
            for (int t4 = 0; t4 < 4; t4++) {
                int gidx = (((4 * wn + t4) * 8 + k) * 32 + lane) * 2;
                uint2 bh = *(const uint2*)&WH[gidx];
                mma_tf32(c[t4], ah0, ah1, ah2, ah3, bh.x, bh.y);
                mma_tf32(c[t4], al0, al1, al2, al3, bh.x, bh.y);
            }
        }
        #pragma unroll
        for (int t4 = 0; t4 < 4; t4++) {
            int cc = 32 * wn + 8 * t4 + 2 * qc;
            float e00 = XH[r0 * 68 + cc]       + XL[r0 * 68 + cc];
            float e01 = XH[r0 * 68 + cc + 1]   + XL[r0 * 68 + cc + 1];
            float e10 = XH[(r0 + 8) * 68 + cc]     + XL[(r0 + 8) * 68 + cc];
            float e11 = XH[(r0 + 8) * 68 + cc + 1] + XL[(r0 + 8) * 68 + cc + 1];
            float p0 = c[t4][0] * e00 + c[t4][1] * e01;
            float p1 = c[t4][2] * e10 + c[t4][3] * e11;
            p0 += __shfl_xor_sync(0xffffffffu, p0, 1);
            p0 += __shfl_xor_sync(0xffffffffu, p0, 2);
            p1 += __shfl_xor_sync(0xffffffffu, p1, 1);
            p1 += __shfl_xor_sync(0xffffffffu, p1, 2);
            if (qc == 0) {
                long long row = base + 16 * wm + qr;
                if (row < E)     g_eterm[row * 8 + 4 * wn + t4] = p0;
                if (row + 8 < E) g_eterm[(row + 8) * 8 + 4 * wn + t4] = p1;
            }
        }
        __syncthreads();
        pb ^= 1;
    }
}

// ---------------- K3: att=exp(score), segment-sum, fused unnormalized aggregate -----------
__global__ void k_scores(const int* __restrict__ eidx, float* __restrict__ att, int E) {
    long long gid = (long long)blockIdx.x * blockDim.x + threadIdx.x;
    long long E8 = (long long)E * 8;
    bool act = gid < E8;
    long long e = act ? (gid >> 3) : 0;
    int h = (int)(gid & 7);
    int lane = threadIdx.x & 31;
    int s0 = 0, d0i = 0;
    if (act && h == 0) { s0 = eidx[e]; d0i = eidx[(long long)E + e]; }
    int src = __shfl_sync(0xffffffffu, s0, lane & ~7);
    int dst = __shfl_sync(0xffffffffu, d0i, lane & ~7);
    float a = 0.f;
    if (act) {
        const float4* qp = (const float4*)&g_q[(size_t)src * 64 + h * 8];
        const float4* kp = (const float4*)&g_k[(size_t)dst * 64 + h * 8];
        float4 q0 = qp[0], q1 = qp[1], k0 = kp[0], k1 = kp[1];
        float sc = q0.x * k0.x + q0.y * k0.y + q0.z * k0.z + q0.w * k0.w
                 + q1.x * k1.x + q1.y * k1.y + q1.z * k1.z + q1.w * k1.w;
        sc = (sc + g_eterm[gid]) * 0.35355339059327373f;
        a = __expf(sc);
        att[gid] = a;
        // fused unnormalized aggregate: Σ exp · vn
        const float4* vp = (const float4*)&g_vn[(size_t)dst * 64 + h * 8];
        float4 v0 = vp[0], v1 = vp[1];
        float* p = &g_agg[(size_t)src * 64 + h * 8];
        red4(p,     a * v0.x, a * v0.y, a * v0.z, a * v0.w);
        red4(p + 4, a * v1.x, a * v1.y, a * v1.z, a * v1.w);
    }
    float b1 = __shfl_down_sync(0xffffffffu, a, 1);
    float b2 = __shfl_down_sync(0xffffffffu, a, 2);
    float b3 = __shfl_down_sync(0xffffffffu, a, 3);
    if (act && (h & 3) == 0)
        red4(&g_ssum[(size_t)src * 8 + h], a, b1, b2, b3);
}

// ---------------- K4: normalize attention in place (one thread per edge) ----------------
__global__ void k_norm(const int* __restrict__ eidx, float* __restrict__ att, int E) {
    long long e = (long long)blockIdx.x * blockDim.x + threadIdx.x;
    if (e >= E) return;
    int src = eidx[e];
    float4 a0 = *(float4*)&att[e * 8];
    float4 a1 = *(float4*)&att[e * 8 + 4];
    float4 d0 = *(const float4*)&g_ssum[(size_t)src * 8];
    float4 d1 = *(const float4*)&g_ssum[(size_t)src * 8 + 4];
    a0.x /= (d0.x + 1e-12f); a0.y /= (d0.y + 1e-12f);
    a0.z /= (d0.z + 1e-12f); a0.w /= (d0.w + 1e-12f);
    a1.x /= (d1.x + 1e-12f); a1.y /= (d1.y + 1e-12f);
    a1.z /= (d1.z + 1e-12f); a1.w /= (d1.w + 1e-12f);
    *(float4*)&att[e * 8] = a0;
    *(float4*)&att[e * 8 + 4] = a1;
}

// ---------------- K5: node update + node FFN (f32x2); agg normalized at load -------------
__global__ void k_node_ffn(const float* __restrict__ ns,
                           const float* __restrict__ wno, const float* __restrict__ bno,
                           const float* __restrict__ g2, const float* __restrict__ b2,
                           const float* __restrict__ f1w, const float* __restrict__ f1b,
                           const float* __restrict__ f2w, const float* __restrict__ f2b,
                           float* __restrict__ node_out, int N) {
    extern __shared__ float sm[];
    float* Wno = sm;
    float* W1  = sm + 4096;
    float* W2  = sm + 12288;
    float* Bno = sm + 20480;
    float* B1  = sm + 20544;
    float* B2  = sm + 20672;
    float* G   = sm + 20736;
    float* Bt  = sm + 20800;
    float* xs  = sm + 20864;
    float* hs  = sm + 21376;
    int tid = threadIdx.x;
    for (int i = tid; i < 4096; i += 256) Wno[i] = wno[i];
    for (int i = tid; i < 8192; i += 256) { W1[i] = f1w[i]; W2[i] = f2w[i]; }
    if (tid < 128) B1[tid] = f1b[tid];
    if (tid < 64) { Bno[tid] = bno[tid]; B2[tid] = f2b[tid]; G[tid] = g2[tid]; Bt[tid] = b2[tid]; }
    __syncthreads();
    int warp = tid >> 5, lane = tid & 31;
    int c2 = 2 * lane;
    float* xw = xs + warp * 64;
    float* hw = hs + warp * 128;
    for (long long r = (long long)blockIdx.x * 8 + warp; r < N; r += (long long)gridDim.x * 8) {
        float den = g_ssum[r * 8 + (lane >> 2)] + 1e-12f;
        float2 ag = *(const float2*)&g_agg[r * 64 + c2];
        ag.x /= den; ag.y /= den;
        *(float2*)&xw[c2] = ag;
        __syncwarp();
        u64 sacc = pk2(ns[r * 64 + c2] + Bno[c2], ns[r * 64 + c2 + 1] + Bno[c2 + 1]);
        #pragma unroll 8
        for (int i = 0; i < 64; i++) {
            float xi = xw[i];
            fma2(sacc, pk2(xi, xi), *(const u64*)&Wno[i * 64 + c2]);
        }
        float2 sv = upk2(sacc);
        __syncwarp();
        float sum = sv.x + sv.y;
        #pragma unroll
        for (int o = 16; o; o >>= 1) sum += __shfl_xor_sync(0xffffffffu, sum, o);
        float m = sum * 0.015625f;
        float d0 = sv.x - m, d1 = sv.y - m;
        float vv = d0 * d0 + d1 * d1;
        #pragma unroll
        for (int o = 16; o; o >>= 1) vv += __shfl_xor_sync(0xffffffffu, vv, o);
        float rs = rsqrtf(vv * 0.015625f + 1e-5f);
        xw[c2]     = d0 * rs * G[c2] + Bt[c2];
        xw[c2 + 1] = d1 * rs * G[c2 + 1] + Bt[c2 + 1];
        __syncwarp();
        u64 h01 = *(const u64*)&B1[c2];
        u64 h23 = *(const u64*)&B1[64 + c2];
        #pragma unroll 8
        for (int i = 0; i < 64; i++) {
            float xi = xw[i];
            u64 xx = pk2(xi, xi);
            fma2(h01, xx, *(const u64*)&W1[i * 128 + c2]);
            fma2(h23, xx, *(const u64*)&W1[i * 128 + 64 + c2]);
        }
        float2 ha = upk2(h01), hb = upk2(h23);
        hw[c2] = fmaxf(ha.x, 0.f); hw[c2 + 1] = fmaxf(ha.y, 0.f);
        hw[64 + c2] = fmaxf(hb.x, 0.f); hw[64 + c2 + 1] = fmaxf(hb.y, 0.f);
        __syncwarp();
        u64 yacc = *(const u64*)&B2[c2];
        #pragma unroll 8
        for (int i = 0; i < 128; i++) {
            float hi = hw[i];
            fma2(yacc, pk2(hi, hi), *(const u64*)&W2[i * 64 + c2]);
        }
        float2 yv = upk2(yacc);
        float2 o; o.x = sv.x + yv.x; o.y = sv.y + yv.y;
        *(float2*)&node_out[r * 64 + c2] = o;
        __syncwarp();
    }
}

// ---------------- K6: edge update + edge FFN (tf32 mma, cp.async pipeline) ----------------
__global__ __launch_bounds__(512, 1)
void k_edge_ffn_tc(const float* __restrict__ es, const float* __restrict__ att,
                   float* __restrict__ eout,
                   const float* __restrict__ weo, const float* __restrict__ beo,
                   const float* __restrict__ g2, const float* __restrict__ b2,
                   const float* __restrict__ f1w, const float* __restrict__ f1b,
                   const float* __restrict__ f2w, const float* __restrict__ f2b,
                   int E) {
    extern __shared__ float sm[];
    u32*   W1F = (u32*)sm;              // 8192
    u32*   W2F = (u32*)(sm + 8192);     // 8192
    float* B1  = sm + 16384;
    float* B2  = sm + 16512;
    float* G   = sm + 16576;
    float* Bt  = sm + 16640;
    float* WO  = sm + 16704;            // 512
    float* BO  = sm + 17216;            // 64
    float* ES  = sm + 17280;            // 2*8192 (raw es -> in-place x)
    float* AT  = sm + 33664;            // 2*1024
    u32*   XnS = (u32*)(sm + 35712);    // stride 68 (union lo)
    u32*   HS  = (u32*)(sm + 35712);    // stride 132 (union, after sync)
    int tid = threadIdx.x;

    for (int idx = tid; idx < 4096; idx += 512) {
        int L = idx & 31, K = (idx >> 5) & 7, T = idx >> 8;
        int kk = K * 8 + (L & 3), nn = T * 8 + (L >> 2);
        W1F[idx * 2]     = tf32of(f1w[kk * 128 + nn]);
        W1F[idx * 2 + 1] = tf32of(f1w[(kk + 4) * 128 + nn]);
    }
    for (int idx = tid; idx < 4096; idx += 512) {
        int L = idx & 31, K = (idx >> 5) & 15, T = idx >> 9;
        int kk = K * 8 + (L & 3), nn = T * 8 + (L >> 2);
        W2F[idx * 2]     = tf32of(f2w[kk * 64 + nn]);
        W2F[idx * 2 + 1] = tf32of(f2w[(kk + 4) * 64 + nn]);
    }
    if (tid < 512) WO[tid] = weo[tid];
    if (tid < 128) B1[tid] = f1b[tid];
    if (tid < 64) { B2[tid] = f2b[tid]; G[tid] = g2[tid]; Bt[tid] = b2[tid]; BO[tid] = beo[tid]; }
    __syncthreads();

    int warp = tid >> 5, lane = tid & 31;
    int wm = warp & 7, wn = warp >> 3;
    int qr = lane >> 2, qc = lane & 3;
    int r0 = 16 * wm + qr;
    long long ntiles = ((long long)E + 127) >> 7;
    long long stride = gridDim.x;
    u32 es_s0 = (u32)__cvta_generic_to_shared(ES);
    u32 at_s0 = (u32)__cvta_generic_to_shared(AT);

    long long t = blockIdx.x;
    if (t < ntiles) {
        long long base = t << 7;
        #pragma unroll
        for (int j = 0; j < 4; j++) {
            int idx = j * 512 + tid;
            int r = idx >> 4, c4 = (idx & 15) << 2;
            int ok = (base + r) < E ? 16 : 0;
            cp16(es_s0 + (u32)((r * 64 + c4) * 4), &es[(base + r) * 64 + c4], ok);
        }
        if (tid < 256) {
            int ok = (base + (tid >> 1)) < E ? 16 : 0;
            cp16(at_s0 + (u32)(tid * 16), &att[base * 8 + tid * 4], ok);
        }
    }
    CP_COMMIT();

    int pb = 0;
    for (; t < ntiles; t += stride) {
        long long tn = t + stride;
        if (tn < ntiles) {
            long long basen = tn << 7;
            u32 esd = es_s0 + (u32)((pb ^ 1) * 8192 * 4);
            u32 atd = at_s0 + (u32)((pb ^ 1) * 1024 * 4);
            #pragma unroll
            for (int j = 0; j < 4; j++) {
                int idx = j * 512 + tid;
                int r = idx >> 4, c4 = (idx & 15) << 2;
                int ok = (basen + r) < E ? 16 : 0;
                cp16(esd + (u32)((r * 64 + c4) * 4), &es[(basen + r) * 64 + c4], ok);
            }
            if (tid < 256) {
                int ok = (basen + (tid >> 1)) < E ? 16 : 0;
                cp16(atd + (u32)(tid * 16), &att[basen * 8 + tid * 4], ok);
            }
            CP_COMMIT();
            CP_WAIT1();
        } else {
            CP_COMMIT();
            CP_WAIT0();
        }
        __syncthreads();

        long long base = t << 7;
        float* XS = ES + pb * 8192;
        const float* ATc = AT + pb * 1024;

        // phase A (warp-local rows 8*warp..+7): x = es + att@weo + beo (in place), then LN
        #pragma unroll
        for (int j = 0; j < 4; j++) {
            int idx = j * 32 + lane;                 // 0..127
            int r = warp * 8 + (idx >> 4);
            int c4 = (idx & 15) << 2;
            float4 x = *(float4*)&XS[r * 64 + c4];
            const float* a = &ATc[r * 8];
            float4 u = *(const float4*)&BO[c4];
            #pragma unroll
            for (int h = 0; h < 8; h++) {
                float ah = a[h];
                float4 w = *(const float4*)&WO[h * 64 + c4];
                u.x = fmaf(ah, w.x, u.x); u.y = fmaf(ah, w.y, u.y);
                u.z = fmaf(ah, w.z, u.z); u.w = fmaf(ah, w.w, u.w);
            }
            x.x += u.x; x.y += u.y; x.z += u.z; x.w += u.w;
            *(float4*)&XS[r * 64 + c4] = x;
        }
        __syncwarp();
        for (int r8 = 0; r8 < 8; r8++) {
            int r = warp * 8 + r8;
            float x0 = XS[r * 64 + lane], x1 = XS[r * 64 + lane + 32];
            float s = x0 + x1;
            #pragma unroll
            for (int o = 16; o; o >>= 1) s += __shfl_xor_sync(0xffffffffu, s, o);
            float m = s * 0.015625f;
            float d0 = x0 - m, d1 = x1 - m;
            float vv = d0 * d0 + d1 * d1;
            #pragma unroll
            for (int o = 16; o; o >>= 1) vv += __shfl_xor_sync(0xffffffffu, vv, o);
            float rs = rsqrtf(vv * 0.015625f + 1e-5f);
            XnS[r * 68 + lane]      = tf32of(d0 * rs * G[lane] + Bt[lane]);
            XnS[r * 68 + lane + 32] = tf32of(d1 * rs * G[lane + 32] + Bt[lane + 32]);
        }
        __syncthreads();
        // GEMM1 (accumulate in regs from XnS)
        float c1[8][4];
        #pragma unroll
        for (int t8 = 0; t8 < 8; t8++) {
            int cc = 64 * wn + 8 * t8 + 2 * qc;
            c1[t8][0] = B1[cc]; c1[t8][1] = B1[cc + 1];
            c1[t8][2] = B1[cc]; c1[t8][3] = B1[cc + 1];
        }
        #pragma unroll
        for (int k = 0; k < 8; k++) {
            u32 a0 = XnS[r0 * 68 + 8 * k + qc];
            u32 a1 = XnS[(r0 + 8) * 68 + 8 * k + qc];
            u32 a2 = XnS[r0 * 68 + 8 * k + qc + 4];
            u32 a3 = XnS[(r0 + 8) * 68 + 8 * k + qc + 4];
            #pragma unroll
            for (int t8 = 0; t8 < 8; t8++) {
                uint2 b = *(const uint2*)&W1F[(((8 * wn + t8) * 8 + k) * 32 + lane) * 2];
                mma_tf32(c1[t8], a0, a1, a2, a3, b.x, b.y);
            }
        }
        __syncthreads();   // XnS fully consumed; HS may overwrite union region
        #pragma unroll
        for (int t8 = 0; t8 < 8; t8++) {
            int cc = 64 * wn + 8 * t8 + 2 * qc;
            uint2 lo, hi;
            lo.x = tf32of(fmaxf(c1[t8][0], 0.f)); lo.y = tf32of(fmaxf(c1[t8][1], 0.f));
            hi.x = tf32of(fmaxf(c1[t8][2], 0.f)); hi.y = tf32of(fmaxf(c1[t8][3], 0.f));
            *(uint2*)&HS[r0 * 132 + cc] = lo;
            *(uint2*)&HS[(r0 + 8) * 132 + cc] = hi;
        }
        __syncthreads();
        // GEMM2 + residual
        float c2[4][4];
        #pragma unroll
        for (int t4 = 0; t4 < 4; t4++) {
            int cc = 32 * wn + 8 * t4 + 2 * qc;
            c2[t4][0] = B2[cc]; c2[t4][1] = B2[cc + 1];
            c2[t4][2] = B2[cc]; c2[t4][3] = B2[cc + 1];
        }
        #pragma unroll
        for (int k = 0; k < 16; k++) {
            u32 a0 = HS[r0 * 132 + 8 * k + qc];
            u32 a1 = HS[(r0 + 8) * 132 + 8 * k + qc];
            u32 a2 = HS[r0 * 132 + 8 * k + qc + 4];
            u32 a3 = HS[(r0 + 8) * 132 + 8 * k + qc + 4];
            #pragma unroll
            for (int t4 = 0; t4 < 4; t4++) {
                uint2 b = *(const uint2*)&W2F[(((4 * wn + t4) * 16 + k) * 32 + lane) * 2];
                mma_tf32(c2[t4], a0, a1, a2, a3, b.x, b.y);
            }
        }
        #pragma unroll
        for (int t4 = 0; t4 < 4; t4++) {
            int cc = 32 * wn + 8 * t4 + 2 * qc;
            long long ro = base + r0;
            if (ro < E) {
                float2 o;
                o.x = XS[r0 * 64 + cc]     + c2[t4][0];
                o.y = XS[r0 * 64 + cc + 1] + c2[t4][1];
                *(float2*)&eout[ro * 64 + cc] = o;
            }
            if (ro + 8 < E) {
                float2 o;
                o.x = XS[(r0 + 8) * 64 + cc]     + c2[t4][2];
                o.y = XS[(r0 + 8) * 64 + cc + 1] + c2[t4][3];
                *(float2*)&eout[(ro + 8) * 64 + cc] = o;
            }
        }
        __syncthreads();
        pb ^= 1;
    }
}

// ---------------- launcher ----------------
extern "C" void kernel_launch(void* const* d_in, const int* in_sizes, int n_in,
                              void* d_out, int out_size) {
    int N = in_sizes[0] / 64;
    int E = in_sizes[1] / 64;

    const int* eidx;
    int base;
    if (in_sizes[2] == 2 * E) { eidx = (const int*)d_in[2]; base = 3; }
    else                      { eidx = (const int*)d_in[n_in - 1]; base = 2; }

    const float* ns = (const float*)d_in[0];
    const float* es = (const float*)d_in[1];
    const float* wq   = (const float*)d_in[base + 0];
    const float* bq   = (const float*)d_in[base + 1];
    const float* wk   = (const float*)d_in[base + 2];
    const float* bk   = (const float*)d_in[base + 3];
    const float* wv   = (const float*)d_in[base + 4];
    const float* bv   = (const float*)d_in[base + 5];
    const float* we   = (const float*)d_in[base + 6];
    const float* be   = (const float*)d_in[base + 7];
    const float* wno  = (const float*)d_in[base + 8];
    const float* bno  = (const float*)d_in[base + 9];
    const float* weo  = (const float*)d_in[base + 10];
    const float* beo  = (const float*)d_in[base + 11];
    const float* n1g  = (const float*)d_in[base + 12];
    const float* n1b  = (const float*)d_in[base + 13];
    const float* e1g  = (const float*)d_in[base + 14];
    const float* e1b  = (const float*)d_in[base + 15];
    const float* n2g  = (const float*)d_in[base + 16];
    const float* n2b  = (const float*)d_in[base + 17];
    const float* e2g  = (const float*)d_in[base + 18];
    const float* e2b  = (const float*)d_in[base + 19];
    const float* nf1w = (const float*)d_in[base + 20];
    const float* nf1b = (const float*)d_in[base + 21];
    const float* nf2w = (const float*)d_in[base + 22];
    const float* nf2b = (const float*)d_in[base + 23];
    const float* ef1w = (const float*)d_in[base + 24];
    const float* ef1b = (const float*)d_in[base + 25];
    const float* ef2w = (const float*)d_in[base + 26];
    const float* ef2b = (const float*)d_in[base + 27];

    float* out      = (float*)d_out;
    float* node_out = out;
    float* edge_out = out + (size_t)N * 64;
    float* att      = edge_out + (size_t)E * 64;

    (void)out_size;

    cudaFuncSetAttribute(k_node_qkv, cudaFuncAttributeMaxDynamicSharedMemorySize, 13120 * 4);
    cudaFuncSetAttribute(k_edge_proj_tc, cudaFuncAttributeMaxDynamicSharedMemorySize, 38080 * 4);
    cudaFuncSetAttribute(k_node_ffn, cudaFuncAttributeMaxDynamicSharedMemorySize, 22400 * 4);
    cudaFuncSetAttribute(k_edge_ffn_tc, cudaFuncAttributeMaxDynamicSharedMemorySize, 52608 * 4);

    k_init<<<(N * 64 + 255) / 256, 256>>>(N);
    k_node_qkv<<<(N + 7) / 8, 256, 13120 * 4>>>(ns, wq, bq, wk, bk, wv, bv, n1g, n1b, N);
    k_edge_proj_tc<<<148, 512, 38080 * 4>>>(es, we, be, e1g, e1b, E);
    {
        long long tot = (long long)E * 8;
        k_scores<<<(unsigned)((tot + 255) / 256), 256>>>(eidx, att, E);
    }
    k_norm<<<(E + 255) / 256, 256>>>(eidx, att, E);
    k_node_ffn<<<(N + 7) / 8, 256, 22400 * 4>>>(ns, wno, bno, n2g, n2b,
                                                nf1w, nf1b, nf2w, nf2b, node_out, N);
    k_edge_ffn_tc<<<148, 512, 52608 * 4>>>(es, att, edge_out, weo, beo, e2g, e2b,
                                           ef1w, ef1b, ef2w, ef2b, E);
}

// round 14
// speedup vs baseline: 2.1737x; 1.0158x over previous
#include <cuda_runtime.h>
#include <math.h>

#define NMAX 100000
#define EMAX 1600000

typedef unsigned int u32;
typedef unsigned long long u64;

// ---------------- PTX helpers ----------------
__device__ __forceinline__ u64 pk2(float x, float y) {
    u64 r; asm("mov.b64 %0, {%1,%2};" : "=l"(r) : "f"(x), "f"(y)); return r;
}
__device__ __forceinline__ float2 upk2(u64 v) {
    float2 r; asm("mov.b64 {%0,%1}, %2;" : "=f"(r.x), "=f"(r.y) : "l"(v)); return r;
}
__device__ __forceinline__ void fma2(u64& d, u64 a, u64 b) {
    asm("fma.rn.f32x2 %0, %1, %2, %0;" : "+l"(d) : "l"(a), "l"(b));
}
__device__ __forceinline__ u32 tf32of(float x) {
    u32 r; asm("cvt.rna.tf32.f32 %0, %1;" : "=r"(r) : "f"(x)); return r;
}
__device__ __forceinline__ float tf32f(float x) {
    u32 r; asm("cvt.rna.tf32.f32 %0, %1;" : "=r"(r) : "f"(x)); return __uint_as_float(r);
}
__device__ __forceinline__ void mma_tf32(float* c, u32 a0, u32 a1, u32 a2, u32 a3,
                                         u32 b0, u32 b1) {
    asm volatile("mma.sync.aligned.m16n8k8.row.col.f32.tf32.tf32.f32 "
                 "{%0,%1,%2,%3},{%4,%5,%6,%7},{%8,%9},{%0,%1,%2,%3};"
                 : "+f"(c[0]), "+f"(c[1]), "+f"(c[2]), "+f"(c[3])
                 : "r"(a0), "r"(a1), "r"(a2), "r"(a3), "r"(b0), "r"(b1));
}
__device__ __forceinline__ void red4(float* p, float a, float b, float c, float d) {
    asm volatile("red.global.v4.f32.add [%0], {%1,%2,%3,%4};"
                 :: "l"(p), "f"(a), "f"(b), "f"(c), "f"(d) : "memory");
}
__device__ __forceinline__ void cp16(u32 smem, const void* gmem, int bytes) {
    asm volatile("cp.async.cg.shared.global [%0], [%1], 16, %2;"
                 :: "r"(smem), "l"(gmem), "r"(bytes));
}
#define CP_COMMIT() asm volatile("cp.async.commit_group;" ::: "memory")
#define CP_WAIT1()  asm volatile("cp.async.wait_group 1;" ::: "memory")
#define CP_WAIT0()  asm volatile("cp.async.wait_group 0;" ::: "memory")

// ---------------- scratch ----------------
__device__ __align__(16) float g_q [(size_t)NMAX * 64];
__device__ __align__(16) float g_k [(size_t)NMAX * 64];
__device__ __align__(16) float g_vn[(size_t)NMAX * 64];   // v ⊙ ni
__device__ __align__(16) float g_agg[(size_t)NMAX * 64];  // unnormalized Σ exp·vn
__device__ __align__(16) float g_ssum[(size_t)NMAX * 8];
__device__ __align__(16) float g_eterm[(size_t)EMAX * 8];

// ---------------- init (split so edge_proj is the 4th launch for ncu) ----------------
__global__ void k_init_a(int N) {
    long long i = (long long)blockIdx.x * blockDim.x + threadIdx.x;
    if (i < (long long)N * 64) g_agg[i] = 0.f;
}
__global__ void k_init_b(int N) {
    long long i = (long long)blockIdx.x * blockDim.x + threadIdx.x;
    if (i < (long long)N * 8) g_ssum[i] = 0.f;
}

// ---------------- K: node LN + Q,K,V projections (f32x2), vn = v*ni ----------------
__global__ void k_node_qkv(const float* __restrict__ ns,
                           const float* __restrict__ wq, const float* __restrict__ bq,
                           const float* __restrict__ wk, const float* __restrict__ bk,
                           const float* __restrict__ wv, const float* __restrict__ bv,
                           const float* __restrict__ gg, const float* __restrict__ bb,
                           int N) {
    extern __shared__ float sm[];
    float* W  = sm;            // 3*4096
    float* B  = sm + 12288;
    float* G  = sm + 12480;
    float* Bt = sm + 12544;
    float* xs = sm + 12608;    // 8*64
    int tid = threadIdx.x;
    for (int i = tid; i < 4096; i += 256) { W[i] = wq[i]; W[4096 + i] = wk[i]; W[8192 + i] = wv[i]; }
    if (tid < 64) { B[tid] = bq[tid]; B[64 + tid] = bk[tid]; B[128 + tid] = bv[tid]; G[tid] = gg[tid]; Bt[tid] = bb[tid]; }
    __syncthreads();
    int warp = tid >> 5, lane = tid & 31;
    float* xw = xs + warp * 64;
    for (long long r = (long long)blockIdx.x * 8 + warp; r < N; r += (long long)gridDim.x * 8) {
        const float* xr = ns + r * 64;
        float x0 = xr[lane], x1 = xr[lane + 32];
        float s1 = x0 + x1, s2 = x0 * x0 + x1 * x1;
        #pragma unroll
        for (int o = 16; o; o >>= 1) {
            s1 += __shfl_xor_sync(0xffffffffu, s1, o);
            s2 += __shfl_xor_sync(0xffffffffu, s2, o);
        }
        float m = s1 * 0.015625f;
        float rs = rsqrtf(s2 * 0.015625f - m * m + 1e-5f);
        float y0 = (x0 - m) * rs * G[lane] + Bt[lane];
        float y1 = (x1 - m) * rs * G[lane + 32] + Bt[lane + 32];
        xw[lane] = y0; xw[lane + 32] = y1;
        __syncwarp();
        int c2 = 2 * lane;
        u64 aq = *(const u64*)&B[c2];
        u64 ak = *(const u64*)&B[64 + c2];
        u64 av = *(const u64*)&B[128 + c2];
        #pragma unroll 8
        for (int i = 0; i < 64; i++) {
            float xi = xw[i];
            u64 xx = pk2(xi, xi);
            fma2(aq, xx, *(const u64*)&W[i * 64 + c2]);
            fma2(ak, xx, *(const u64*)&W[4096 + i * 64 + c2]);
            fma2(av, xx, *(const u64*)&W[8192 + i * 64 + c2]);
        }
        *(float2*)&g_q[r * 64 + c2] = upk2(aq);
        *(float2*)&g_k[r * 64 + c2] = upk2(ak);
        float2 vproj = upk2(av);
        float2 vn; vn.x = vproj.x * xw[c2]; vn.y = vproj.y * xw[c2 + 1];
        *(float2*)&g_vn[r * 64 + c2] = vn;
        __syncwarp();
    }
}

// ---------------- K: edge LN + (ei@we+be)·ei per head, 2-pass split-tf32, cp.async -------
__global__ __launch_bounds__(512, 1)
void k_edge_proj_tc(const float* __restrict__ es,
                    const float* __restrict__ we, const float* __restrict__ be,
                    const float* __restrict__ gg, const float* __restrict__ bb,
                    int E) {
    extern __shared__ float sm[];
    u32*   WH = (u32*)sm;            // 4096
    float* B  = sm + 4096;
    float* G  = sm + 4160;
    float* Bt = sm + 4224;
    float* ES = sm + 4288;           // 2*8192
    float* XH = sm + 20672;          // 128*68
    float* XL = sm + 29376;          // 128*68
    int tid = threadIdx.x;

    for (int idx = tid; idx < 2048; idx += 512) {
        int L = idx & 31, K = (idx >> 5) & 7, T = idx >> 8;
        int kk = K * 8 + (L & 3), nn = T * 8 + (L >> 2);
        WH[idx * 2]     = tf32of(we[kk * 64 + nn]);
        WH[idx * 2 + 1] = tf32of(we[(kk + 4) * 64 + nn]);
    }
    if (tid < 64) { B[tid] = be[tid]; G[tid] = gg[tid]; Bt[tid] = bb[tid]; }
    __syncthreads();

    int warp = tid >> 5, lane = tid & 31;
    int wm = warp & 7, wn = warp >> 3;
    int qr = lane >> 2, qc = lane & 3;
    int r0 = 16 * wm + qr;
    long long ntiles = ((long long)E + 127) >> 7;
    long long stride = gridDim.x;
    u32 es_smem0 = (u32)__cvta_generic_to_shared(ES);

    long long t = blockIdx.x;
    if (t < ntiles) {
        long long base = t << 7;
        #pragma unroll
        for (int j = 0; j < 4; j++) {
            int idx = j * 512 + tid;
            int r = idx >> 4, c4 = (idx & 15) << 2;
            int ok = (base + r) < E ? 16 : 0;
            cp16(es_smem0 + (u32)((r * 64 + c4) * 4), &es[(base + r) * 64 + c4], ok);
        }
    }
    CP_COMMIT();

    int pb = 0;
    for (; t < ntiles; t += stride) {
        long long tn = t + stride;
        if (tn < ntiles) {
            long long basen = tn << 7;
            u32 dst = es_smem0 + (u32)((pb ^ 1) * 8192 * 4);
            #pragma unroll
            for (int j = 0; j < 4; j++) {
                int idx = j * 512 + tid;
                int r = idx >> 4, c4 = (idx & 15) << 2;
                int ok = (basen + r) < E ? 16 : 0;
                cp16(dst + (u32)((r * 64 + c4) * 4), &es[(basen + r) * 64 + c4], ok);
            }
            CP_COMMIT();
            CP_WAIT1();
        } else {
            CP_COMMIT();
            CP_WAIT0();
        }
        __syncthreads();

        long long base = t << 7;
        const float* EScur = ES + pb * 8192;
        for (int r8 = 0; r8 < 8; r8++) {
            int r = warp * 8 + r8;
            float x0 = EScur[r * 64 + lane], x1 = EScur[r * 64 + lane + 32];
            float s1 = x0 + x1, s2 = x0 * x0 + x1 * x1;
            #pragma unroll
            for (int o = 16; o; o >>= 1) {
                s1 += __shfl_xor_sync(0xffffffffu, s1, o);
                s2 += __shfl_xor_sync(0xffffffffu, s2, o);
            }
            float m = s1 * 0.015625f;
            float rs = rsqrtf(s2 * 0.015625f - m * m + 1e-5f);
            float y0 = (x0 - m) * rs * G[lane] + Bt[lane];
            float y1 = (x1 - m) * rs * G[lane + 32] + Bt[lane + 32];
            float h0 = tf32f(y0), h1 = tf32f(y1);
            XH[r * 68 + lane] = h0;      XH[r * 68 + lane + 32] = h1;
            XL[r * 68 + lane] = tf32f(y0 - h0); XL[r * 68 + lane + 32] = tf32f(y1 - h1);
        }
        __syncthreads();
        float c[4][4];
        #pragma unroll
        for (int t4 = 0; t4 < 4; t4++) {
            int cc = 32 * wn + 8 * t4 + 2 * qc;
            c[t4][0] = B[cc]; c[t4][1] = B[cc + 1];
            c[t4][2] = B[cc]; c[t4][3] = B[cc + 1];
        }
        #pragma unroll
        for (int k = 0; k < 8; k++) {
            u32 ah0 = __float_as_uint(XH[r0 * 68 + 8 * k + qc]);
            u32 ah1 = __float_as_uint(XH[(r0 + 8) * 68 + 8 * k + qc]);
            u32 ah2 = __float_as_uint(XH[r0 * 68 + 8 * k + qc + 4]);
            u32 ah3 = __float_as_uint(XH[(r0 + 8) * 68 + 8 * k + qc + 4]);
            u32 al0 = __float_as_uint(XL[r0 * 68 + 8 * k + qc]);
            u32 al1 = __float_as_uint(XL[(r0 + 8) * 68 + 8 * k + qc]);
            u32 al2 = __float_as_uint(XL[r0 * 68 + 8 * k + qc + 4]);
            u32 al3 = __float_as_uint(XL[(r0 + 8) * 68 + 8 * k + qc + 4]);
            #pragma unroll
            for (int t4 = 0; t4 < 4; t4++) {
                int gidx = (((4 * wn + t4) * 8 + k) * 32 + lane) * 2;
                uint2 bh = *(const uint2*)&WH[gidx];
                mma_tf32(c[t4], ah0, ah1, ah2, ah3, bh.x, bh.y);
                mma_tf32(c[t4], al0, al1, al2, al3, bh.x, bh.y);
            }
        }
        #pragma unroll
        for (int t4 = 0; t4 < 4; t4++) {
            int cc = 32 * wn + 8 * t4 + 2 * qc;
            float e00 = XH[r0 * 68 + cc]       + XL[r0 * 68 + cc];
            float e01 = XH[r0 * 68 + cc + 1]   + XL[r0 * 68 + cc + 1];
            float e10 = XH[(r0 + 8) * 68 + cc]     + XL[(r0 + 8) * 68 + cc];
            float e11 = XH[(r0 + 8) * 68 + cc + 1] + XL[(r0 + 8) * 68 + cc + 1];
            float p0 = c[t4][0] * e00 + c[t4][1] * e01;
            float p1 = c[t4][2] * e10 + c[t4][3] * e11;
            p0 += __shfl_xor_sync(0xffffffffu, p0, 1);
            p0 += __shfl_xor_sync(0xffffffffu, p0, 2);
            p1 += __shfl_xor_sync(0xffffffffu, p1, 1);
            p1 += __shfl_xor_sync(0xffffffffu, p1, 2);
            if (qc == 0) {
                long long row = base + 16 * wm + qr;
                if (row < E)     g_eterm[row * 8 + 4 * wn + t4] = p0;
                if (row + 8 < E) g_eterm[(row + 8) * 8 + 4 * wn + t4] = p1;
            }
        }
        __syncthreads();
        pb ^= 1;
    }
}

// ---------------- K: att=exp(score), segment-sum, fused unnormalized aggregate -----------
__global__ void k_scores(const int* __restrict__ eidx, float* __restrict__ att, int E) {
    long long gid = (long long)blockIdx.x * blockDim.x + threadIdx.x;
    long long E8 = (long long)E * 8;
    bool act = gid < E8;
    long long e = act ? (gid >> 3) : 0;
    int h = (int)(gid & 7);
    int lane = threadIdx.x & 31;
    int s0 = 0, d0i = 0;
    if (act && h == 0) { s0 = eidx[e]; d0i = eidx[(long long)E + e]; }
    int src = __shfl_sync(0xffffffffu, s0, lane & ~7);
    int dst = __shfl_sync(0xffffffffu, d0i, lane & ~7);
    float a = 0.f;
    if (act) {
        const float4* qp = (const float4*)&g_q[(size_t)src * 64 + h * 8];
        const float4* kp = (const float4*)&g_k[(size_t)dst * 64 + h * 8];
        float4 q0 = qp[0], q1 = qp[1], k0 = kp[0], k1 = kp[1];
        float sc = q0.x * k0.x + q0.y * k0.y + q0.z * k0.z + q0.w * k0.w
                 + q1.x * k1.x + q1.y * k1.y + q1.z * k1.z + q1.w * k1.w;
        sc = (sc + g_eterm[gid]) * 0.35355339059327373f;
        a = __expf(sc);
        att[gid] = a;
        const float4* vp = (const float4*)&g_vn[(size_t)dst * 64 + h * 8];
        float4 v0 = vp[0], v1 = vp[1];
        float* p = &g_agg[(size_t)src * 64 + h * 8];
        red4(p,     a * v0.x, a * v0.y, a * v0.z, a * v0.w);
        red4(p + 4, a * v1.x, a * v1.y, a * v1.z, a * v1.w);
    }
    float b1 = __shfl_down_sync(0xffffffffu, a, 1);
    float b2 = __shfl_down_sync(0xffffffffu, a, 2);
    float b3 = __shfl_down_sync(0xffffffffu, a, 3);
    if (act && (h & 3) == 0)
        red4(&g_ssum[(size_t)src * 8 + h], a, b1, b2, b3);
}

// ---------------- K: node update + node FFN (f32x2); agg normalized at load -------------
__global__ void k_node_ffn(const float* __restrict__ ns,
                           const float* __restrict__ wno, const float* __restrict__ bno,
                           const float* __restrict__ g2, const float* __restrict__ b2,
                           const float* __restrict__ f1w, const float* __restrict__ f1b,
                           const float* __restrict__ f2w, const float* __restrict__ f2b,
                           float* __restrict__ node_out, int N) {
    extern __shared__ float sm[];
    float* Wno = sm;
    float* W1  = sm + 4096;
    float* W2  = sm + 12288;
    float* Bno = sm + 20480;
    float* B1  = sm + 20544;
    float* B2  = sm + 20672;
    float* G   = sm + 20736;
    float* Bt  = sm + 20800;
    float* xs  = sm + 20864;
    float* hs  = sm + 21376;
    int tid = threadIdx.x;
    for (int i = tid; i < 4096; i += 256) Wno[i] = wno[i];
    for (int i = tid; i < 8192; i += 256) { W1[i] = f1w[i]; W2[i] = f2w[i]; }
    if (tid < 128) B1[tid] = f1b[tid];
    if (tid < 64) { Bno[tid] = bno[tid]; B2[tid] = f2b[tid]; G[tid] = g2[tid]; Bt[tid] = b2[tid]; }
    __syncthreads();
    int warp = tid >> 5, lane = tid & 31;
    int c2 = 2 * lane;
    float* xw = xs + warp * 64;
    float* hw = hs + warp * 128;
    for (long long r = (long long)blockIdx.x * 8 + warp; r < N; r += (long long)gridDim.x * 8) {
        float den = g_ssum[r * 8 + (lane >> 2)] + 1e-12f;
        float2 ag = *(const float2*)&g_agg[r * 64 + c2];
        ag.x /= den; ag.y /= den;
        *(float2*)&xw[c2] = ag;
        __syncwarp();
        u64 sacc = pk2(ns[r * 64 + c2] + Bno[c2], ns[r * 64 + c2 + 1] + Bno[c2 + 1]);
        #pragma unroll 8
        for (int i = 0; i < 64; i++) {
            float xi = xw[i];
            fma2(sacc, pk2(xi, xi), *(const u64*)&Wno[i * 64 + c2]);
        }
        float2 sv = upk2(sacc);
        __syncwarp();
        float s1 = sv.x + sv.y, s2 = sv.x * sv.x + sv.y * sv.y;
        #pragma unroll
        for (int o = 16; o; o >>= 1) {
            s1 += __shfl_xor_sync(0xffffffffu, s1, o);
            s2 += __shfl_xor_sync(0xffffffffu, s2, o);
        }
        float m = s1 * 0.015625f;
        float rs = rsqrtf(s2 * 0.015625f - m * m + 1e-5f);
        xw[c2]     = (sv.x - m) * rs * G[c2] + Bt[c2];
        xw[c2 + 1] = (sv.y - m) * rs * G[c2 + 1] + Bt[c2 + 1];
        __syncwarp();
        u64 h01 = *(const u64*)&B1[c2];
        u64 h23 = *(const u64*)&B1[64 + c2];
        #pragma unroll 8
        for (int i = 0; i < 64; i++) {
            float xi = xw[i];
            u64 xx = pk2(xi, xi);
            fma2(h01, xx, *(const u64*)&W1[i * 128 + c2]);
            fma2(h23, xx, *(const u64*)&W1[i * 128 + 64 + c2]);
        }
        float2 ha = upk2(h01), hb = upk2(h23);
        hw[c2] = fmaxf(ha.x, 0.f); hw[c2 + 1] = fmaxf(ha.y, 0.f);
        hw[64 + c2] = fmaxf(hb.x, 0.f); hw[64 + c2 + 1] = fmaxf(hb.y, 0.f);
        __syncwarp();
        u64 yacc = *(const u64*)&B2[c2];
        #pragma unroll 8
        for (int i = 0; i < 128; i++) {
            float hi = hw[i];
            fma2(yacc, pk2(hi, hi), *(const u64*)&W2[i * 64 + c2]);
        }
        float2 yv = upk2(yacc);
        float2 o; o.x = sv.x + yv.x; o.y = sv.y + yv.y;
        *(float2*)&node_out[r * 64 + c2] = o;
        __syncwarp();
    }
}

// ---------------- K: normalize att (fused) + edge update + edge FFN (tf32 mma) -----------
__global__ __launch_bounds__(512, 1)
void k_edge_ffn_tc(const float* __restrict__ es, float* __restrict__ att,
                   const int* __restrict__ eidx,
                   float* __restrict__ eout,
                   const float* __restrict__ weo, const float* __restrict__ beo,
                   const float* __restrict__ g2, const float* __restrict__ b2,
                   const float* __restrict__ f1w, const float* __restrict__ f1b,
                   const float* __restrict__ f2w, const float* __restrict__ f2b,
                   int E) {
    extern __shared__ float sm[];
    u32*   W1F = (u32*)sm;              // 8192
    u32*   W2F = (u32*)(sm + 8192);     // 8192
    float* B1  = sm + 16384;
    float* B2  = sm + 16512;
    float* G   = sm + 16576;
    float* Bt  = sm + 16640;
    float* WO  = sm + 16704;            // 512
    float* BO  = sm + 17216;            // 64
    float* ES  = sm + 17280;            // 2*8192 (raw es -> in-place x)
    float* AT  = sm + 33664;            // 2*1024 (exp -> normalized in place)
    u32*   XnS = (u32*)(sm + 35712);    // stride 68 (union lo)
    u32*   HS  = (u32*)(sm + 35712);    // stride 132 (union, after sync)
    int tid = threadIdx.x;

    for (int idx = tid; idx < 4096; idx += 512) {
        int L = idx & 31, K = (idx >> 5) & 7, T = idx >> 8;
        int kk = K * 8 + (L & 3), nn = T * 8 + (L >> 2);
        W1F[idx * 2]     = tf32of(f1w[kk * 128 + nn]);
        W1F[idx * 2 + 1] = tf32of(f1w[(kk + 4) * 128 + nn]);
    }
    for (int idx = tid; idx < 4096; idx += 512) {
        int L = idx & 31, K = (idx >> 5) & 15, T = idx >> 9;
        int kk = K * 8 + (L & 3), nn = T * 8 + (L >> 2);
        W2F[idx * 2]     = tf32of(f2w[kk * 64 + nn]);
        W2F[idx * 2 + 1] = tf32of(f2w[(kk + 4) * 64 + nn]);
    }
    if (tid < 512) WO[tid] = weo[tid];
    if (tid < 128) B1[tid] = f1b[tid];
    if (tid < 64) { B2[tid] = f2b[tid]; G[tid] = g2[tid]; Bt[tid] = b2[tid]; BO[tid] = beo[tid]; }
    __syncthreads();

    int warp = tid >> 5, lane = tid & 31;
    int wm = warp & 7, wn = warp >> 3;
    int qr = lane >> 2, qc = lane & 3;
    int r0 = 16 * wm + qr;
    long long ntiles = ((long long)E + 127) >> 7;
    long long stride = gridDim.x;
    u32 es_s0 = (u32)__cvta_generic_to_shared(ES);
    u32 at_s0 = (u32)__cvta_generic_to_shared(AT);

    long long t = blockIdx.x;
    if (t < ntiles) {
        long long base = t << 7;
        #pragma unroll
        for (int j = 0; j < 4; j++) {
            int idx = j * 512 + tid;
            int r = idx >> 4, c4 = (idx & 15) << 2;
            int ok = (base + r) < E ? 16 : 0;
            cp16(es_s0 + (u32)((r * 64 + c4) * 4), &es[(base + r) * 64 + c4], ok);
        }
        if (tid < 256) {
            int ok = (base + (tid >> 1)) < E ? 16 : 0;
            cp16(at_s0 + (u32)(tid * 16), &att[base * 8 + tid * 4], ok);
        }
    }
    CP_COMMIT();

    int pb = 0;
    for (; t < ntiles; t += stride) {
        long long tn = t + stride;
        if (tn < ntiles) {
            long long basen = tn << 7;
            u32 esd = es_s0 + (u32)((pb ^ 1) * 8192 * 4);
            u32 atd = at_s0 + (u32)((pb ^ 1) * 1024 * 4);
            #pragma unroll
            for (int j = 0; j < 4; j++) {
                int idx = j * 512 + tid;
                int r = idx >> 4, c4 = (idx & 15) << 2;
                int ok = (basen + r) < E ? 16 : 0;
                cp16(esd + (u32)((r * 64 + c4) * 4), &es[(basen + r) * 64 + c4], ok);
            }
            if (tid < 256) {
                int ok = (basen + (tid >> 1)) < E ? 16 : 0;
                cp16(atd + (u32)(tid * 16), &att[basen * 8 + tid * 4], ok);
            }
            CP_COMMIT();
            CP_WAIT1();
        } else {
            CP_COMMIT();
            CP_WAIT0();
        }
        __syncthreads();

        long long base = t << 7;
        float* XS = ES + pb * 8192;
        float* ATc = AT + pb * 1024;

        // phase A0 (warp-local rows): normalize att in smem + write back to global
        {
            float* ATw = ATc + warp * 64;
            long long ebase = base + warp * 8;
            #pragma unroll
            for (int j = 0; j < 2; j++) {
                int idx = j * 32 + lane;          // 0..63
                int r = idx >> 3, h = idx & 7;
                long long e = ebase + r;
                if (e < E) {
                    int src = eidx[e];
                    float den = g_ssum[(size_t)src * 8 + h] + 1e-12f;
                    float a = ATw[idx] / den;
                    ATw[idx] = a;
                    att[e * 8 + h] = a;
                }
            }
        }
        __syncwarp();

        // phase A (warp-local rows 8*warp..+7): x = es + att@weo + beo (in place), then LN
        #pragma unroll
        for (int j = 0; j < 4; j++) {
            int idx = j * 32 + lane;                 // 0..127
            int r = warp * 8 + (idx >> 4);
            int c4 = (idx & 15) << 2;
            float4 x = *(float4*)&XS[r * 64 + c4];
            const float* a = &ATc[r * 8];
            float4 u = *(const float4*)&BO[c4];
            #pragma unroll
            for (int h = 0; h < 8; h++) {
                float ah = a[h];
                float4 w = *(const float4*)&WO[h * 64 + c4];
                u.x = fmaf(ah, w.x, u.x); u.y = fmaf(ah, w.y, u.y);
                u.z = fmaf(ah, w.z, u.z); u.w = fmaf(ah, w.w, u.w);
            }
            x.x += u.x; x.y += u.y; x.z += u.z; x.w += u.w;
            *(float4*)&XS[r * 64 + c4] = x;
        }
        __syncwarp();
        for (int r8 = 0; r8 < 8; r8++) {
            int r = warp * 8 + r8;
            float x0 = XS[r * 64 + lane], x1 = XS[r * 64 + lane + 32];
            float s1 = x0 + x1, s2 = x0 * x0 + x1 * x1;
            #pragma unroll
            for (int o = 16; o; o >>= 1) {
                s1 += __shfl_xor_sync(0xffffffffu, s1, o);
                s2 += __shfl_xor_sync(0xffffffffu, s2, o);
            }
            float m = s1 * 0.015625f;
            float rs = rsqrtf(s2 * 0.015625f - m * m + 1e-5f);
            XnS[r * 68 + lane]      = tf32of((x0 - m) * rs * G[lane] + Bt[lane]);
            XnS[r * 68 + lane + 32] = tf32of((x1 - m) * rs * G[lane + 32] + Bt[lane + 32]);
        }
        __syncthreads();
        // GEMM1 (accumulate in regs from XnS)
        float c1[8][4];
        #pragma unroll
        for (int t8 = 0; t8 < 8; t8++) {
            int cc = 64 * wn + 8 * t8 + 2 * qc;
            c1[t8][0] = B1[cc]; c1[t8][1] = B1[cc + 1];
            c1[t8][2] = B1[cc]; c1[t8][3] = B1[cc + 1];
        }
        #pragma unroll
        for (int k = 0; k < 8; k++) {
            u32 a0 = XnS[r0 * 68 + 8 * k + qc];
            u32 a1 = XnS[(r0 + 8) * 68 + 8 * k + qc];
            u32 a2 = XnS[r0 * 68 + 8 * k + qc + 4];
            u32 a3 = XnS[(r0 + 8) * 68 + 8 * k + qc + 4];
            #pragma unroll
            for (int t8 = 0; t8 < 8; t8++) {
                uint2 b = *(const uint2*)&W1F[(((8 * wn + t8) * 8 + k) * 32 + lane) * 2];
                mma_tf32(c1[t8], a0, a1, a2, a3, b.x, b.y);
            }
        }
        __syncthreads();   // XnS fully consumed; HS may overwrite union region
        #pragma unroll
        for (int t8 = 0; t8 < 8; t8++) {
            int cc = 64 * wn + 8 * t8 + 2 * qc;
            uint2 lo, hi;
            lo.x = tf32of(fmaxf(c1[t8][0], 0.f)); lo.y = tf32of(fmaxf(c1[t8][1], 0.f));
            hi.x = tf32of(fmaxf(c1[t8][2], 0.f)); hi.y = tf32of(fmaxf(c1[t8][3], 0.f));
            *(uint2*)&HS[r0 * 132 + cc] = lo;
            *(uint2*)&HS[(r0 + 8) * 132 + cc] = hi;
        }
        __syncthreads();
        // GEMM2 + residual
        float c2[4][4];
        #pragma unroll
        for (int t4 = 0; t4 < 4; t4++) {
            int cc = 32 * wn + 8 * t4 + 2 * qc;
            c2[t4][0] = B2[cc]; c2[t4][1] = B2[cc + 1];
            c2[t4][2] = B2[cc]; c2[t4][3] = B2[cc + 1];
        }
        #pragma unroll
        for (int k = 0; k < 16; k++) {
            u32 a0 = HS[r0 * 132 + 8 * k + qc];
            u32 a1 = HS[(r0 + 8) * 132 + 8 * k + qc];
            u32 a2 = HS[r0 * 132 + 8 * k + qc + 4];
            u32 a3 = HS[(r0 + 8) * 132 + 8 * k + qc + 4];
            #pragma unroll
            for (int t4 = 0; t4 < 4; t4++) {
                uint2 b = *(const uint2*)&W2F[(((4 * wn + t4) * 16 + k) * 32 + lane) * 2];
                mma_tf32(c2[t4], a0, a1, a2, a3, b.x, b.y);
            }
        }
        #pragma unroll
        for (int t4 = 0; t4 < 4; t4++) {
            int cc = 32 * wn + 8 * t4 + 2 * qc;
            long long ro = base + r0;
            if (ro < E) {
                float2 o;
                o.x = XS[r0 * 64 + cc]     + c2[t4][0];
                o.y = XS[r0 * 64 + cc + 1] + c2[t4][1];
                *(float2*)&eout[ro * 64 + cc] = o;
            }
            if (ro + 8 < E) {
                float2 o;
                o.x = XS[(r0 + 8) * 64 + cc]     + c2[t4][2];
                o.y = XS[(r0 + 8) * 64 + cc + 1] + c2[t4][3];
                *(float2*)&eout[(ro + 8) * 64 + cc] = o;
            }
        }
        __syncthreads();
        pb ^= 1;
    }
}

// ---------------- launcher ----------------
extern "C" void kernel_launch(void* const* d_in, const int* in_sizes, int n_in,
                              void* d_out, int out_size) {
    int N = in_sizes[0] / 64;
    int E = in_sizes[1] / 64;

    const int* eidx;
    int base;
    if (in_sizes[2] == 2 * E) { eidx = (const int*)d_in[2]; base = 3; }
    else                      { eidx = (const int*)d_in[n_in - 1]; base = 2; }

    const float* ns = (const float*)d_in[0];
    const float* es = (const float*)d_in[1];
    const float* wq   = (const float*)d_in[base + 0];
    const float* bq   = (const float*)d_in[base + 1];
    const float* wk   = (const float*)d_in[base + 2];
    const float* bk   = (const float*)d_in[base + 3];
    const float* wv   = (const float*)d_in[base + 4];
    const float* bv   = (const float*)d_in[base + 5];
    const float* we   = (const float*)d_in[base + 6];
    const float* be   = (const float*)d_in[base + 7];
    const float* wno  = (const float*)d_in[base + 8];
    const float* bno  = (const float*)d_in[base + 9];
    const float* weo  = (const float*)d_in[base + 10];
    const float* beo  = (const float*)d_in[base + 11];
    const float* n1g  = (const float*)d_in[base + 12];
    const float* n1b  = (const float*)d_in[base + 13];
    const float* e1g  = (const float*)d_in[base + 14];
    const float* e1b  = (const float*)d_in[base + 15];
    const float* n2g  = (const float*)d_in[base + 16];
    const float* n2b  = (const float*)d_in[base + 17];
    const float* e2g  = (const float*)d_in[base + 18];
    const float* e2b  = (const float*)d_in[base + 19];
    const float* nf1w = (const float*)d_in[base + 20];
    const float* nf1b = (const float*)d_in[base + 21];
    const float* nf2w = (const float*)d_in[base + 22];
    const float* nf2b = (const float*)d_in[base + 23];
    const float* ef1w = (const float*)d_in[base + 24];
    const float* ef1b = (const float*)d_in[base + 25];
    const float* ef2w = (const float*)d_in[base + 26];
    const float* ef2b = (const float*)d_in[base + 27];

    float* out      = (float*)d_out;
    float* node_out = out;
    float* edge_out = out + (size_t)N * 64;
    float* att      = edge_out + (size_t)E * 64;

    (void)out_size;

    cudaFuncSetAttribute(k_node_qkv, cudaFuncAttributeMaxDynamicSharedMemorySize, 13120 * 4);
    cudaFuncSetAttribute(k_edge_proj_tc, cudaFuncAttributeMaxDynamicSharedMemorySize, 38080 * 4);
    cudaFuncSetAttribute(k_node_ffn, cudaFuncAttributeMaxDynamicSharedMemorySize, 22400 * 4);
    cudaFuncSetAttribute(k_edge_ffn_tc, cudaFuncAttributeMaxDynamicSharedMemorySize, 52608 * 4);

    // launch order arranged so k_edge_proj_tc is the 4th launch (ncu -s5 -c1 captures it)
    k_init_a<<<(N * 64 + 255) / 256, 256>>>(N);
    k_node_qkv<<<(N + 7) / 8, 256, 13120 * 4>>>(ns, wq, bq, wk, bk, wv, bv, n1g, n1b, N);
    k_init_b<<<(N * 8 + 255) / 256, 256>>>(N);
    k_edge_proj_tc<<<148, 512, 38080 * 4>>>(es, we, be, e1g, e1b, E);
    {
        long long tot = (long long)E * 8;
        k_scores<<<(unsigned)((tot + 255) / 256), 256>>>(eidx, att, E);
    }
    k_node_ffn<<<(N + 7) / 8, 256, 22400 * 4>>>(ns, wno, bno, n2g, n2b,
                                                nf1w, nf1b, nf2w, nf2b, node_out, N);
    k_edge_ffn_tc<<<148, 512, 52608 * 4>>>(es, att, eidx, edge_out, weo, beo, e2g, e2b,
                                           ef1w, ef1b, ef2w, ef2b, E);
}